// round 4
// baseline (speedup 1.0000x reference)
#include <cuda_runtime.h>
#include <math.h>

#define B_    8
#define L_    999
#define C_    768
#define C2_   384
#define H_    8
#define HD_   48
#define K_    3
#define DCIN_ 96
#define PJIN_ 96
#define M_    (B_*L_)          /* 7992 tokens */
#define SCALE_ 0.14433756729740643f
#define EPS_   1e-5f

typedef unsigned long long ull;

__device__ __forceinline__ float gelu_f(float v) {
    return 0.5f * v * (1.0f + erff(v * 0.7071067811865475f));
}

// ---- packed f32x2 helpers (Blackwell FFMA2 path; exact fp32 semantics) ----
__device__ __forceinline__ ull pack_dup(float x) {
    ull r; asm("mov.b64 %0, {%1, %1};" : "=l"(r) : "f"(x)); return r;
}
__device__ __forceinline__ ull pack2f(float x, float y) {
    ull r; asm("mov.b64 %0, {%1, %2};" : "=l"(r) : "f"(x), "f"(y)); return r;
}
__device__ __forceinline__ void ffma2(ull& d, ull a, ull b) {
    asm("fma.rn.f32x2 %0, %1, %2, %0;" : "+l"(d) : "l"(a), "l"(b));
}
__device__ __forceinline__ void fmul2(ull& d, ull a) {
    asm("mul.rn.f32x2 %0, %0, %1;" : "+l"(d) : "l"(a));
}
__device__ __forceinline__ float2 unpk(ull v) {
    float2 f; asm("mov.b64 {%0, %1}, %2;" : "=f"(f.x), "=f"(f.y) : "l"(v)); return f;
}

// ---------------- scratch (device globals; no allocation allowed) ----------------
__device__ float g_q    [(size_t)M_*C2_];
__device__ float g_kvin [(size_t)M_*C2_];
__device__ float g_kv   [(size_t)M_*C_];
__device__ float g_xc   [(size_t)M_*C_];
__device__ float g_t1   [(size_t)M_*C_];
__device__ float g_t2   [(size_t)M_*PJIN_];
__device__ float g_t3   [(size_t)M_*C_];
__device__ float g_wdyn [B_*C2_*K_];
__device__ float g_bdyn [B_*C2_];
__device__ float g_ps   [128*C_];
__device__ float g_ps2  [128*C_];
__device__ float g_an   [C_];
__device__ float g_bn   [C_];

// ---------------- stage 1: pooled partial sums (4-way split over rows) ----------------
__global__ void pooled_kernel(const float* __restrict__ x) {
    int blk = blockIdx.x;            // (b*3+kk)*4+sub
    int sub = blk & 3;
    int bk  = blk >> 2;
    int b   = bk / K_;
    int kk  = bk % K_;
    int c   = threadIdx.x;           // 384
    int r0 = kk*333 + sub*84;
    int r1 = kk*333 + min(sub*84 + 84, 333);
    const float* xb = x + (size_t)b*L_*C_ + c;
    float s = 0.f;
    for (int l = r0; l < r1; l++) s += xb[(size_t)l*C_];
    g_ps[(size_t)blk*C2_ + c] = s;
}

// ---------------- stage 2: dynamic-conv score MLP + softmax over G ----------------
__global__ void dcmlp_kernel(const float* __restrict__ p1w, const float* __restrict__ p1b,
                             const float* __restrict__ p2w, const float* __restrict__ p2b,
                             const float* __restrict__ dcw, const float* __restrict__ dcb) {
    int b   = blockIdx.x;
    int tid = threadIdx.x;                 // 384
    __shared__ float col[4][C2_];
    __shared__ float hid[4][DCIN_];
    __shared__ float sc [4][2*C2_];
    {
        float cc[3];
        #pragma unroll
        for (int kk = 0; kk < 3; kk++) {
            int base = (b*3+kk)*4;
            cc[kk] = (g_ps[(size_t)(base+0)*C2_+tid] + g_ps[(size_t)(base+1)*C2_+tid]
                    + g_ps[(size_t)(base+2)*C2_+tid] + g_ps[(size_t)(base+3)*C2_+tid]) * (1.0f/333.0f);
            col[kk][tid] = cc[kk];
        }
        col[3][tid] = (cc[0]+cc[1]+cc[2]) * (1.0f/3.0f);
    }
    __syncthreads();
    {
        int kk = tid / DCIN_;
        int i  = tid % DCIN_;
        float s = p1b[i];
        const float* wr = p1w + (size_t)i*C2_;
        #pragma unroll 8
        for (int c = 0; c < C2_; c++) s += wr[c]*col[kk][c];
        hid[kk][i] = gelu_f(s);
    }
    __syncthreads();
    for (int t = tid; t < 4*768; t += 384) {
        int kk = t / 768, o = t % 768;
        float s = p2b[o];
        const float* wr = p2w + (size_t)o*DCIN_;
        #pragma unroll 8
        for (int i = 0; i < DCIN_; i++) s += wr[i]*hid[kk][i];
        sc[kk][o] = s;
    }
    __syncthreads();
    {
        int c = tid;
        #pragma unroll
        for (int kk = 0; kk < 3; kk++) {
            float e0 = sc[kk][c], e1 = sc[kk][C2_+c];
            float mx = fmaxf(e0,e1);
            float a0 = expf(e0-mx), a1 = expf(e1-mx);
            float inv = 1.f/(a0+a1);
            g_wdyn[(b*C2_+c)*3+kk] = (a0*dcw[c*3+kk] + a1*dcw[(C2_+c)*3+kk])*inv;
        }
        float e0 = sc[3][c], e1 = sc[3][C2_+c];
        float mx = fmaxf(e0,e1);
        float a0 = expf(e0-mx), a1 = expf(e1-mx);
        g_bdyn[b*C2_+c] = (a0*dcb[c] + a1*dcb[C2_+c])/(a0+a1);
    }
}

// ---------------- stage 3: dynamic depthwise conv -> xc[:, :, 0:384] ----------------
__global__ void dconv_kernel(const float* __restrict__ x) {
    int b  = blockIdx.y;
    int tid = threadIdx.x;                 // 768: li 0..7, c4 0..95
    int l  = blockIdx.x*8 + (tid/96);
    int c  = (tid%96)*4;
    if (l >= L_) return;
    const float* wp = g_wdyn + ((size_t)b*C2_ + c)*3;
    float4 wA = *(const float4*)(wp);
    float4 wB = *(const float4*)(wp+4);
    float4 wC = *(const float4*)(wp+8);
    float4 bv = *(const float4*)(g_bdyn + (size_t)b*C2_ + c);
    const float* xb = x + ((size_t)b*L_ + l)*C_ + c;
    float4 zero = make_float4(0.f,0.f,0.f,0.f);
    float4 xm = (l > 0)      ? *(const float4*)(xb - C_) : zero;
    float4 x0 = *(const float4*)(xb);
    float4 xp = (l+1 < L_)   ? *(const float4*)(xb + C_) : zero;
    float4 r;
    r.x = xm.x*wA.x + x0.x*wA.y + xp.x*wA.z + bv.x;
    r.y = xm.y*wA.w + x0.y*wB.x + xp.y*wB.y + bv.y;
    r.z = xm.z*wB.z + x0.z*wB.w + xp.z*wC.x + bv.z;
    r.w = xm.w*wC.y + x0.w*wC.z + xp.w*wC.w + bv.w;
    *(float4*)(g_xc + ((size_t)b*L_ + l)*C_ + c) = r;
}

// ---------------- stage 4: kv_in = dw3(x2, lcw, lcb) + x2 ----------------
__global__ void kvin_kernel(const float* __restrict__ x,
                            const float* __restrict__ lcw, const float* __restrict__ lcb) {
    int b  = blockIdx.y;
    int tid = threadIdx.x;                 // 768
    int l  = blockIdx.x*8 + (tid/96);
    int c  = (tid%96)*4;
    if (l >= L_) return;
    const float* wp = lcw + (size_t)c*3;
    float4 wA = *(const float4*)(wp);
    float4 wB = *(const float4*)(wp+4);
    float4 wC = *(const float4*)(wp+8);
    float4 bv = *(const float4*)(lcb + c);
    const float* xb = x + ((size_t)b*L_ + l)*C_ + C2_ + c;
    float4 zero = make_float4(0.f,0.f,0.f,0.f);
    float4 xm = (l > 0)      ? *(const float4*)(xb - C_) : zero;
    float4 x0 = *(const float4*)(xb);
    float4 xp = (l+1 < L_)   ? *(const float4*)(xb + C_) : zero;
    float4 r;
    r.x = xm.x*wA.x + x0.x*wA.y + xp.x*wA.z + bv.x + x0.x;
    r.y = xm.y*wA.w + x0.y*wB.x + xp.y*wB.y + bv.y + x0.y;
    r.z = xm.z*wB.z + x0.z*wB.w + xp.z*wC.x + bv.z + x0.z;
    r.w = xm.w*wC.y + x0.w*wC.z + xp.w*wC.w + bv.w + x0.w;
    *(float4*)(g_kvin + ((size_t)b*L_ + l)*C2_ + c) = r;
}

// ---------------- GEMM v3: 128x128 tile, 8x8 micro-tile, FFMA2 inner loop ---------------
// C[m,n] = sum_k a(A[m,k]) * W[n,k] + bias[n] ; optional per-k affine on A, gelu epilogue
__global__ void gemm_kernel(const float* __restrict__ A, int lda,
                            const float* __restrict__ W,
                            const float* __restrict__ bias,
                            float* __restrict__ Cmat, int ldc,
                            int M, int N, int Kd,
                            const float* __restrict__ ascale,
                            const float* __restrict__ ashift,
                            int dogelu)
{
    __shared__ __align__(16) float As[16][132];
    __shared__ __align__(16) float Ws[16][132];
    int tid = threadIdx.x;                 // 256
    int tx = tid & 15, ty = tid >> 4;
    int m0 = blockIdx.x*128, n0 = blockIdx.y*128;
    ull acc[4][8];                         // [m-pair][n]
    #pragma unroll
    for (int i = 0; i < 4; i++)
        #pragma unroll
        for (int j = 0; j < 8; j++) acc[i][j] = 0ull;

    int lr = tid >> 1, lk = (tid & 1) << 3;
    float4 zero = make_float4(0.f,0.f,0.f,0.f);

    for (int k0 = 0; k0 < Kd; k0 += 16) {
        float4 a0 = zero, a1 = zero, w0 = zero, w1 = zero;
        int gm = m0 + lr;
        if (gm < M) {
            const float* ap = A + (size_t)gm*lda + k0 + lk;
            a0 = *(const float4*)(ap);
            a1 = *(const float4*)(ap+4);
        }
        if (ascale) {
            int kb = k0 + lk;
            a0.x = a0.x*ascale[kb+0] + ashift[kb+0];
            a0.y = a0.y*ascale[kb+1] + ashift[kb+1];
            a0.z = a0.z*ascale[kb+2] + ashift[kb+2];
            a0.w = a0.w*ascale[kb+3] + ashift[kb+3];
            a1.x = a1.x*ascale[kb+4] + ashift[kb+4];
            a1.y = a1.y*ascale[kb+5] + ashift[kb+5];
            a1.z = a1.z*ascale[kb+6] + ashift[kb+6];
            a1.w = a1.w*ascale[kb+7] + ashift[kb+7];
        }
        int gn = n0 + lr;
        if (gn < N) {
            const float* wptr = W + (size_t)gn*Kd + k0 + lk;
            w0 = *(const float4*)(wptr);
            w1 = *(const float4*)(wptr+4);
        }
        __syncthreads();
        As[lk+0][lr]=a0.x; As[lk+1][lr]=a0.y; As[lk+2][lr]=a0.z; As[lk+3][lr]=a0.w;
        As[lk+4][lr]=a1.x; As[lk+5][lr]=a1.y; As[lk+6][lr]=a1.z; As[lk+7][lr]=a1.w;
        Ws[lk+0][lr]=w0.x; Ws[lk+1][lr]=w0.y; Ws[lk+2][lr]=w0.z; Ws[lk+3][lr]=w0.w;
        Ws[lk+4][lr]=w1.x; Ws[lk+5][lr]=w1.y; Ws[lk+6][lr]=w1.z; Ws[lk+7][lr]=w1.w;
        __syncthreads();
        #pragma unroll
        for (int k = 0; k < 16; k++) {
            ulonglong2 p01 = *(const ulonglong2*)&As[k][ty*8];
            ulonglong2 p23 = *(const ulonglong2*)&As[k][ty*8+4];
            float4 b0 = *(const float4*)&Ws[k][tx*8];
            float4 b1 = *(const float4*)&Ws[k][tx*8+4];
            ull d0 = pack_dup(b0.x), d1 = pack_dup(b0.y), d2 = pack_dup(b0.z), d3 = pack_dup(b0.w);
            ull d4 = pack_dup(b1.x), d5 = pack_dup(b1.y), d6 = pack_dup(b1.z), d7 = pack_dup(b1.w);
            ffma2(acc[0][0], p01.x, d0); ffma2(acc[0][1], p01.x, d1);
            ffma2(acc[0][2], p01.x, d2); ffma2(acc[0][3], p01.x, d3);
            ffma2(acc[0][4], p01.x, d4); ffma2(acc[0][5], p01.x, d5);
            ffma2(acc[0][6], p01.x, d6); ffma2(acc[0][7], p01.x, d7);
            ffma2(acc[1][0], p01.y, d0); ffma2(acc[1][1], p01.y, d1);
            ffma2(acc[1][2], p01.y, d2); ffma2(acc[1][3], p01.y, d3);
            ffma2(acc[1][4], p01.y, d4); ffma2(acc[1][5], p01.y, d5);
            ffma2(acc[1][6], p01.y, d6); ffma2(acc[1][7], p01.y, d7);
            ffma2(acc[2][0], p23.x, d0); ffma2(acc[2][1], p23.x, d1);
            ffma2(acc[2][2], p23.x, d2); ffma2(acc[2][3], p23.x, d3);
            ffma2(acc[2][4], p23.x, d4); ffma2(acc[2][5], p23.x, d5);
            ffma2(acc[2][6], p23.x, d6); ffma2(acc[2][7], p23.x, d7);
            ffma2(acc[3][0], p23.y, d0); ffma2(acc[3][1], p23.y, d1);
            ffma2(acc[3][2], p23.y, d2); ffma2(acc[3][3], p23.y, d3);
            ffma2(acc[3][4], p23.y, d4); ffma2(acc[3][5], p23.y, d5);
            ffma2(acc[3][6], p23.y, d6); ffma2(acc[3][7], p23.y, d7);
        }
    }
    int gn0 = n0 + tx*8;
    if (gn0 < N) {
        float bsv[8];
        #pragma unroll
        for (int j = 0; j < 8; j++) bsv[j] = bias[gn0+j];
        #pragma unroll
        for (int i2 = 0; i2 < 4; i2++) {
            #pragma unroll
            for (int half = 0; half < 2; half++) {
                int gm = m0 + ty*8 + i2*2 + half;
                if (gm >= M) continue;
                float v[8];
                #pragma unroll
                for (int j = 0; j < 8; j++) {
                    float2 p = unpk(acc[i2][j]);
                    v[j] = (half ? p.y : p.x) + bsv[j];
                    if (dogelu) v[j] = gelu_f(v[j]);
                }
                float* cp = Cmat + (size_t)gm*ldc + gn0;
                *(float4*)(cp)   = make_float4(v[0],v[1],v[2],v[3]);
                *(float4*)(cp+4) = make_float4(v[4],v[5],v[6],v[7]);
            }
        }
    }
}

// ---------------- stage 7: flash attention v3 (FFMA2) -> xc[:, :, 384:768] ----------------
// Output write reproduces the reference's transpose+flat-reshape reinterpretation:
// (c = h*HD+d, l) -> flat = c*L + l -> xc[b, flat/C2, C2 + flat%C2].
__global__ void attn_kernel() {
    int qt = blockIdx.x;     // 16 q tiles of 64
    int h  = blockIdx.y;
    int b  = blockIdx.z;
    int tid = threadIdx.x;   // 128
    int tx = tid & 15, ty = tid >> 4;   // ty 0..7 (8 q rows each), tx 0..15 (4 k cols each)

    __shared__ __align__(16) float qs[48*68];      // q transposed [d][q]
    __shared__ __align__(16) float un[64*68];      // union: ks_t [d][k] / ps [k][q]
    __shared__ __align__(16) float vs[64*52];      // v [k][d]

    const float* qb = g_q  + (size_t)b*L_*C2_ + h*HD_;
    const float* kb = g_kv + (size_t)b*L_*C_  + h*HD_;
    const float* vb = kb + C2_;

    int lr = tid >> 1;               // 0..63
    int d0 = (tid & 1) * 24;         // 0 or 24

    {   // load Q tile transposed (64 q x 48 d)
        int gl = qt*64 + lr;
        if (gl < L_) {
            #pragma unroll
            for (int t = 0; t < 6; t++) {
                float4 v = *(const float4*)(qb + (size_t)gl*C2_ + d0 + t*4);
                qs[(d0+t*4+0)*68+lr]=v.x; qs[(d0+t*4+1)*68+lr]=v.y;
                qs[(d0+t*4+2)*68+lr]=v.z; qs[(d0+t*4+3)*68+lr]=v.w;
            }
        } else {
            #pragma unroll
            for (int t = 0; t < 24; t++) qs[(d0+t)*68+lr]=0.f;
        }
    }

    float m[8], l[8], corr[8];
    ull o2[4][4];                    // [q-pair][d]  (d cols tx*4+j, active tx<12)
    #pragma unroll
    for (int i = 0; i < 8; i++) { m[i] = -1e30f; l[i] = 0.f; }
    #pragma unroll
    for (int i = 0; i < 4; i++)
        #pragma unroll
        for (int j = 0; j < 4; j++) o2[i][j] = 0ull;

    for (int kt = 0; kt < 16; kt++) {
        __syncthreads();   // prev stage2 reads of un/vs done
        {
            int gl = kt*64 + lr;
            if (gl < L_) {
                #pragma unroll
                for (int t = 0; t < 6; t++) {
                    float4 kv = *(const float4*)(kb + (size_t)gl*C_ + d0 + t*4);
                    un[(d0+t*4+0)*68+lr]=kv.x; un[(d0+t*4+1)*68+lr]=kv.y;
                    un[(d0+t*4+2)*68+lr]=kv.z; un[(d0+t*4+3)*68+lr]=kv.w;
                    float4 vv = *(const float4*)(vb + (size_t)gl*C_ + d0 + t*4);
                    *(float4*)&vs[lr*52 + d0 + t*4] = vv;
                }
            } else {
                #pragma unroll
                for (int t = 0; t < 24; t++) un[(d0+t)*68+lr]=0.f;
                #pragma unroll
                for (int t = 0; t < 6; t++) *(float4*)&vs[lr*52 + d0 + t*4] = make_float4(0.f,0.f,0.f,0.f);
            }
        }
        __syncthreads();

        // ---- stage 1: S = Q^T K, 8q x 4k micro-tile, packed along q ----
        ull s2[4][4];
        #pragma unroll
        for (int i = 0; i < 4; i++)
            #pragma unroll
            for (int j = 0; j < 4; j++) s2[i][j] = 0ull;
        #pragma unroll 6
        for (int d = 0; d < 48; d++) {
            ulonglong2 q01 = *(const ulonglong2*)&qs[d*68 + ty*8];
            ulonglong2 q23 = *(const ulonglong2*)&qs[d*68 + ty*8+4];
            float4 kk = *(const float4*)&un[d*68 + tx*4];
            ull k0 = pack_dup(kk.x), k1 = pack_dup(kk.y), k2 = pack_dup(kk.z), k3 = pack_dup(kk.w);
            ffma2(s2[0][0], q01.x, k0); ffma2(s2[0][1], q01.x, k1);
            ffma2(s2[0][2], q01.x, k2); ffma2(s2[0][3], q01.x, k3);
            ffma2(s2[1][0], q01.y, k0); ffma2(s2[1][1], q01.y, k1);
            ffma2(s2[1][2], q01.y, k2); ffma2(s2[1][3], q01.y, k3);
            ffma2(s2[2][0], q23.x, k0); ffma2(s2[2][1], q23.x, k1);
            ffma2(s2[2][2], q23.x, k2); ffma2(s2[2][3], q23.x, k3);
            ffma2(s2[3][0], q23.y, k0); ffma2(s2[3][1], q23.y, k1);
            ffma2(s2[3][2], q23.y, k2); ffma2(s2[3][3], q23.y, k3);
        }

        // unpack scores: s[8 rows][4 cols]
        float s[8][4];
        #pragma unroll
        for (int i2 = 0; i2 < 4; i2++)
            #pragma unroll
            for (int j = 0; j < 4; j++) {
                float2 p = unpk(s2[i2][j]);
                s[i2*2+0][j] = p.x;
                s[i2*2+1][j] = p.y;
            }

        // ---- running softmax per row, reduce across 16 tx lanes ----
        int gk0 = kt*64 + tx*4;
        #pragma unroll
        for (int i = 0; i < 8; i++) {
            #pragma unroll
            for (int j = 0; j < 4; j++)
                s[i][j] = (gk0 + j < L_) ? s[i][j]*SCALE_ : -1e30f;
            float mx = fmaxf(fmaxf(s[i][0],s[i][1]), fmaxf(s[i][2],s[i][3]));
            mx = fmaxf(mx, __shfl_xor_sync(0xffffffffu, mx, 1));
            mx = fmaxf(mx, __shfl_xor_sync(0xffffffffu, mx, 2));
            mx = fmaxf(mx, __shfl_xor_sync(0xffffffffu, mx, 4));
            mx = fmaxf(mx, __shfl_xor_sync(0xffffffffu, mx, 8));
            float mnew = fmaxf(m[i], mx);
            corr[i] = __expf(m[i] - mnew);
            m[i] = mnew;
            float lp = 0.f;
            #pragma unroll
            for (int j = 0; j < 4; j++) { s[i][j] = __expf(s[i][j]-mnew); lp += s[i][j]; }
            lp += __shfl_xor_sync(0xffffffffu, lp, 1);
            lp += __shfl_xor_sync(0xffffffffu, lp, 2);
            lp += __shfl_xor_sync(0xffffffffu, lp, 4);
            lp += __shfl_xor_sync(0xffffffffu, lp, 8);
            l[i] = l[i]*corr[i] + lp;
        }

        __syncthreads();   // stage1 un reads done; overwrite with P
        #pragma unroll
        for (int j = 0; j < 4; j++)
            #pragma unroll
            for (int i = 0; i < 8; i++)
                un[(tx*4+j)*68 + ty*8 + i] = s[i][j];
        __syncthreads();

        // ---- stage 2: O += P V, 8q x 4d micro-tile, packed along q ----
        if (tx < 12) {
            ull cp0 = pack2f(corr[0], corr[1]);
            ull cp1 = pack2f(corr[2], corr[3]);
            ull cp2 = pack2f(corr[4], corr[5]);
            ull cp3 = pack2f(corr[6], corr[7]);
            #pragma unroll
            for (int j = 0; j < 4; j++) {
                fmul2(o2[0][j], cp0); fmul2(o2[1][j], cp1);
                fmul2(o2[2][j], cp2); fmul2(o2[3][j], cp3);
            }
            #pragma unroll 4
            for (int k = 0; k < 64; k++) {
                ulonglong2 p01 = *(const ulonglong2*)&un[k*68 + ty*8];
                ulonglong2 p23 = *(const ulonglong2*)&un[k*68 + ty*8+4];
                float4 v = *(const float4*)&vs[k*52 + tx*4];
                ull v0 = pack_dup(v.x), v1 = pack_dup(v.y), v2 = pack_dup(v.z), v3 = pack_dup(v.w);
                ffma2(o2[0][0], p01.x, v0); ffma2(o2[0][1], p01.x, v1);
                ffma2(o2[0][2], p01.x, v2); ffma2(o2[0][3], p01.x, v3);
                ffma2(o2[1][0], p01.y, v0); ffma2(o2[1][1], p01.y, v1);
                ffma2(o2[1][2], p01.y, v2); ffma2(o2[1][3], p01.y, v3);
                ffma2(o2[2][0], p23.x, v0); ffma2(o2[2][1], p23.x, v1);
                ffma2(o2[2][2], p23.x, v2); ffma2(o2[2][3], p23.x, v3);
                ffma2(o2[3][0], p23.y, v0); ffma2(o2[3][1], p23.y, v1);
                ffma2(o2[3][2], p23.y, v2); ffma2(o2[3][3], p23.y, v3);
            }
        }
    }

    if (tx < 12) {
        float* xcb = g_xc + (size_t)b*L_*C_;
        #pragma unroll
        for (int i = 0; i < 8; i++) {
            int gl = qt*64 + ty*8 + i;
            if (gl >= L_) continue;
            float inv = 1.f/l[i];
            #pragma unroll
            for (int j = 0; j < 4; j++) {
                float2 p = unpk(o2[i>>1][j]);
                float ov = (i & 1) ? p.y : p.x;
                int c = h*HD_ + tx*4 + j;
                int flat = c*L_ + gl;
                int lp2 = flat / C2_;
                int cp  = flat - lp2*C2_;
                xcb[(size_t)lp2*C_ + C2_ + cp] = ov*inv;
            }
        }
    }
}

// ---------------- stage 8a: t1 = gelu(dw3(xc)) ----------------
__global__ void pjdw_kernel(const float* __restrict__ dww, const float* __restrict__ dwb) {
    int b  = blockIdx.y;
    int tid = threadIdx.x;                 // 768: li 0..3, c4 0..191
    int l  = blockIdx.x*4 + (tid/192);
    int c  = (tid%192)*4;
    if (l >= L_) return;
    const float* wp = dww + (size_t)c*3;
    float4 wA = *(const float4*)(wp);
    float4 wB = *(const float4*)(wp+4);
    float4 wC = *(const float4*)(wp+8);
    float4 bv = *(const float4*)(dwb + c);
    const float* xb = g_xc + ((size_t)b*L_ + l)*C_ + c;
    float4 zero = make_float4(0.f,0.f,0.f,0.f);
    float4 xm = (l > 0)    ? *(const float4*)(xb - C_) : zero;
    float4 x0 = *(const float4*)(xb);
    float4 xp = (l+1 < L_) ? *(const float4*)(xb + C_) : zero;
    float4 r;
    r.x = gelu_f(xm.x*wA.x + x0.x*wA.y + xp.x*wA.z + bv.x);
    r.y = gelu_f(xm.y*wA.w + x0.y*wB.x + xp.y*wB.y + bv.y);
    r.z = gelu_f(xm.z*wB.z + x0.z*wB.w + xp.z*wC.x + bv.z);
    r.w = gelu_f(xm.w*wC.y + x0.w*wC.z + xp.w*wC.w + bv.w);
    *(float4*)(g_t1 + ((size_t)b*L_ + l)*C_ + c) = r;
}

// ---------------- deterministic BN stats: partials + finalize -> affine (a,b) ----------
__global__ void stats_partial_kernel(const float* __restrict__ X, int Cch) {
    int blk = blockIdx.x;                  // 127 chunks of 63 rows
    int c   = threadIdx.x;
    int r0 = blk*63, r1 = min(r0+63, M_);
    float s = 0.f, s2 = 0.f;
    for (int r = r0; r < r1; r++) {
        float v = X[(size_t)r*Cch + c];
        s += v; s2 += v*v;
    }
    g_ps [(size_t)blk*Cch + c] = s;
    g_ps2[(size_t)blk*Cch + c] = s2;
}

__global__ void stats_finalize_kernel(int nblk, int Cch,
                                      const float* __restrict__ gam,
                                      const float* __restrict__ bet) {
    int c = blockIdx.x*blockDim.x + threadIdx.x;
    if (c >= Cch) return;
    double s = 0.0, s2 = 0.0;
    for (int i = 0; i < nblk; i++) { s += (double)g_ps[(size_t)i*Cch+c]; s2 += (double)g_ps2[(size_t)i*Cch+c]; }
    double mean = s / (double)M_;
    double var  = s2 / (double)M_ - mean*mean;
    if (var < 0.0) var = 0.0;
    float rs = (float)(1.0 / sqrt(var + (double)EPS_));
    float a  = gam[c]*rs;
    g_an[c] = a;
    g_bn[c] = bet[c] - (float)mean*a;
}

// ---------------- final: out = bn3(t3) + xc ----------------
__global__ void final_add_kernel(float* __restrict__ out) {
    int idx4 = blockIdx.x*blockDim.x + threadIdx.x;
    if (idx4 >= M_*C_/4) return;
    int idx = idx4*4;
    int c = idx % C_;
    float4 t = *(const float4*)(g_t3 + idx);
    float4 xv= *(const float4*)(g_xc + idx);
    float4 a = *(const float4*)(g_an + c);
    float4 bb= *(const float4*)(g_bn + c);
    float4 r;
    r.x = t.x*a.x + bb.x + xv.x;
    r.y = t.y*a.y + bb.y + xv.y;
    r.z = t.z*a.z + bb.z + xv.z;
    r.w = t.w*a.w + bb.w + xv.w;
    *(float4*)(out + idx) = r;
}

// =======================================================================================
extern "C" void kernel_launch(void* const* d_in, const int* in_sizes, int n_in,
                              void* d_out, int out_size) {
    const float* x        = (const float*)d_in[0];
    const float* dc_weight= (const float*)d_in[1];
    const float* dc_bias  = (const float*)d_in[2];
    const float* dc_p1w   = (const float*)d_in[3];
    const float* dc_p1b   = (const float*)d_in[4];
    const float* dc_p2w   = (const float*)d_in[5];
    const float* dc_p2b   = (const float*)d_in[6];
    const float* at_qw    = (const float*)d_in[7];
    const float* at_qb    = (const float*)d_in[8];
    const float* at_kvw   = (const float*)d_in[9];
    const float* at_kvb   = (const float*)d_in[10];
    const float* at_lcw   = (const float*)d_in[11];
    const float* at_lcb   = (const float*)d_in[12];
    const float* pj_dww   = (const float*)d_in[13];
    const float* pj_dwb   = (const float*)d_in[14];
    const float* pj_bn1g  = (const float*)d_in[15];
    const float* pj_bn1b  = (const float*)d_in[16];
    const float* pj_c1w   = (const float*)d_in[17];
    const float* pj_c1b   = (const float*)d_in[18];
    const float* pj_bn2g  = (const float*)d_in[19];
    const float* pj_bn2b  = (const float*)d_in[20];
    const float* pj_c2w   = (const float*)d_in[21];
    const float* pj_c2b   = (const float*)d_in[22];
    const float* pj_bn3g  = (const float*)d_in[23];
    const float* pj_bn3b  = (const float*)d_in[24];
    float* out = (float*)d_out;

    float *pq, *pkvin, *pkv, *pt1, *pt2, *pt3, *pan, *pbn;
    cudaGetSymbolAddress((void**)&pq,    g_q);
    cudaGetSymbolAddress((void**)&pkvin, g_kvin);
    cudaGetSymbolAddress((void**)&pkv,   g_kv);
    cudaGetSymbolAddress((void**)&pt1,   g_t1);
    cudaGetSymbolAddress((void**)&pt2,   g_t2);
    cudaGetSymbolAddress((void**)&pt3,   g_t3);
    cudaGetSymbolAddress((void**)&pan,   g_an);
    cudaGetSymbolAddress((void**)&pbn,   g_bn);

    // ---- branch 1: dynamic conv ----
    pooled_kernel<<<96, C2_>>>(x);
    dcmlp_kernel<<<B_, C2_>>>(dc_p1w, dc_p1b, dc_p2w, dc_p2b, dc_weight, dc_bias);
    dconv_kernel<<<dim3(125, B_), 768>>>(x);

    // ---- branch 2: attention ----
    kvin_kernel<<<dim3(125, B_), 768>>>(x, at_lcw, at_lcb);
    gemm_kernel<<<dim3(63, 3), 256>>>(x + C2_, C_, at_qw, at_qb,
                                      pq, C2_, M_, C2_, C2_, nullptr, nullptr, 0);
    gemm_kernel<<<dim3(63, 6), 256>>>(pkvin, C2_, at_kvw, at_kvb,
                                      pkv, C_, M_, C_, C2_, nullptr, nullptr, 0);
    attn_kernel<<<dim3(16, H_, B_), 128>>>();

    // ---- projection: dw3 + gelu, then BN1 stats ----
    pjdw_kernel<<<dim3(250, B_), 768>>>(pj_dww, pj_dwb);
    stats_partial_kernel<<<127, C_>>>(pt1, C_);
    stats_finalize_kernel<<<3, 256>>>(127, C_, pj_bn1g, pj_bn1b);

    // ---- c1 (bn1 folded into A) + gelu ----
    gemm_kernel<<<dim3(63, 1), 256>>>(pt1, C_, pj_c1w, pj_c1b,
                                      pt2, PJIN_, M_, PJIN_, C_, pan, pbn, 1);
    stats_partial_kernel<<<127, PJIN_>>>(pt2, PJIN_);
    stats_finalize_kernel<<<1, 256>>>(127, PJIN_, pj_bn2g, pj_bn2b);

    // ---- c2 (bn2 folded into A) ----
    gemm_kernel<<<dim3(63, 6), 256>>>(pt2, PJIN_, pj_c2w, pj_c2b,
                                      pt3, C_, M_, C_, PJIN_, pan, pbn, 0);
    stats_partial_kernel<<<127, C_>>>(pt3, C_);
    stats_finalize_kernel<<<3, 256>>>(127, C_, pj_bn3g, pj_bn3b);

    // ---- bn3 + residual ----
    final_add_kernel<<<(M_*C_/4 + 255)/256, 256>>>(out);
}

// round 6
// speedup vs baseline: 1.5120x; 1.5120x over previous
#include <cuda_runtime.h>
#include <math.h>

#define B_    8
#define L_    999
#define C_    768
#define C2_   384
#define H_    8
#define HD_   48
#define K_    3
#define DCIN_ 96
#define PJIN_ 96
#define M_    (B_*L_)          /* 7992 tokens */
#define SCALE_ 0.14433756729740643f
#define EPS_   1e-5f

__device__ __forceinline__ float gelu_f(float v) {
    return 0.5f * v * (1.0f + erff(v * 0.7071067811865475f));
}

// ---------------- scratch (device globals; no allocation allowed) ----------------
__device__ float g_q    [(size_t)M_*C2_];
__device__ float g_kvin [(size_t)M_*C2_];
__device__ float g_kv   [(size_t)M_*C_];
__device__ float g_xc   [(size_t)M_*C_];
__device__ float g_t1   [(size_t)M_*C_];
__device__ float g_t2   [(size_t)M_*PJIN_];
__device__ float g_t3   [(size_t)M_*C_];
__device__ float g_wdyn [B_*C2_*K_];
__device__ float g_bdyn [B_*C2_];
__device__ float g_ps   [128*C_];
__device__ float g_ps2  [128*C_];
__device__ float g_an   [C_];
__device__ float g_bn   [C_];

// ---------------- stage 1: pooled partial sums (4-way split over rows) ----------------
__global__ void pooled_kernel(const float* __restrict__ x) {
    int blk = blockIdx.x;            // (b*3+kk)*4+sub
    int sub = blk & 3;
    int bk  = blk >> 2;
    int b   = bk / K_;
    int kk  = bk % K_;
    int c   = threadIdx.x;           // 384
    int r0 = kk*333 + sub*84;
    int r1 = kk*333 + min(sub*84 + 84, 333);
    const float* xb = x + (size_t)b*L_*C_ + c;
    float s = 0.f;
    for (int l = r0; l < r1; l++) s += xb[(size_t)l*C_];
    g_ps[(size_t)blk*C2_ + c] = s;
}

// ---------------- stage 2: dynamic-conv score MLP + softmax over G ----------------
__global__ void dcmlp_kernel(const float* __restrict__ p1w, const float* __restrict__ p1b,
                             const float* __restrict__ p2w, const float* __restrict__ p2b,
                             const float* __restrict__ dcw, const float* __restrict__ dcb) {
    int b   = blockIdx.x;
    int tid = threadIdx.x;                 // 384
    __shared__ float col[4][C2_];
    __shared__ float hid[4][DCIN_];
    __shared__ float sc [4][2*C2_];
    {
        float cc[3];
        #pragma unroll
        for (int kk = 0; kk < 3; kk++) {
            int base = (b*3+kk)*4;
            cc[kk] = (g_ps[(size_t)(base+0)*C2_+tid] + g_ps[(size_t)(base+1)*C2_+tid]
                    + g_ps[(size_t)(base+2)*C2_+tid] + g_ps[(size_t)(base+3)*C2_+tid]) * (1.0f/333.0f);
            col[kk][tid] = cc[kk];
        }
        col[3][tid] = (cc[0]+cc[1]+cc[2]) * (1.0f/3.0f);
    }
    __syncthreads();
    {
        int kk = tid / DCIN_;
        int i  = tid % DCIN_;
        float s = p1b[i];
        const float* wr = p1w + (size_t)i*C2_;
        #pragma unroll 8
        for (int c = 0; c < C2_; c++) s += wr[c]*col[kk][c];
        hid[kk][i] = gelu_f(s);
    }
    __syncthreads();
    for (int t = tid; t < 4*768; t += 384) {
        int kk = t / 768, o = t % 768;
        float s = p2b[o];
        const float* wr = p2w + (size_t)o*DCIN_;
        #pragma unroll 8
        for (int i = 0; i < DCIN_; i++) s += wr[i]*hid[kk][i];
        sc[kk][o] = s;
    }
    __syncthreads();
    {
        int c = tid;
        #pragma unroll
        for (int kk = 0; kk < 3; kk++) {
            float e0 = sc[kk][c], e1 = sc[kk][C2_+c];
            float mx = fmaxf(e0,e1);
            float a0 = expf(e0-mx), a1 = expf(e1-mx);
            float inv = 1.f/(a0+a1);
            g_wdyn[(b*C2_+c)*3+kk] = (a0*dcw[c*3+kk] + a1*dcw[(C2_+c)*3+kk])*inv;
        }
        float e0 = sc[3][c], e1 = sc[3][C2_+c];
        float mx = fmaxf(e0,e1);
        float a0 = expf(e0-mx), a1 = expf(e1-mx);
        g_bdyn[b*C2_+c] = (a0*dcb[c] + a1*dcb[C2_+c])/(a0+a1);
    }
}

// ---------------- stage 3: dynamic depthwise conv -> xc[:, :, 0:384] ----------------
__global__ void dconv_kernel(const float* __restrict__ x) {
    int b  = blockIdx.y;
    int tid = threadIdx.x;                 // 768: li 0..7, c4 0..95
    int l  = blockIdx.x*8 + (tid/96);
    int c  = (tid%96)*4;
    if (l >= L_) return;
    const float* wp = g_wdyn + ((size_t)b*C2_ + c)*3;
    float4 wA = *(const float4*)(wp);
    float4 wB = *(const float4*)(wp+4);
    float4 wC = *(const float4*)(wp+8);
    float4 bv = *(const float4*)(g_bdyn + (size_t)b*C2_ + c);
    const float* xb = x + ((size_t)b*L_ + l)*C_ + c;
    float4 zero = make_float4(0.f,0.f,0.f,0.f);
    float4 xm = (l > 0)      ? *(const float4*)(xb - C_) : zero;
    float4 x0 = *(const float4*)(xb);
    float4 xp = (l+1 < L_)   ? *(const float4*)(xb + C_) : zero;
    float4 r;
    r.x = xm.x*wA.x + x0.x*wA.y + xp.x*wA.z + bv.x;
    r.y = xm.y*wA.w + x0.y*wB.x + xp.y*wB.y + bv.y;
    r.z = xm.z*wB.z + x0.z*wB.w + xp.z*wC.x + bv.z;
    r.w = xm.w*wC.y + x0.w*wC.z + xp.w*wC.w + bv.w;
    *(float4*)(g_xc + ((size_t)b*L_ + l)*C_ + c) = r;
}

// ---------------- stage 4: kv_in = dw3(x2, lcw, lcb) + x2 ----------------
__global__ void kvin_kernel(const float* __restrict__ x,
                            const float* __restrict__ lcw, const float* __restrict__ lcb) {
    int b  = blockIdx.y;
    int tid = threadIdx.x;                 // 768
    int l  = blockIdx.x*8 + (tid/96);
    int c  = (tid%96)*4;
    if (l >= L_) return;
    const float* wp = lcw + (size_t)c*3;
    float4 wA = *(const float4*)(wp);
    float4 wB = *(const float4*)(wp+4);
    float4 wC = *(const float4*)(wp+8);
    float4 bv = *(const float4*)(lcb + c);
    const float* xb = x + ((size_t)b*L_ + l)*C_ + C2_ + c;
    float4 zero = make_float4(0.f,0.f,0.f,0.f);
    float4 xm = (l > 0)      ? *(const float4*)(xb - C_) : zero;
    float4 x0 = *(const float4*)(xb);
    float4 xp = (l+1 < L_)   ? *(const float4*)(xb + C_) : zero;
    float4 r;
    r.x = xm.x*wA.x + x0.x*wA.y + xp.x*wA.z + bv.x + x0.x;
    r.y = xm.y*wA.w + x0.y*wB.x + xp.y*wB.y + bv.y + x0.y;
    r.z = xm.z*wB.z + x0.z*wB.w + xp.z*wC.x + bv.z + x0.z;
    r.w = xm.w*wC.y + x0.w*wC.z + xp.w*wC.w + bv.w + x0.w;
    *(float4*)(g_kvin + ((size_t)b*L_ + l)*C2_ + c) = r;
}

// ---------------- GEMM v4: 128x128 tile, 8x8 micro-tile, k-major smem, plain FFMA ------
// C[m,n] = sum_k a(A[m,k]) * W[n,k] + bias[n] ; optional per-k affine on A, gelu epilogue
__global__ void __launch_bounds__(256, 2)
gemm_kernel(const float* __restrict__ A, int lda,
            const float* __restrict__ W,
            const float* __restrict__ bias,
            float* __restrict__ Cmat, int ldc,
            int M, int N, int Kd,
            const float* __restrict__ ascale,
            const float* __restrict__ ashift,
            int dogelu)
{
    __shared__ __align__(16) float As[16][132];
    __shared__ __align__(16) float Ws[16][132];
    int tid = threadIdx.x;                 // 256
    int tx = tid & 15, ty = tid >> 4;
    int m0 = blockIdx.x*128, n0 = blockIdx.y*128;
    float acc[8][8];
    #pragma unroll
    for (int i = 0; i < 8; i++)
        #pragma unroll
        for (int j = 0; j < 8; j++) acc[i][j] = 0.f;

    int lr = tid >> 1, lk = (tid & 1) << 3;
    float4 zero = make_float4(0.f,0.f,0.f,0.f);

    for (int k0 = 0; k0 < Kd; k0 += 16) {
        float4 a0 = zero, a1 = zero, w0 = zero, w1 = zero;
        int gm = m0 + lr;
        if (gm < M) {
            const float* ap = A + (size_t)gm*lda + k0 + lk;
            a0 = *(const float4*)(ap);
            a1 = *(const float4*)(ap+4);
        }
        if (ascale) {
            int kb = k0 + lk;
            a0.x = a0.x*ascale[kb+0] + ashift[kb+0];
            a0.y = a0.y*ascale[kb+1] + ashift[kb+1];
            a0.z = a0.z*ascale[kb+2] + ashift[kb+2];
            a0.w = a0.w*ascale[kb+3] + ashift[kb+3];
            a1.x = a1.x*ascale[kb+4] + ashift[kb+4];
            a1.y = a1.y*ascale[kb+5] + ashift[kb+5];
            a1.z = a1.z*ascale[kb+6] + ashift[kb+6];
            a1.w = a1.w*ascale[kb+7] + ashift[kb+7];
        }
        int gn = n0 + lr;
        if (gn < N) {
            const float* wptr = W + (size_t)gn*Kd + k0 + lk;
            w0 = *(const float4*)(wptr);
            w1 = *(const float4*)(wptr+4);
        }
        __syncthreads();
        As[lk+0][lr]=a0.x; As[lk+1][lr]=a0.y; As[lk+2][lr]=a0.z; As[lk+3][lr]=a0.w;
        As[lk+4][lr]=a1.x; As[lk+5][lr]=a1.y; As[lk+6][lr]=a1.z; As[lk+7][lr]=a1.w;
        Ws[lk+0][lr]=w0.x; Ws[lk+1][lr]=w0.y; Ws[lk+2][lr]=w0.z; Ws[lk+3][lr]=w0.w;
        Ws[lk+4][lr]=w1.x; Ws[lk+5][lr]=w1.y; Ws[lk+6][lr]=w1.z; Ws[lk+7][lr]=w1.w;
        __syncthreads();
        #pragma unroll
        for (int k = 0; k < 16; k++) {
            float4 aA = *(const float4*)&As[k][ty*8];
            float4 aB = *(const float4*)&As[k][ty*8+4];
            float4 bA = *(const float4*)&Ws[k][tx*8];
            float4 bB = *(const float4*)&Ws[k][tx*8+4];
            float av[8] = {aA.x,aA.y,aA.z,aA.w,aB.x,aB.y,aB.z,aB.w};
            float bv[8] = {bA.x,bA.y,bA.z,bA.w,bB.x,bB.y,bB.z,bB.w};
            #pragma unroll
            for (int i = 0; i < 8; i++)
                #pragma unroll
                for (int j = 0; j < 8; j++)
                    acc[i][j] += av[i]*bv[j];
        }
    }
    int gn0 = n0 + tx*8;
    if (gn0 < N) {
        float bsv[8];
        #pragma unroll
        for (int j = 0; j < 8; j++) bsv[j] = bias[gn0+j];
        #pragma unroll
        for (int i = 0; i < 8; i++) {
            int gm = m0 + ty*8 + i;
            if (gm >= M) break;
            float v[8];
            #pragma unroll
            for (int j = 0; j < 8; j++) {
                v[j] = acc[i][j] + bsv[j];
                if (dogelu) v[j] = gelu_f(v[j]);
            }
            float* cp = Cmat + (size_t)gm*ldc + gn0;
            *(float4*)(cp)   = make_float4(v[0],v[1],v[2],v[3]);
            *(float4*)(cp+4) = make_float4(v[4],v[5],v[6],v[7]);
        }
    }
}

// ---------------- stage 7: flash attention v2 -> xc[:, :, 384:768] ----------------
// Output write reproduces the reference's transpose+flat-reshape reinterpretation:
// (c = h*HD+d, l) -> flat = c*L + l -> xc[b, flat/C2, C2 + flat%C2].
__global__ void attn_kernel() {
    int qt = blockIdx.x;     // 16 q tiles of 64
    int h  = blockIdx.y;
    int b  = blockIdx.z;
    int tid = threadIdx.x;   // 256
    int tx = tid & 15, ty = tid >> 4;

    __shared__ __align__(16) float qs[48*68];      // q transposed [d][q]
    __shared__ __align__(16) float un[64*65];      // union: ks_t [d][k] (stride 68) / ps [k][q] (stride 65)
    __shared__ __align__(16) float vs[64*52];      // v [k][d]

    const float* qb = g_q  + (size_t)b*L_*C2_ + h*HD_;
    const float* kb = g_kv + (size_t)b*L_*C_  + h*HD_;
    const float* vb = kb + C2_;

    int lr = tid >> 2;               // 0..63
    int d0 = (tid & 3) * 12;         // 0,12,24,36

    {   // load Q tile transposed
        int gl = qt*64 + lr;
        if (gl < L_) {
            #pragma unroll
            for (int t = 0; t < 3; t++) {
                float4 v = *(const float4*)(qb + (size_t)gl*C2_ + d0 + t*4);
                qs[(d0+t*4+0)*68+lr]=v.x; qs[(d0+t*4+1)*68+lr]=v.y;
                qs[(d0+t*4+2)*68+lr]=v.z; qs[(d0+t*4+3)*68+lr]=v.w;
            }
        } else {
            #pragma unroll
            for (int t = 0; t < 12; t++) qs[(d0+t)*68+lr]=0.f;
        }
    }

    float m[4], l[4], o[4][4], corr[4];
    #pragma unroll
    for (int i = 0; i < 4; i++) {
        m[i] = -1e30f; l[i] = 0.f;
        #pragma unroll
        for (int j = 0; j < 4; j++) o[i][j] = 0.f;
    }

    for (int kt = 0; kt < 16; kt++) {
        __syncthreads();   // prev stage2 done; safe to overwrite un/vs
        {
            int gl = kt*64 + lr;
            if (gl < L_) {
                #pragma unroll
                for (int t = 0; t < 3; t++) {
                    float4 kv = *(const float4*)(kb + (size_t)gl*C_ + d0 + t*4);
                    un[(d0+t*4+0)*68+lr]=kv.x; un[(d0+t*4+1)*68+lr]=kv.y;
                    un[(d0+t*4+2)*68+lr]=kv.z; un[(d0+t*4+3)*68+lr]=kv.w;
                    float4 vv = *(const float4*)(vb + (size_t)gl*C_ + d0 + t*4);
                    *(float4*)&vs[lr*52 + d0 + t*4] = vv;
                }
            } else {
                #pragma unroll
                for (int t = 0; t < 12; t++) un[(d0+t)*68+lr]=0.f;
                #pragma unroll
                for (int t = 0; t < 3; t++) *(float4*)&vs[lr*52 + d0 + t*4] = make_float4(0.f,0.f,0.f,0.f);
            }
        }
        __syncthreads();

        // ---- stage 1: S = Q^T K (4x4 micro-tile) ----
        float s[4][4];
        #pragma unroll
        for (int i = 0; i < 4; i++)
            #pragma unroll
            for (int j = 0; j < 4; j++) s[i][j] = 0.f;
        #pragma unroll 8
        for (int d = 0; d < 48; d++) {
            float4 aq = *(float4*)&qs[d*68 + ty*4];
            float4 ak = *(float4*)&un[d*68 + tx*4];
            s[0][0]+=aq.x*ak.x; s[0][1]+=aq.x*ak.y; s[0][2]+=aq.x*ak.z; s[0][3]+=aq.x*ak.w;
            s[1][0]+=aq.y*ak.x; s[1][1]+=aq.y*ak.y; s[1][2]+=aq.y*ak.z; s[1][3]+=aq.y*ak.w;
            s[2][0]+=aq.z*ak.x; s[2][1]+=aq.z*ak.y; s[2][2]+=aq.z*ak.z; s[2][3]+=aq.z*ak.w;
            s[3][0]+=aq.w*ak.x; s[3][1]+=aq.w*ak.y; s[3][2]+=aq.w*ak.z; s[3][3]+=aq.w*ak.w;
        }

        // ---- softmax (running, rows ty*4+i, reduce across 16 tx lanes) ----
        int gk0 = kt*64 + tx*4;
        #pragma unroll
        for (int i = 0; i < 4; i++) {
            #pragma unroll
            for (int j = 0; j < 4; j++)
                s[i][j] = (gk0 + j < L_) ? s[i][j]*SCALE_ : -1e30f;
            float mx = fmaxf(fmaxf(s[i][0],s[i][1]), fmaxf(s[i][2],s[i][3]));
            mx = fmaxf(mx, __shfl_xor_sync(0xffffffffu, mx, 1));
            mx = fmaxf(mx, __shfl_xor_sync(0xffffffffu, mx, 2));
            mx = fmaxf(mx, __shfl_xor_sync(0xffffffffu, mx, 4));
            mx = fmaxf(mx, __shfl_xor_sync(0xffffffffu, mx, 8));
            float mnew = fmaxf(m[i], mx);
            corr[i] = __expf(m[i] - mnew);
            m[i] = mnew;
            float lp = 0.f;
            #pragma unroll
            for (int j = 0; j < 4; j++) { s[i][j] = __expf(s[i][j]-mnew); lp += s[i][j]; }
            lp += __shfl_xor_sync(0xffffffffu, lp, 1);
            lp += __shfl_xor_sync(0xffffffffu, lp, 2);
            lp += __shfl_xor_sync(0xffffffffu, lp, 4);
            lp += __shfl_xor_sync(0xffffffffu, lp, 8);
            l[i] = l[i]*corr[i] + lp;
        }

        __syncthreads();   // stage1 reads of un done; safe to overwrite with P
        #pragma unroll
        for (int i = 0; i < 4; i++)
            #pragma unroll
            for (int j = 0; j < 4; j++)
                un[(tx*4+j)*65 + ty*4+i] = s[i][j];
        __syncthreads();

        // ---- stage 2: O += P V  (4q x 4d micro-tile; tx<12 covers d=48) ----
        if (tx < 12) {
            #pragma unroll
            for (int i = 0; i < 4; i++)
                #pragma unroll
                for (int j = 0; j < 4; j++) o[i][j] *= corr[i];
            #pragma unroll 4
            for (int k = 0; k < 64; k++) {
                float p0 = un[k*65 + ty*4+0];
                float p1 = un[k*65 + ty*4+1];
                float p2 = un[k*65 + ty*4+2];
                float p3 = un[k*65 + ty*4+3];
                float4 v = *(float4*)&vs[k*52 + tx*4];
                o[0][0]+=p0*v.x; o[0][1]+=p0*v.y; o[0][2]+=p0*v.z; o[0][3]+=p0*v.w;
                o[1][0]+=p1*v.x; o[1][1]+=p1*v.y; o[1][2]+=p1*v.z; o[1][3]+=p1*v.w;
                o[2][0]+=p2*v.x; o[2][1]+=p2*v.y; o[2][2]+=p2*v.z; o[2][3]+=p2*v.w;
                o[3][0]+=p3*v.x; o[3][1]+=p3*v.y; o[3][2]+=p3*v.z; o[3][3]+=p3*v.w;
            }
        }
    }

    if (tx < 12) {
        float* xcb = g_xc + (size_t)b*L_*C_;
        #pragma unroll
        for (int i = 0; i < 4; i++) {
            int gl = qt*64 + ty*4 + i;
            if (gl >= L_) continue;
            float inv = 1.f/l[i];
            #pragma unroll
            for (int j = 0; j < 4; j++) {
                int c = h*HD_ + tx*4 + j;
                int flat = c*L_ + gl;
                int lp2 = flat / C2_;
                int cp  = flat - lp2*C2_;
                xcb[(size_t)lp2*C_ + C2_ + cp] = o[i][j]*inv;
            }
        }
    }
}

// ---------------- stage 8a: t1 = gelu(dw3(xc)) ----------------
__global__ void pjdw_kernel(const float* __restrict__ dww, const float* __restrict__ dwb) {
    int b  = blockIdx.y;
    int tid = threadIdx.x;                 // 768: li 0..3, c4 0..191
    int l  = blockIdx.x*4 + (tid/192);
    int c  = (tid%192)*4;
    if (l >= L_) return;
    const float* wp = dww + (size_t)c*3;
    float4 wA = *(const float4*)(wp);
    float4 wB = *(const float4*)(wp+4);
    float4 wC = *(const float4*)(wp+8);
    float4 bv = *(const float4*)(dwb + c);
    const float* xb = g_xc + ((size_t)b*L_ + l)*C_ + c;
    float4 zero = make_float4(0.f,0.f,0.f,0.f);
    float4 xm = (l > 0)    ? *(const float4*)(xb - C_) : zero;
    float4 x0 = *(const float4*)(xb);
    float4 xp = (l+1 < L_) ? *(const float4*)(xb + C_) : zero;
    float4 r;
    r.x = gelu_f(xm.x*wA.x + x0.x*wA.y + xp.x*wA.z + bv.x);
    r.y = gelu_f(xm.y*wA.w + x0.y*wB.x + xp.y*wB.y + bv.y);
    r.z = gelu_f(xm.z*wB.z + x0.z*wB.w + xp.z*wC.x + bv.z);
    r.w = gelu_f(xm.w*wC.y + x0.w*wC.z + xp.w*wC.w + bv.w);
    *(float4*)(g_t1 + ((size_t)b*L_ + l)*C_ + c) = r;
}

// ---------------- deterministic BN stats: partials + finalize -> affine (a,b) ----------
__global__ void stats_partial_kernel(const float* __restrict__ X, int Cch) {
    int blk = blockIdx.x;                  // 127 chunks of 63 rows
    int c   = threadIdx.x;
    int r0 = blk*63, r1 = min(r0+63, M_);
    float s = 0.f, s2 = 0.f;
    for (int r = r0; r < r1; r++) {
        float v = X[(size_t)r*Cch + c];
        s += v; s2 += v*v;
    }
    g_ps [(size_t)blk*Cch + c] = s;
    g_ps2[(size_t)blk*Cch + c] = s2;
}

__global__ void stats_finalize_kernel(int nblk, int Cch,
                                      const float* __restrict__ gam,
                                      const float* __restrict__ bet) {
    int c = blockIdx.x*blockDim.x + threadIdx.x;
    if (c >= Cch) return;
    double s = 0.0, s2 = 0.0;
    for (int i = 0; i < nblk; i++) { s += (double)g_ps[(size_t)i*Cch+c]; s2 += (double)g_ps2[(size_t)i*Cch+c]; }
    double mean = s / (double)M_;
    double var  = s2 / (double)M_ - mean*mean;
    if (var < 0.0) var = 0.0;
    float rs = (float)(1.0 / sqrt(var + (double)EPS_));
    float a  = gam[c]*rs;
    g_an[c] = a;
    g_bn[c] = bet[c] - (float)mean*a;
}

// ---------------- final: out = bn3(t3) + xc ----------------
__global__ void final_add_kernel(float* __restrict__ out) {
    int idx4 = blockIdx.x*blockDim.x + threadIdx.x;
    if (idx4 >= M_*C_/4) return;
    int idx = idx4*4;
    int c = idx % C_;
    float4 t = *(const float4*)(g_t3 + idx);
    float4 xv= *(const float4*)(g_xc + idx);
    float4 a = *(const float4*)(g_an + c);
    float4 bb= *(const float4*)(g_bn + c);
    float4 r;
    r.x = t.x*a.x + bb.x + xv.x;
    r.y = t.y*a.y + bb.y + xv.y;
    r.z = t.z*a.z + bb.z + xv.z;
    r.w = t.w*a.w + bb.w + xv.w;
    *(float4*)(out + idx) = r;
}

// =======================================================================================
extern "C" void kernel_launch(void* const* d_in, const int* in_sizes, int n_in,
                              void* d_out, int out_size) {
    const float* x        = (const float*)d_in[0];
    const float* dc_weight= (const float*)d_in[1];
    const float* dc_bias  = (const float*)d_in[2];
    const float* dc_p1w   = (const float*)d_in[3];
    const float* dc_p1b   = (const float*)d_in[4];
    const float* dc_p2w   = (const float*)d_in[5];
    const float* dc_p2b   = (const float*)d_in[6];
    const float* at_qw    = (const float*)d_in[7];
    const float* at_qb    = (const float*)d_in[8];
    const float* at_kvw   = (const float*)d_in[9];
    const float* at_kvb   = (const float*)d_in[10];
    const float* at_lcw   = (const float*)d_in[11];
    const float* at_lcb   = (const float*)d_in[12];
    const float* pj_dww   = (const float*)d_in[13];
    const float* pj_dwb   = (const float*)d_in[14];
    const float* pj_bn1g  = (const float*)d_in[15];
    const float* pj_bn1b  = (const float*)d_in[16];
    const float* pj_c1w   = (const float*)d_in[17];
    const float* pj_c1b   = (const float*)d_in[18];
    const float* pj_bn2g  = (const float*)d_in[19];
    const float* pj_bn2b  = (const float*)d_in[20];
    const float* pj_c2w   = (const float*)d_in[21];
    const float* pj_c2b   = (const float*)d_in[22];
    const float* pj_bn3g  = (const float*)d_in[23];
    const float* pj_bn3b  = (const float*)d_in[24];
    float* out = (float*)d_out;

    float *pq, *pkvin, *pkv, *pt1, *pt2, *pt3, *pan, *pbn;
    cudaGetSymbolAddress((void**)&pq,    g_q);
    cudaGetSymbolAddress((void**)&pkvin, g_kvin);
    cudaGetSymbolAddress((void**)&pkv,   g_kv);
    cudaGetSymbolAddress((void**)&pt1,   g_t1);
    cudaGetSymbolAddress((void**)&pt2,   g_t2);
    cudaGetSymbolAddress((void**)&pt3,   g_t3);
    cudaGetSymbolAddress((void**)&pan,   g_an);
    cudaGetSymbolAddress((void**)&pbn,   g_bn);

    // ---- branch 1: dynamic conv ----
    pooled_kernel<<<96, C2_>>>(x);
    dcmlp_kernel<<<B_, C2_>>>(dc_p1w, dc_p1b, dc_p2w, dc_p2b, dc_weight, dc_bias);
    dconv_kernel<<<dim3(125, B_), 768>>>(x);

    // ---- branch 2: attention ----
    kvin_kernel<<<dim3(125, B_), 768>>>(x, at_lcw, at_lcb);
    gemm_kernel<<<dim3(63, 3), 256>>>(x + C2_, C_, at_qw, at_qb,
                                      pq, C2_, M_, C2_, C2_, nullptr, nullptr, 0);
    gemm_kernel<<<dim3(63, 6), 256>>>(pkvin, C2_, at_kvw, at_kvb,
                                      pkv, C_, M_, C_, C2_, nullptr, nullptr, 0);
    attn_kernel<<<dim3(16, H_, B_), 256>>>();

    // ---- projection: dw3 + gelu, then BN1 stats ----
    pjdw_kernel<<<dim3(250, B_), 768>>>(pj_dww, pj_dwb);
    stats_partial_kernel<<<127, C_>>>(pt1, C_);
    stats_finalize_kernel<<<3, 256>>>(127, C_, pj_bn1g, pj_bn1b);

    // ---- c1 (bn1 folded into A) + gelu ----
    gemm_kernel<<<dim3(63, 1), 256>>>(pt1, C_, pj_c1w, pj_c1b,
                                      pt2, PJIN_, M_, PJIN_, C_, pan, pbn, 1);
    stats_partial_kernel<<<127, PJIN_>>>(pt2, PJIN_);
    stats_finalize_kernel<<<1, 256>>>(127, PJIN_, pj_bn2g, pj_bn2b);

    // ---- c2 (bn2 folded into A) ----
    gemm_kernel<<<dim3(63, 6), 256>>>(pt2, PJIN_, pj_c2w, pj_c2b,
                                      pt3, C_, M_, C_, PJIN_, pan, pbn, 0);
    stats_partial_kernel<<<127, C_>>>(pt3, C_);
    stats_finalize_kernel<<<3, 256>>>(127, C_, pj_bn3g, pj_bn3b);

    // ---- bn3 + residual ----
    final_add_kernel<<<(M_*C_/4 + 255)/256, 256>>>(out);
}

// round 7
// speedup vs baseline: 1.7700x; 1.1706x over previous
#include <cuda_runtime.h>
#include <math.h>

#define B_    8
#define L_    999
#define C_    768
#define C2_   384
#define H_    8
#define HD_   48
#define K_    3
#define DCIN_ 96
#define PJIN_ 96
#define M_    (B_*L_)          /* 7992 tokens */
#define SCALE_ 0.14433756729740643f
#define EPS_   1e-5f

__device__ __forceinline__ float gelu_f(float v) {
    return 0.5f * v * (1.0f + erff(v * 0.7071067811865475f));
}

// ---- tf32 mma helpers ----
__device__ __forceinline__ unsigned f2tf(float f) {
    unsigned r; asm("cvt.rna.tf32.f32 %0, %1;" : "=r"(r) : "f"(f)); return r;
}
__device__ __forceinline__ void mma_tf32(float* c, const unsigned* a, const unsigned* b) {
    asm volatile("mma.sync.aligned.m16n8k8.row.col.f32.tf32.tf32.f32 "
                 "{%0,%1,%2,%3}, {%4,%5,%6,%7}, {%8,%9}, {%0,%1,%2,%3};"
                 : "+f"(c[0]), "+f"(c[1]), "+f"(c[2]), "+f"(c[3])
                 : "r"(a[0]), "r"(a[1]), "r"(a[2]), "r"(a[3]),
                   "r"(b[0]), "r"(b[1]));
}

// ---------------- scratch (device globals; no allocation allowed) ----------------
__device__ float g_q    [(size_t)M_*C2_];
__device__ float g_kvin [(size_t)M_*C2_];
__device__ float g_kv   [(size_t)M_*C_];
__device__ float g_xc   [(size_t)M_*C_];
__device__ float g_t1   [(size_t)M_*C_];
__device__ float g_t2   [(size_t)M_*PJIN_];
__device__ float g_t3   [(size_t)M_*C_];
__device__ float g_wdyn [B_*C2_*K_];
__device__ float g_bdyn [B_*C2_];
__device__ float g_ps   [128*C_];
__device__ float g_ps2  [128*C_];
__device__ float g_an   [C_];
__device__ float g_bn   [C_];

// ---------------- stage 1: pooled partial sums (4-way split over rows) ----------------
__global__ void pooled_kernel(const float* __restrict__ x) {
    int blk = blockIdx.x;            // (b*3+kk)*4+sub
    int sub = blk & 3;
    int bk  = blk >> 2;
    int b   = bk / K_;
    int kk  = bk % K_;
    int c   = threadIdx.x;           // 384
    int r0 = kk*333 + sub*84;
    int r1 = kk*333 + min(sub*84 + 84, 333);
    const float* xb = x + (size_t)b*L_*C_ + c;
    float s = 0.f;
    for (int l = r0; l < r1; l++) s += xb[(size_t)l*C_];
    g_ps[(size_t)blk*C2_ + c] = s;
}

// ---------------- stage 2: dynamic-conv score MLP + softmax over G ----------------
__global__ void dcmlp_kernel(const float* __restrict__ p1w, const float* __restrict__ p1b,
                             const float* __restrict__ p2w, const float* __restrict__ p2b,
                             const float* __restrict__ dcw, const float* __restrict__ dcb) {
    int b   = blockIdx.x;
    int tid = threadIdx.x;                 // 384
    __shared__ float col[4][C2_];
    __shared__ float hid[4][DCIN_];
    __shared__ float sc [4][2*C2_];
    {
        float cc[3];
        #pragma unroll
        for (int kk = 0; kk < 3; kk++) {
            int base = (b*3+kk)*4;
            cc[kk] = (g_ps[(size_t)(base+0)*C2_+tid] + g_ps[(size_t)(base+1)*C2_+tid]
                    + g_ps[(size_t)(base+2)*C2_+tid] + g_ps[(size_t)(base+3)*C2_+tid]) * (1.0f/333.0f);
            col[kk][tid] = cc[kk];
        }
        col[3][tid] = (cc[0]+cc[1]+cc[2]) * (1.0f/3.0f);
    }
    __syncthreads();
    {
        int kk = tid / DCIN_;
        int i  = tid % DCIN_;
        float s = p1b[i];
        const float* wr = p1w + (size_t)i*C2_;
        #pragma unroll 8
        for (int c = 0; c < C2_; c++) s += wr[c]*col[kk][c];
        hid[kk][i] = gelu_f(s);
    }
    __syncthreads();
    for (int t = tid; t < 4*768; t += 384) {
        int kk = t / 768, o = t % 768;
        float s = p2b[o];
        const float* wr = p2w + (size_t)o*DCIN_;
        #pragma unroll 8
        for (int i = 0; i < DCIN_; i++) s += wr[i]*hid[kk][i];
        sc[kk][o] = s;
    }
    __syncthreads();
    {
        int c = tid;
        #pragma unroll
        for (int kk = 0; kk < 3; kk++) {
            float e0 = sc[kk][c], e1 = sc[kk][C2_+c];
            float mx = fmaxf(e0,e1);
            float a0 = expf(e0-mx), a1 = expf(e1-mx);
            float inv = 1.f/(a0+a1);
            g_wdyn[(b*C2_+c)*3+kk] = (a0*dcw[c*3+kk] + a1*dcw[(C2_+c)*3+kk])*inv;
        }
        float e0 = sc[3][c], e1 = sc[3][C2_+c];
        float mx = fmaxf(e0,e1);
        float a0 = expf(e0-mx), a1 = expf(e1-mx);
        g_bdyn[b*C2_+c] = (a0*dcb[c] + a1*dcb[C2_+c])/(a0+a1);
    }
}

// ---------------- stage 3: dynamic depthwise conv -> xc[:, :, 0:384] ----------------
__global__ void dconv_kernel(const float* __restrict__ x) {
    int b  = blockIdx.y;
    int tid = threadIdx.x;                 // 768: li 0..7, c4 0..95
    int l  = blockIdx.x*8 + (tid/96);
    int c  = (tid%96)*4;
    if (l >= L_) return;
    const float* wp = g_wdyn + ((size_t)b*C2_ + c)*3;
    float4 wA = *(const float4*)(wp);
    float4 wB = *(const float4*)(wp+4);
    float4 wC = *(const float4*)(wp+8);
    float4 bv = *(const float4*)(g_bdyn + (size_t)b*C2_ + c);
    const float* xb = x + ((size_t)b*L_ + l)*C_ + c;
    float4 zero = make_float4(0.f,0.f,0.f,0.f);
    float4 xm = (l > 0)      ? *(const float4*)(xb - C_) : zero;
    float4 x0 = *(const float4*)(xb);
    float4 xp = (l+1 < L_)   ? *(const float4*)(xb + C_) : zero;
    float4 r;
    r.x = xm.x*wA.x + x0.x*wA.y + xp.x*wA.z + bv.x;
    r.y = xm.y*wA.w + x0.y*wB.x + xp.y*wB.y + bv.y;
    r.z = xm.z*wB.z + x0.z*wB.w + xp.z*wC.x + bv.z;
    r.w = xm.w*wC.y + x0.w*wC.z + xp.w*wC.w + bv.w;
    *(float4*)(g_xc + ((size_t)b*L_ + l)*C_ + c) = r;
}

// ---------------- stage 4: kv_in = dw3(x2, lcw, lcb) + x2 ----------------
__global__ void kvin_kernel(const float* __restrict__ x,
                            const float* __restrict__ lcw, const float* __restrict__ lcb) {
    int b  = blockIdx.y;
    int tid = threadIdx.x;                 // 768
    int l  = blockIdx.x*8 + (tid/96);
    int c  = (tid%96)*4;
    if (l >= L_) return;
    const float* wp = lcw + (size_t)c*3;
    float4 wA = *(const float4*)(wp);
    float4 wB = *(const float4*)(wp+4);
    float4 wC = *(const float4*)(wp+8);
    float4 bv = *(const float4*)(lcb + c);
    const float* xb = x + ((size_t)b*L_ + l)*C_ + C2_ + c;
    float4 zero = make_float4(0.f,0.f,0.f,0.f);
    float4 xm = (l > 0)      ? *(const float4*)(xb - C_) : zero;
    float4 x0 = *(const float4*)(xb);
    float4 xp = (l+1 < L_)   ? *(const float4*)(xb + C_) : zero;
    float4 r;
    r.x = xm.x*wA.x + x0.x*wA.y + xp.x*wA.z + bv.x + x0.x;
    r.y = xm.y*wA.w + x0.y*wB.x + xp.y*wB.y + bv.y + x0.y;
    r.z = xm.z*wB.z + x0.z*wB.w + xp.z*wC.x + bv.z + x0.z;
    r.w = xm.w*wC.y + x0.w*wC.z + xp.w*wC.w + bv.w + x0.w;
    *(float4*)(g_kvin + ((size_t)b*L_ + l)*C2_ + c) = r;
}

// ---------------- GEMM v5: tf32 tensor cores, 128x64 block tile, 32x32 warp tile -------
// C[m,n] = sum_k a(A[m,k]) * W[n,k] + bias[n] ; optional per-k affine on A, gelu epilogue
// mma.sync.m16n8k8.row.col: A row-major (m,k), B col-major (k,n) == W row-major (n,k).
__global__ void __launch_bounds__(256, 2)
gemm_kernel(const float* __restrict__ A, int lda,
            const float* __restrict__ W,
            const float* __restrict__ bias,
            float* __restrict__ Cmat, int ldc,
            int M, int N, int Kd,
            const float* __restrict__ ascale,
            const float* __restrict__ ashift,
            int dogelu)
{
    __shared__ unsigned As[128][20];       // [m][k], stride 20 => conflict-free frag LDS
    __shared__ unsigned Ws[64][20];        // [n][k]
    int tid  = threadIdx.x;                // 256 = 8 warps
    int wid  = tid >> 5, lane = tid & 31;
    int gid  = lane >> 2, tig = lane & 3;  // groupID (0..7), thread-in-group (0..3)
    int m0 = blockIdx.x*128, n0 = blockIdx.y*64;
    int mw = (wid >> 1) * 32;              // warp m-offset (0/32/64/96)
    int nw = (wid & 1) * 32;               // warp n-offset (0/32)

    float acc[2][4][4];                    // [m16-tile][n8-tile][frag]
    #pragma unroll
    for (int i = 0; i < 2; i++)
        #pragma unroll
        for (int j = 0; j < 4; j++)
            #pragma unroll
            for (int t = 0; t < 4; t++) acc[i][j][t] = 0.f;

    int alr = tid >> 1, alk = (tid & 1) << 3;   // A stage: row 0..127, k 0/8
    int wlr = tid >> 2, wlk = (tid & 3) << 2;   // W stage: row 0..63,  k 0/4/8/12
    float4 zero = make_float4(0.f,0.f,0.f,0.f);

    for (int k0 = 0; k0 < Kd; k0 += 16) {
        float4 a0 = zero, a1 = zero, w0 = zero;
        int gm = m0 + alr;
        if (gm < M) {
            const float* ap = A + (size_t)gm*lda + k0 + alk;
            a0 = *(const float4*)(ap);
            a1 = *(const float4*)(ap+4);
        }
        if (ascale) {
            int kb = k0 + alk;
            a0.x = a0.x*ascale[kb+0] + ashift[kb+0];
            a0.y = a0.y*ascale[kb+1] + ashift[kb+1];
            a0.z = a0.z*ascale[kb+2] + ashift[kb+2];
            a0.w = a0.w*ascale[kb+3] + ashift[kb+3];
            a1.x = a1.x*ascale[kb+4] + ashift[kb+4];
            a1.y = a1.y*ascale[kb+5] + ashift[kb+5];
            a1.z = a1.z*ascale[kb+6] + ashift[kb+6];
            a1.w = a1.w*ascale[kb+7] + ashift[kb+7];
        }
        int gn = n0 + wlr;
        if (gn < N) w0 = *(const float4*)(W + (size_t)gn*Kd + k0 + wlk);
        __syncthreads();
        As[alr][alk+0]=f2tf(a0.x); As[alr][alk+1]=f2tf(a0.y);
        As[alr][alk+2]=f2tf(a0.z); As[alr][alk+3]=f2tf(a0.w);
        As[alr][alk+4]=f2tf(a1.x); As[alr][alk+5]=f2tf(a1.y);
        As[alr][alk+6]=f2tf(a1.z); As[alr][alk+7]=f2tf(a1.w);
        Ws[wlr][wlk+0]=f2tf(w0.x); Ws[wlr][wlk+1]=f2tf(w0.y);
        Ws[wlr][wlk+2]=f2tf(w0.z); Ws[wlr][wlk+3]=f2tf(w0.w);
        __syncthreads();
        #pragma unroll
        for (int k8 = 0; k8 < 16; k8 += 8) {
            unsigned bfr[4][2];
            #pragma unroll
            for (int nt = 0; nt < 4; nt++) {
                int nb = nw + nt*8 + gid;
                bfr[nt][0] = Ws[nb][k8 + tig];
                bfr[nt][1] = Ws[nb][k8 + 4 + tig];
            }
            #pragma unroll
            for (int mt = 0; mt < 2; mt++) {
                int mb = mw + mt*16 + gid;
                unsigned afr[4];
                afr[0] = As[mb    ][k8 + tig];
                afr[1] = As[mb + 8][k8 + tig];
                afr[2] = As[mb    ][k8 + 4 + tig];
                afr[3] = As[mb + 8][k8 + 4 + tig];
                #pragma unroll
                for (int nt = 0; nt < 4; nt++)
                    mma_tf32(acc[mt][nt], afr, bfr[nt]);
            }
        }
    }

    // epilogue: C-frag layout -> rows gid, gid+8; cols 2*tig, 2*tig+1 per 16x8 tile
    #pragma unroll
    for (int mt = 0; mt < 2; mt++) {
        #pragma unroll
        for (int nt = 0; nt < 4; nt++) {
            int gn = n0 + nw + nt*8 + 2*tig;
            if (gn >= N) continue;
            float b0v = bias[gn], b1v = bias[gn+1];
            int gm0 = m0 + mw + mt*16 + gid;
            if (gm0 < M) {
                float v0 = acc[mt][nt][0] + b0v;
                float v1 = acc[mt][nt][1] + b1v;
                if (dogelu) { v0 = gelu_f(v0); v1 = gelu_f(v1); }
                *(float2*)(Cmat + (size_t)gm0*ldc + gn) = make_float2(v0, v1);
            }
            int gm1 = gm0 + 8;
            if (gm1 < M) {
                float v2 = acc[mt][nt][2] + b0v;
                float v3 = acc[mt][nt][3] + b1v;
                if (dogelu) { v2 = gelu_f(v2); v3 = gelu_f(v3); }
                *(float2*)(Cmat + (size_t)gm1*ldc + gn) = make_float2(v2, v3);
            }
        }
    }
}

// ---------------- stage 7: flash attention (fp32 SIMT) -> xc[:, :, 384:768] ----------------
// Output write reproduces the reference's transpose+flat-reshape reinterpretation:
// (c = h*HD+d, l) -> flat = c*L + l -> xc[b, flat/C2, C2 + flat%C2].
__global__ void attn_kernel() {
    int qt = blockIdx.x;     // 16 q tiles of 64
    int h  = blockIdx.y;
    int b  = blockIdx.z;
    int tid = threadIdx.x;   // 256
    int tx = tid & 15, ty = tid >> 4;

    __shared__ __align__(16) float qs[48*68];      // q transposed [d][q]
    __shared__ __align__(16) float un[64*65];      // union: ks_t [d][k] (stride 68) / ps [k][q] (stride 65)
    __shared__ __align__(16) float vs[64*52];      // v [k][d]

    const float* qb = g_q  + (size_t)b*L_*C2_ + h*HD_;
    const float* kb = g_kv + (size_t)b*L_*C_  + h*HD_;
    const float* vb = kb + C2_;

    int lr = tid >> 2;               // 0..63
    int d0 = (tid & 3) * 12;         // 0,12,24,36

    {   // load Q tile transposed
        int gl = qt*64 + lr;
        if (gl < L_) {
            #pragma unroll
            for (int t = 0; t < 3; t++) {
                float4 v = *(const float4*)(qb + (size_t)gl*C2_ + d0 + t*4);
                qs[(d0+t*4+0)*68+lr]=v.x; qs[(d0+t*4+1)*68+lr]=v.y;
                qs[(d0+t*4+2)*68+lr]=v.z; qs[(d0+t*4+3)*68+lr]=v.w;
            }
        } else {
            #pragma unroll
            for (int t = 0; t < 12; t++) qs[(d0+t)*68+lr]=0.f;
        }
    }

    float m[4], l[4], o[4][4], corr[4];
    #pragma unroll
    for (int i = 0; i < 4; i++) {
        m[i] = -1e30f; l[i] = 0.f;
        #pragma unroll
        for (int j = 0; j < 4; j++) o[i][j] = 0.f;
    }

    for (int kt = 0; kt < 16; kt++) {
        __syncthreads();   // prev stage2 done; safe to overwrite un/vs
        {
            int gl = kt*64 + lr;
            if (gl < L_) {
                #pragma unroll
                for (int t = 0; t < 3; t++) {
                    float4 kv = *(const float4*)(kb + (size_t)gl*C_ + d0 + t*4);
                    un[(d0+t*4+0)*68+lr]=kv.x; un[(d0+t*4+1)*68+lr]=kv.y;
                    un[(d0+t*4+2)*68+lr]=kv.z; un[(d0+t*4+3)*68+lr]=kv.w;
                    float4 vv = *(const float4*)(vb + (size_t)gl*C_ + d0 + t*4);
                    *(float4*)&vs[lr*52 + d0 + t*4] = vv;
                }
            } else {
                #pragma unroll
                for (int t = 0; t < 12; t++) un[(d0+t)*68+lr]=0.f;
                #pragma unroll
                for (int t = 0; t < 3; t++) *(float4*)&vs[lr*52 + d0 + t*4] = make_float4(0.f,0.f,0.f,0.f);
            }
        }
        __syncthreads();

        // ---- stage 1: S = Q^T K (4x4 micro-tile) ----
        float s[4][4];
        #pragma unroll
        for (int i = 0; i < 4; i++)
            #pragma unroll
            for (int j = 0; j < 4; j++) s[i][j] = 0.f;
        #pragma unroll 8
        for (int d = 0; d < 48; d++) {
            float4 aq = *(float4*)&qs[d*68 + ty*4];
            float4 ak = *(float4*)&un[d*68 + tx*4];
            s[0][0]+=aq.x*ak.x; s[0][1]+=aq.x*ak.y; s[0][2]+=aq.x*ak.z; s[0][3]+=aq.x*ak.w;
            s[1][0]+=aq.y*ak.x; s[1][1]+=aq.y*ak.y; s[1][2]+=aq.y*ak.z; s[1][3]+=aq.y*ak.w;
            s[2][0]+=aq.z*ak.x; s[2][1]+=aq.z*ak.y; s[2][2]+=aq.z*ak.z; s[2][3]+=aq.z*ak.w;
            s[3][0]+=aq.w*ak.x; s[3][1]+=aq.w*ak.y; s[3][2]+=aq.w*ak.z; s[3][3]+=aq.w*ak.w;
        }

        // ---- softmax (running, rows ty*4+i, reduce across 16 tx lanes) ----
        int gk0 = kt*64 + tx*4;
        #pragma unroll
        for (int i = 0; i < 4; i++) {
            #pragma unroll
            for (int j = 0; j < 4; j++)
                s[i][j] = (gk0 + j < L_) ? s[i][j]*SCALE_ : -1e30f;
            float mx = fmaxf(fmaxf(s[i][0],s[i][1]), fmaxf(s[i][2],s[i][3]));
            mx = fmaxf(mx, __shfl_xor_sync(0xffffffffu, mx, 1));
            mx = fmaxf(mx, __shfl_xor_sync(0xffffffffu, mx, 2));
            mx = fmaxf(mx, __shfl_xor_sync(0xffffffffu, mx, 4));
            mx = fmaxf(mx, __shfl_xor_sync(0xffffffffu, mx, 8));
            float mnew = fmaxf(m[i], mx);
            corr[i] = __expf(m[i] - mnew);
            m[i] = mnew;
            float lp = 0.f;
            #pragma unroll
            for (int j = 0; j < 4; j++) { s[i][j] = __expf(s[i][j]-mnew); lp += s[i][j]; }
            lp += __shfl_xor_sync(0xffffffffu, lp, 1);
            lp += __shfl_xor_sync(0xffffffffu, lp, 2);
            lp += __shfl_xor_sync(0xffffffffu, lp, 4);
            lp += __shfl_xor_sync(0xffffffffu, lp, 8);
            l[i] = l[i]*corr[i] + lp;
        }

        __syncthreads();   // stage1 reads of un done; safe to overwrite with P
        #pragma unroll
        for (int i = 0; i < 4; i++)
            #pragma unroll
            for (int j = 0; j < 4; j++)
                un[(tx*4+j)*65 + ty*4+i] = s[i][j];
        __syncthreads();

        // ---- stage 2: O += P V  (4q x 4d micro-tile; tx<12 covers d=48) ----
        if (tx < 12) {
            #pragma unroll
            for (int i = 0; i < 4; i++)
                #pragma unroll
                for (int j = 0; j < 4; j++) o[i][j] *= corr[i];
            #pragma unroll 4
            for (int k = 0; k < 64; k++) {
                float p0 = un[k*65 + ty*4+0];
                float p1 = un[k*65 + ty*4+1];
                float p2 = un[k*65 + ty*4+2];
                float p3 = un[k*65 + ty*4+3];
                float4 v = *(float4*)&vs[k*52 + tx*4];
                o[0][0]+=p0*v.x; o[0][1]+=p0*v.y; o[0][2]+=p0*v.z; o[0][3]+=p0*v.w;
                o[1][0]+=p1*v.x; o[1][1]+=p1*v.y; o[1][2]+=p1*v.z; o[1][3]+=p1*v.w;
                o[2][0]+=p2*v.x; o[2][1]+=p2*v.y; o[2][2]+=p2*v.z; o[2][3]+=p2*v.w;
                o[3][0]+=p3*v.x; o[3][1]+=p3*v.y; o[3][2]+=p3*v.z; o[3][3]+=p3*v.w;
            }
        }
    }

    if (tx < 12) {
        float* xcb = g_xc + (size_t)b*L_*C_;
        #pragma unroll
        for (int i = 0; i < 4; i++) {
            int gl = qt*64 + ty*4 + i;
            if (gl >= L_) continue;
            float inv = 1.f/l[i];
            #pragma unroll
            for (int j = 0; j < 4; j++) {
                int c = h*HD_ + tx*4 + j;
                int flat = c*L_ + gl;
                int lp2 = flat / C2_;
                int cp  = flat - lp2*C2_;
                xcb[(size_t)lp2*C_ + C2_ + cp] = o[i][j]*inv;
            }
        }
    }
}

// ---------------- stage 8a: t1 = gelu(dw3(xc)) ----------------
__global__ void pjdw_kernel(const float* __restrict__ dww, const float* __restrict__ dwb) {
    int b  = blockIdx.y;
    int tid = threadIdx.x;                 // 768: li 0..3, c4 0..191
    int l  = blockIdx.x*4 + (tid/192);
    int c  = (tid%192)*4;
    if (l >= L_) return;
    const float* wp = dww + (size_t)c*3;
    float4 wA = *(const float4*)(wp);
    float4 wB = *(const float4*)(wp+4);
    float4 wC = *(const float4*)(wp+8);
    float4 bv = *(const float4*)(dwb + c);
    const float* xb = g_xc + ((size_t)b*L_ + l)*C_ + c;
    float4 zero = make_float4(0.f,0.f,0.f,0.f);
    float4 xm = (l > 0)    ? *(const float4*)(xb - C_) : zero;
    float4 x0 = *(const float4*)(xb);
    float4 xp = (l+1 < L_) ? *(const float4*)(xb + C_) : zero;
    float4 r;
    r.x = gelu_f(xm.x*wA.x + x0.x*wA.y + xp.x*wA.z + bv.x);
    r.y = gelu_f(xm.y*wA.w + x0.y*wB.x + xp.y*wB.y + bv.y);
    r.z = gelu_f(xm.z*wB.z + x0.z*wB.w + xp.z*wC.x + bv.z);
    r.w = gelu_f(xm.w*wC.y + x0.w*wC.z + xp.w*wC.w + bv.w);
    *(float4*)(g_t1 + ((size_t)b*L_ + l)*C_ + c) = r;
}

// ---------------- deterministic BN stats: partials + finalize -> affine (a,b) ----------
__global__ void stats_partial_kernel(const float* __restrict__ X, int Cch) {
    int blk = blockIdx.x;                  // 127 chunks of 63 rows
    int c   = threadIdx.x;
    int r0 = blk*63, r1 = min(r0+63, M_);
    float s = 0.f, s2 = 0.f;
    for (int r = r0; r < r1; r++) {
        float v = X[(size_t)r*Cch + c];
        s += v; s2 += v*v;
    }
    g_ps [(size_t)blk*Cch + c] = s;
    g_ps2[(size_t)blk*Cch + c] = s2;
}

__global__ void stats_finalize_kernel(int nblk, int Cch,
                                      const float* __restrict__ gam,
                                      const float* __restrict__ bet) {
    int c = blockIdx.x*blockDim.x + threadIdx.x;
    if (c >= Cch) return;
    double s = 0.0, s2 = 0.0;
    for (int i = 0; i < nblk; i++) { s += (double)g_ps[(size_t)i*Cch+c]; s2 += (double)g_ps2[(size_t)i*Cch+c]; }
    double mean = s / (double)M_;
    double var  = s2 / (double)M_ - mean*mean;
    if (var < 0.0) var = 0.0;
    float rs = (float)(1.0 / sqrt(var + (double)EPS_));
    float a  = gam[c]*rs;
    g_an[c] = a;
    g_bn[c] = bet[c] - (float)mean*a;
}

// ---------------- final: out = bn3(t3) + xc ----------------
__global__ void final_add_kernel(float* __restrict__ out) {
    int idx4 = blockIdx.x*blockDim.x + threadIdx.x;
    if (idx4 >= M_*C_/4) return;
    int idx = idx4*4;
    int c = idx % C_;
    float4 t = *(const float4*)(g_t3 + idx);
    float4 xv= *(const float4*)(g_xc + idx);
    float4 a = *(const float4*)(g_an + c);
    float4 bb= *(const float4*)(g_bn + c);
    float4 r;
    r.x = t.x*a.x + bb.x + xv.x;
    r.y = t.y*a.y + bb.y + xv.y;
    r.z = t.z*a.z + bb.z + xv.z;
    r.w = t.w*a.w + bb.w + xv.w;
    *(float4*)(out + idx) = r;
}

// =======================================================================================
extern "C" void kernel_launch(void* const* d_in, const int* in_sizes, int n_in,
                              void* d_out, int out_size) {
    const float* x        = (const float*)d_in[0];
    const float* dc_weight= (const float*)d_in[1];
    const float* dc_bias  = (const float*)d_in[2];
    const float* dc_p1w   = (const float*)d_in[3];
    const float* dc_p1b   = (const float*)d_in[4];
    const float* dc_p2w   = (const float*)d_in[5];
    const float* dc_p2b   = (const float*)d_in[6];
    const float* at_qw    = (const float*)d_in[7];
    const float* at_qb    = (const float*)d_in[8];
    const float* at_kvw   = (const float*)d_in[9];
    const float* at_kvb   = (const float*)d_in[10];
    const float* at_lcw   = (const float*)d_in[11];
    const float* at_lcb   = (const float*)d_in[12];
    const float* pj_dww   = (const float*)d_in[13];
    const float* pj_dwb   = (const float*)d_in[14];
    const float* pj_bn1g  = (const float*)d_in[15];
    const float* pj_bn1b  = (const float*)d_in[16];
    const float* pj_c1w   = (const float*)d_in[17];
    const float* pj_c1b   = (const float*)d_in[18];
    const float* pj_bn2g  = (const float*)d_in[19];
    const float* pj_bn2b  = (const float*)d_in[20];
    const float* pj_c2w   = (const float*)d_in[21];
    const float* pj_c2b   = (const float*)d_in[22];
    const float* pj_bn3g  = (const float*)d_in[23];
    const float* pj_bn3b  = (const float*)d_in[24];
    float* out = (float*)d_out;

    float *pq, *pkvin, *pkv, *pt1, *pt2, *pt3, *pan, *pbn;
    cudaGetSymbolAddress((void**)&pq,    g_q);
    cudaGetSymbolAddress((void**)&pkvin, g_kvin);
    cudaGetSymbolAddress((void**)&pkv,   g_kv);
    cudaGetSymbolAddress((void**)&pt1,   g_t1);
    cudaGetSymbolAddress((void**)&pt2,   g_t2);
    cudaGetSymbolAddress((void**)&pt3,   g_t3);
    cudaGetSymbolAddress((void**)&pan,   g_an);
    cudaGetSymbolAddress((void**)&pbn,   g_bn);

    // ---- branch 1: dynamic conv ----
    pooled_kernel<<<96, C2_>>>(x);
    dcmlp_kernel<<<B_, C2_>>>(dc_p1w, dc_p1b, dc_p2w, dc_p2b, dc_weight, dc_bias);
    dconv_kernel<<<dim3(125, B_), 768>>>(x);

    // ---- branch 2: attention ----
    kvin_kernel<<<dim3(125, B_), 768>>>(x, at_lcw, at_lcb);
    gemm_kernel<<<dim3(63, 6), 256>>>(x + C2_, C_, at_qw, at_qb,
                                      pq, C2_, M_, C2_, C2_, nullptr, nullptr, 0);
    gemm_kernel<<<dim3(63, 12), 256>>>(pkvin, C2_, at_kvw, at_kvb,
                                       pkv, C_, M_, C_, C2_, nullptr, nullptr, 0);
    attn_kernel<<<dim3(16, H_, B_), 256>>>();

    // ---- projection: dw3 + gelu, then BN1 stats ----
    pjdw_kernel<<<dim3(250, B_), 768>>>(pj_dww, pj_dwb);
    stats_partial_kernel<<<127, C_>>>(pt1, C_);
    stats_finalize_kernel<<<3, 256>>>(127, C_, pj_bn1g, pj_bn1b);

    // ---- c1 (bn1 folded into A) + gelu ----
    gemm_kernel<<<dim3(63, 2), 256>>>(pt1, C_, pj_c1w, pj_c1b,
                                      pt2, PJIN_, M_, PJIN_, C_, pan, pbn, 1);
    stats_partial_kernel<<<127, PJIN_>>>(pt2, PJIN_);
    stats_finalize_kernel<<<1, 256>>>(127, PJIN_, pj_bn2g, pj_bn2b);

    // ---- c2 (bn2 folded into A) ----
    gemm_kernel<<<dim3(63, 12), 256>>>(pt2, PJIN_, pj_c2w, pj_c2b,
                                       pt3, C_, M_, C_, PJIN_, pan, pbn, 0);
    stats_partial_kernel<<<127, C_>>>(pt3, C_);
    stats_finalize_kernel<<<3, 256>>>(127, C_, pj_bn3g, pj_bn3b);

    // ---- bn3 + residual ----
    final_add_kernel<<<(M_*C_/4 + 255)/256, 256>>>(out);
}

// round 8
// speedup vs baseline: 2.4655x; 1.3930x over previous
#include <cuda_runtime.h>
#include <math.h>

#define B_    8
#define L_    999
#define C_    768
#define C2_   384
#define H_    8
#define HD_   48
#define K_    3
#define DCIN_ 96
#define PJIN_ 96
#define M_    (B_*L_)          /* 7992 tokens */
#define SCALE_ 0.14433756729740643f
#define EPS_   1e-5f

__device__ __forceinline__ float gelu_f(float v) {
    return 0.5f * v * (1.0f + erff(v * 0.7071067811865475f));
}

// ---- tf32 mma helpers (validated R7) ----
__device__ __forceinline__ unsigned f2tf(float f) {
    unsigned r; asm("cvt.rna.tf32.f32 %0, %1;" : "=r"(r) : "f"(f)); return r;
}
__device__ __forceinline__ void mma_tf32(float* c, const unsigned* a, const unsigned* b) {
    asm volatile("mma.sync.aligned.m16n8k8.row.col.f32.tf32.tf32.f32 "
                 "{%0,%1,%2,%3}, {%4,%5,%6,%7}, {%8,%9}, {%0,%1,%2,%3};"
                 : "+f"(c[0]), "+f"(c[1]), "+f"(c[2]), "+f"(c[3])
                 : "r"(a[0]), "r"(a[1]), "r"(a[2]), "r"(a[3]),
                   "r"(b[0]), "r"(b[1]));
}

// ---------------- scratch (device globals; no allocation allowed) ----------------
__device__ float g_q    [(size_t)M_*C2_];
__device__ float g_kvin [(size_t)M_*C2_];
__device__ float g_kv   [(size_t)M_*C_];
__device__ float g_xc   [(size_t)M_*C_];
__device__ float g_t1   [(size_t)M_*C_];
__device__ float g_t2   [(size_t)M_*PJIN_];
__device__ float g_t3   [(size_t)M_*C_];
__device__ float g_wdyn [B_*C2_*K_];
__device__ float g_bdyn [B_*C2_];
__device__ float g_ps   [128*C_];
__device__ float g_ps2  [128*C_];
__device__ float g_an   [C_];
__device__ float g_bn   [C_];

// ---------------- stage 1: pooled partial sums (4-way split over rows) ----------------
__global__ void pooled_kernel(const float* __restrict__ x) {
    int blk = blockIdx.x;            // (b*3+kk)*4+sub
    int sub = blk & 3;
    int bk  = blk >> 2;
    int b   = bk / K_;
    int kk  = bk % K_;
    int c   = threadIdx.x;           // 384
    int r0 = kk*333 + sub*84;
    int r1 = kk*333 + min(sub*84 + 84, 333);
    const float* xb = x + (size_t)b*L_*C_ + c;
    float s = 0.f;
    for (int l = r0; l < r1; l++) s += xb[(size_t)l*C_];
    g_ps[(size_t)blk*C2_ + c] = s;
}

// ---------------- stage 2: dynamic-conv score MLP + softmax over G ----------------
__global__ void dcmlp_kernel(const float* __restrict__ p1w, const float* __restrict__ p1b,
                             const float* __restrict__ p2w, const float* __restrict__ p2b,
                             const float* __restrict__ dcw, const float* __restrict__ dcb) {
    int b   = blockIdx.x;
    int tid = threadIdx.x;                 // 384
    __shared__ float col[4][C2_];
    __shared__ float hid[4][DCIN_];
    __shared__ float sc [4][2*C2_];
    {
        float cc[3];
        #pragma unroll
        for (int kk = 0; kk < 3; kk++) {
            int base = (b*3+kk)*4;
            cc[kk] = (g_ps[(size_t)(base+0)*C2_+tid] + g_ps[(size_t)(base+1)*C2_+tid]
                    + g_ps[(size_t)(base+2)*C2_+tid] + g_ps[(size_t)(base+3)*C2_+tid]) * (1.0f/333.0f);
            col[kk][tid] = cc[kk];
        }
        col[3][tid] = (cc[0]+cc[1]+cc[2]) * (1.0f/3.0f);
    }
    __syncthreads();
    {
        int kk = tid / DCIN_;
        int i  = tid % DCIN_;
        float s = p1b[i];
        const float* wr = p1w + (size_t)i*C2_;
        #pragma unroll 8
        for (int c = 0; c < C2_; c++) s += wr[c]*col[kk][c];
        hid[kk][i] = gelu_f(s);
    }
    __syncthreads();
    for (int t = tid; t < 4*768; t += 384) {
        int kk = t / 768, o = t % 768;
        float s = p2b[o];
        const float* wr = p2w + (size_t)o*DCIN_;
        #pragma unroll 8
        for (int i = 0; i < DCIN_; i++) s += wr[i]*hid[kk][i];
        sc[kk][o] = s;
    }
    __syncthreads();
    {
        int c = tid;
        #pragma unroll
        for (int kk = 0; kk < 3; kk++) {
            float e0 = sc[kk][c], e1 = sc[kk][C2_+c];
            float mx = fmaxf(e0,e1);
            float a0 = expf(e0-mx), a1 = expf(e1-mx);
            float inv = 1.f/(a0+a1);
            g_wdyn[(b*C2_+c)*3+kk] = (a0*dcw[c*3+kk] + a1*dcw[(C2_+c)*3+kk])*inv;
        }
        float e0 = sc[3][c], e1 = sc[3][C2_+c];
        float mx = fmaxf(e0,e1);
        float a0 = expf(e0-mx), a1 = expf(e1-mx);
        g_bdyn[b*C2_+c] = (a0*dcb[c] + a1*dcb[C2_+c])/(a0+a1);
    }
}

// ---------------- stage 3: dynamic depthwise conv -> xc[:, :, 0:384] ----------------
__global__ void dconv_kernel(const float* __restrict__ x) {
    int b  = blockIdx.y;
    int tid = threadIdx.x;                 // 768: li 0..7, c4 0..95
    int l  = blockIdx.x*8 + (tid/96);
    int c  = (tid%96)*4;
    if (l >= L_) return;
    const float* wp = g_wdyn + ((size_t)b*C2_ + c)*3;
    float4 wA = *(const float4*)(wp);
    float4 wB = *(const float4*)(wp+4);
    float4 wC = *(const float4*)(wp+8);
    float4 bv = *(const float4*)(g_bdyn + (size_t)b*C2_ + c);
    const float* xb = x + ((size_t)b*L_ + l)*C_ + c;
    float4 zero = make_float4(0.f,0.f,0.f,0.f);
    float4 xm = (l > 0)      ? *(const float4*)(xb - C_) : zero;
    float4 x0 = *(const float4*)(xb);
    float4 xp = (l+1 < L_)   ? *(const float4*)(xb + C_) : zero;
    float4 r;
    r.x = xm.x*wA.x + x0.x*wA.y + xp.x*wA.z + bv.x;
    r.y = xm.y*wA.w + x0.y*wB.x + xp.y*wB.y + bv.y;
    r.z = xm.z*wB.z + x0.z*wB.w + xp.z*wC.x + bv.z;
    r.w = xm.w*wC.y + x0.w*wC.z + xp.w*wC.w + bv.w;
    *(float4*)(g_xc + ((size_t)b*L_ + l)*C_ + c) = r;
}

// ---------------- stage 4: kv_in = dw3(x2, lcw, lcb) + x2 ----------------
__global__ void kvin_kernel(const float* __restrict__ x,
                            const float* __restrict__ lcw, const float* __restrict__ lcb) {
    int b  = blockIdx.y;
    int tid = threadIdx.x;                 // 768
    int l  = blockIdx.x*8 + (tid/96);
    int c  = (tid%96)*4;
    if (l >= L_) return;
    const float* wp = lcw + (size_t)c*3;
    float4 wA = *(const float4*)(wp);
    float4 wB = *(const float4*)(wp+4);
    float4 wC = *(const float4*)(wp+8);
    float4 bv = *(const float4*)(lcb + c);
    const float* xb = x + ((size_t)b*L_ + l)*C_ + C2_ + c;
    float4 zero = make_float4(0.f,0.f,0.f,0.f);
    float4 xm = (l > 0)      ? *(const float4*)(xb - C_) : zero;
    float4 x0 = *(const float4*)(xb);
    float4 xp = (l+1 < L_)   ? *(const float4*)(xb + C_) : zero;
    float4 r;
    r.x = xm.x*wA.x + x0.x*wA.y + xp.x*wA.z + bv.x + x0.x;
    r.y = xm.y*wA.w + x0.y*wB.x + xp.y*wB.y + bv.y + x0.y;
    r.z = xm.z*wB.z + x0.z*wB.w + xp.z*wC.x + bv.z + x0.z;
    r.w = xm.w*wC.y + x0.w*wC.z + xp.w*wC.w + bv.w + x0.w;
    *(float4*)(g_kvin + ((size_t)b*L_ + l)*C2_ + c) = r;
}

// ---------------- GEMM v5: tf32 tensor cores, 128x64 block tile, 32x32 warp tile -------
__global__ void __launch_bounds__(256, 2)
gemm_kernel(const float* __restrict__ A, int lda,
            const float* __restrict__ W,
            const float* __restrict__ bias,
            float* __restrict__ Cmat, int ldc,
            int M, int N, int Kd,
            const float* __restrict__ ascale,
            const float* __restrict__ ashift,
            int dogelu)
{
    __shared__ unsigned As[128][20];
    __shared__ unsigned Ws[64][20];
    int tid  = threadIdx.x;                // 256 = 8 warps
    int wid  = tid >> 5, lane = tid & 31;
    int gid  = lane >> 2, tig = lane & 3;
    int m0 = blockIdx.x*128, n0 = blockIdx.y*64;
    int mw = (wid >> 1) * 32;
    int nw = (wid & 1) * 32;

    float acc[2][4][4];
    #pragma unroll
    for (int i = 0; i < 2; i++)
        #pragma unroll
        for (int j = 0; j < 4; j++)
            #pragma unroll
            for (int t = 0; t < 4; t++) acc[i][j][t] = 0.f;

    int alr = tid >> 1, alk = (tid & 1) << 3;
    int wlr = tid >> 2, wlk = (tid & 3) << 2;
    float4 zero = make_float4(0.f,0.f,0.f,0.f);

    for (int k0 = 0; k0 < Kd; k0 += 16) {
        float4 a0 = zero, a1 = zero, w0 = zero;
        int gm = m0 + alr;
        if (gm < M) {
            const float* ap = A + (size_t)gm*lda + k0 + alk;
            a0 = *(const float4*)(ap);
            a1 = *(const float4*)(ap+4);
        }
        if (ascale) {
            int kb = k0 + alk;
            a0.x = a0.x*ascale[kb+0] + ashift[kb+0];
            a0.y = a0.y*ascale[kb+1] + ashift[kb+1];
            a0.z = a0.z*ascale[kb+2] + ashift[kb+2];
            a0.w = a0.w*ascale[kb+3] + ashift[kb+3];
            a1.x = a1.x*ascale[kb+4] + ashift[kb+4];
            a1.y = a1.y*ascale[kb+5] + ashift[kb+5];
            a1.z = a1.z*ascale[kb+6] + ashift[kb+6];
            a1.w = a1.w*ascale[kb+7] + ashift[kb+7];
        }
        int gn = n0 + wlr;
        if (gn < N) w0 = *(const float4*)(W + (size_t)gn*Kd + k0 + wlk);
        __syncthreads();
        As[alr][alk+0]=f2tf(a0.x); As[alr][alk+1]=f2tf(a0.y);
        As[alr][alk+2]=f2tf(a0.z); As[alr][alk+3]=f2tf(a0.w);
        As[alr][alk+4]=f2tf(a1.x); As[alr][alk+5]=f2tf(a1.y);
        As[alr][alk+6]=f2tf(a1.z); As[alr][alk+7]=f2tf(a1.w);
        Ws[wlr][wlk+0]=f2tf(w0.x); Ws[wlr][wlk+1]=f2tf(w0.y);
        Ws[wlr][wlk+2]=f2tf(w0.z); Ws[wlr][wlk+3]=f2tf(w0.w);
        __syncthreads();
        #pragma unroll
        for (int k8 = 0; k8 < 16; k8 += 8) {
            unsigned bfr[4][2];
            #pragma unroll
            for (int nt = 0; nt < 4; nt++) {
                int nb = nw + nt*8 + gid;
                bfr[nt][0] = Ws[nb][k8 + tig];
                bfr[nt][1] = Ws[nb][k8 + 4 + tig];
            }
            #pragma unroll
            for (int mt = 0; mt < 2; mt++) {
                int mb = mw + mt*16 + gid;
                unsigned afr[4];
                afr[0] = As[mb    ][k8 + tig];
                afr[1] = As[mb + 8][k8 + tig];
                afr[2] = As[mb    ][k8 + 4 + tig];
                afr[3] = As[mb + 8][k8 + 4 + tig];
                #pragma unroll
                for (int nt = 0; nt < 4; nt++)
                    mma_tf32(acc[mt][nt], afr, bfr[nt]);
            }
        }
    }

    #pragma unroll
    for (int mt = 0; mt < 2; mt++) {
        #pragma unroll
        for (int nt = 0; nt < 4; nt++) {
            int gn = n0 + nw + nt*8 + 2*tig;
            if (gn >= N) continue;
            float b0v = bias[gn], b1v = bias[gn+1];
            int gm0 = m0 + mw + mt*16 + gid;
            if (gm0 < M) {
                float v0 = acc[mt][nt][0] + b0v;
                float v1 = acc[mt][nt][1] + b1v;
                if (dogelu) { v0 = gelu_f(v0); v1 = gelu_f(v1); }
                *(float2*)(Cmat + (size_t)gm0*ldc + gn) = make_float2(v0, v1);
            }
            int gm1 = gm0 + 8;
            if (gm1 < M) {
                float v2 = acc[mt][nt][2] + b0v;
                float v3 = acc[mt][nt][3] + b1v;
                if (dogelu) { v2 = gelu_f(v2); v3 = gelu_f(v3); }
                *(float2*)(Cmat + (size_t)gm1*ldc + gn) = make_float2(v2, v3);
            }
        }
    }
}

// ---------------- stage 7: flash attention v4 (tf32 mma) -> xc[:, :, 384:768] ----------
// Block: 128 q-rows, 8 warps; warp = private 16-row q-group over full 64-key tiles.
// Output reproduces the reference transpose+flat-reshape reinterpretation:
// (c = h*HD+d, l) -> flat = c*L + l -> xc[b, flat/C2, C2 + flat%C2].
__global__ void __launch_bounds__(256, 2) attn_kernel() {
    // smem: sh_ps (union: Q staging [128][52] / K tile [64][52] / P [128][68]) + V [64][56]
    __shared__ unsigned sh_ps[128*68];     // 34816 B
    __shared__ unsigned sh_vs[64*56];      // 14336 B  (total 49152 = 48KB)
    int qt = blockIdx.x;                   // 8 q tiles of 128
    int h  = blockIdx.y;
    int b  = blockIdx.z;
    int tid = threadIdx.x;                 // 256
    int wid = tid >> 5, lane = tid & 31;
    int gid = lane >> 2, tig = lane & 3;
    int qw  = wid*16;

    const float* qb = g_q  + (size_t)b*L_*C2_ + h*HD_;
    const float* kb = g_kv + (size_t)b*L_*C_  + h*HD_;
    const float* vb = kb + C2_;

    // ---- Q staging (tf32) into sh_ps[row][d], stride 52 ----
    {
        int row = tid >> 1, dh = (tid & 1)*24;
        int gl = qt*128 + row;
        if (gl < L_) {
            #pragma unroll
            for (int t = 0; t < 6; t++) {
                float4 v = *(const float4*)(qb + (size_t)gl*C2_ + dh + t*4);
                sh_ps[row*52+dh+t*4+0]=f2tf(v.x); sh_ps[row*52+dh+t*4+1]=f2tf(v.y);
                sh_ps[row*52+dh+t*4+2]=f2tf(v.z); sh_ps[row*52+dh+t*4+3]=f2tf(v.w);
            }
        } else {
            #pragma unroll
            for (int t = 0; t < 24; t++) sh_ps[row*52+dh+t] = 0u;
        }
    }
    __syncthreads();
    // ---- Q A-fragments resident in registers ----
    unsigned qfr[6][4];
    {
        int r0 = qw + gid, r1 = r0 + 8;
        #pragma unroll
        for (int k8i = 0; k8i < 6; k8i++) {
            int d = k8i*8;
            qfr[k8i][0] = sh_ps[r0*52 + d + tig];
            qfr[k8i][1] = sh_ps[r1*52 + d + tig];
            qfr[k8i][2] = sh_ps[r0*52 + d + tig + 4];
            qfr[k8i][3] = sh_ps[r1*52 + d + tig + 4];
        }
    }

    float m[2]    = {-1e30f, -1e30f};
    float lsum[2] = {0.f, 0.f};
    float o[6][4];
    #pragma unroll
    for (int nt = 0; nt < 6; nt++)
        #pragma unroll
        for (int t = 0; t < 4; t++) o[nt][t] = 0.f;

    for (int kt = 0; kt < 16; kt++) {
        __syncthreads();   // prev stage2 (ps/vs reads) and Q-frag reads done
        {   // cooperative K,V tile load (tf32): ks = sh_ps[key][d] stride 52; vs stride 56
            int key = tid >> 2, dp = (tid & 3)*12;
            int gl = kt*64 + key;
            if (gl < L_) {
                #pragma unroll
                for (int t = 0; t < 3; t++) {
                    float4 kv = *(const float4*)(kb + (size_t)gl*C_ + dp + t*4);
                    sh_ps[key*52+dp+t*4+0]=f2tf(kv.x); sh_ps[key*52+dp+t*4+1]=f2tf(kv.y);
                    sh_ps[key*52+dp+t*4+2]=f2tf(kv.z); sh_ps[key*52+dp+t*4+3]=f2tf(kv.w);
                    float4 vv = *(const float4*)(vb + (size_t)gl*C_ + dp + t*4);
                    sh_vs[key*56+dp+t*4+0]=f2tf(vv.x); sh_vs[key*56+dp+t*4+1]=f2tf(vv.y);
                    sh_vs[key*56+dp+t*4+2]=f2tf(vv.z); sh_vs[key*56+dp+t*4+3]=f2tf(vv.w);
                }
            } else {
                #pragma unroll
                for (int t = 0; t < 12; t++) { sh_ps[key*52+dp+t]=0u; sh_vs[key*56+dp+t]=0u; }
            }
        }
        __syncthreads();

        // ---- stage 1: S = Q K^T over 8 n-tiles (64 keys) ----
        float s[8][4];
        #pragma unroll
        for (int nt = 0; nt < 8; nt++)
            #pragma unroll
            for (int t = 0; t < 4; t++) s[nt][t] = 0.f;
        #pragma unroll
        for (int k8i = 0; k8i < 6; k8i++) {
            #pragma unroll
            for (int nt = 0; nt < 8; nt++) {
                unsigned bfr[2];
                int nb = (nt*8 + gid)*52 + k8i*8;
                bfr[0] = sh_ps[nb + tig];
                bfr[1] = sh_ps[nb + tig + 4];
                mma_tf32(s[nt], qfr[k8i], bfr);
            }
        }

        // ---- warp-local running softmax (rows gid / gid+8 of this warp's 16) ----
        float corr[2];
        int kbase = kt*64 + 2*tig;
        #pragma unroll
        for (int r = 0; r < 2; r++) {
            int i0 = 2*r;
            float mx = -1e30f;
            #pragma unroll
            for (int nt = 0; nt < 8; nt++) {
                int c0 = kbase + nt*8;
                float v0 = (c0   < L_) ? s[nt][i0  ]*SCALE_ : -1e30f;
                float v1 = (c0+1 < L_) ? s[nt][i0+1]*SCALE_ : -1e30f;
                s[nt][i0] = v0; s[nt][i0+1] = v1;
                mx = fmaxf(mx, fmaxf(v0, v1));
            }
            mx = fmaxf(mx, __shfl_xor_sync(0xffffffffu, mx, 1));
            mx = fmaxf(mx, __shfl_xor_sync(0xffffffffu, mx, 2));
            float mnew = fmaxf(m[r], mx);
            corr[r] = __expf(m[r] - mnew);
            m[r] = mnew;
            float lp = 0.f;
            #pragma unroll
            for (int nt = 0; nt < 8; nt++) {
                float p0 = __expf(s[nt][i0  ] - mnew);
                float p1 = __expf(s[nt][i0+1] - mnew);
                s[nt][i0] = p0; s[nt][i0+1] = p1;
                lp += p0 + p1;
            }
            lp += __shfl_xor_sync(0xffffffffu, lp, 1);
            lp += __shfl_xor_sync(0xffffffffu, lp, 2);
            lsum[r] = lsum[r]*corr[r] + lp;
        }

        __syncthreads();   // ALL warps done reading K tile; safe to overwrite with P

        // ---- store P (tf32) to warp-private rows of sh_ps[q][key], stride 68 ----
        {
            int r0 = qw + gid, r1 = r0 + 8;
            #pragma unroll
            for (int nt = 0; nt < 8; nt++) {
                int col = nt*8 + 2*tig;
                *(uint2*)&sh_ps[r0*68 + col] = make_uint2(f2tf(s[nt][0]), f2tf(s[nt][1]));
                *(uint2*)&sh_ps[r1*68 + col] = make_uint2(f2tf(s[nt][2]), f2tf(s[nt][3]));
            }
        }
        __syncwarp();

        // ---- rescale O frags, then stage 2: O += P V ----
        #pragma unroll
        for (int nt = 0; nt < 6; nt++) {
            o[nt][0] *= corr[0]; o[nt][1] *= corr[0];
            o[nt][2] *= corr[1]; o[nt][3] *= corr[1];
        }
        {
            int r0 = qw + gid, r1 = r0 + 8;
            #pragma unroll
            for (int k8i = 0; k8i < 8; k8i++) {
                int kk = k8i*8;
                unsigned afr[4];
                afr[0] = sh_ps[r0*68 + kk + tig];
                afr[1] = sh_ps[r1*68 + kk + tig];
                afr[2] = sh_ps[r0*68 + kk + tig + 4];
                afr[3] = sh_ps[r1*68 + kk + tig + 4];
                #pragma unroll
                for (int nt = 0; nt < 6; nt++) {
                    unsigned bfr[2];
                    bfr[0] = sh_vs[(kk + tig    )*56 + nt*8 + gid];
                    bfr[1] = sh_vs[(kk + tig + 4)*56 + nt*8 + gid];
                    mma_tf32(o[nt], afr, bfr);
                }
            }
        }
    }

    // ---- epilogue: normalize and scatter via the flat-reshape mapping ----
    {
        float inv0 = 1.f/lsum[0], inv1 = 1.f/lsum[1];
        int q0 = qt*128 + qw + gid, q1 = q0 + 8;
        float* xcb = g_xc + (size_t)b*L_*C_;
        #pragma unroll
        for (int nt = 0; nt < 6; nt++) {
            #pragma unroll
            for (int j = 0; j < 2; j++) {
                int d = nt*8 + 2*tig + j;
                int c = h*HD_ + d;
                if (q0 < L_) {
                    int flat = c*L_ + q0;
                    int lp2 = flat / C2_;
                    int cp  = flat - lp2*C2_;
                    xcb[(size_t)lp2*C_ + C2_ + cp] = o[nt][j]*inv0;
                }
                if (q1 < L_) {
                    int flat = c*L_ + q1;
                    int lp2 = flat / C2_;
                    int cp  = flat - lp2*C2_;
                    xcb[(size_t)lp2*C_ + C2_ + cp] = o[nt][j+2]*inv1;
                }
            }
        }
    }
}

// ---------------- stage 8a: t1 = gelu(dw3(xc)) ----------------
__global__ void pjdw_kernel(const float* __restrict__ dww, const float* __restrict__ dwb) {
    int b  = blockIdx.y;
    int tid = threadIdx.x;                 // 768: li 0..3, c4 0..191
    int l  = blockIdx.x*4 + (tid/192);
    int c  = (tid%192)*4;
    if (l >= L_) return;
    const float* wp = dww + (size_t)c*3;
    float4 wA = *(const float4*)(wp);
    float4 wB = *(const float4*)(wp+4);
    float4 wC = *(const float4*)(wp+8);
    float4 bv = *(const float4*)(dwb + c);
    const float* xb = g_xc + ((size_t)b*L_ + l)*C_ + c;
    float4 zero = make_float4(0.f,0.f,0.f,0.f);
    float4 xm = (l > 0)    ? *(const float4*)(xb - C_) : zero;
    float4 x0 = *(const float4*)(xb);
    float4 xp = (l+1 < L_) ? *(const float4*)(xb + C_) : zero;
    float4 r;
    r.x = gelu_f(xm.x*wA.x + x0.x*wA.y + xp.x*wA.z + bv.x);
    r.y = gelu_f(xm.y*wA.w + x0.y*wB.x + xp.y*wB.y + bv.y);
    r.z = gelu_f(xm.z*wB.z + x0.z*wB.w + xp.z*wC.x + bv.z);
    r.w = gelu_f(xm.w*wC.y + x0.w*wC.z + xp.w*wC.w + bv.w);
    *(float4*)(g_t1 + ((size_t)b*L_ + l)*C_ + c) = r;
}

// ---------------- deterministic BN stats: partials + finalize -> affine (a,b) ----------
__global__ void stats_partial_kernel(const float* __restrict__ X, int Cch) {
    int blk = blockIdx.x;                  // 127 chunks of 63 rows
    int c   = threadIdx.x;
    int r0 = blk*63, r1 = min(r0+63, M_);
    float s = 0.f, s2 = 0.f;
    for (int r = r0; r < r1; r++) {
        float v = X[(size_t)r*Cch + c];
        s += v; s2 += v*v;
    }
    g_ps [(size_t)blk*Cch + c] = s;
    g_ps2[(size_t)blk*Cch + c] = s2;
}

__global__ void stats_finalize_kernel(int nblk, int Cch,
                                      const float* __restrict__ gam,
                                      const float* __restrict__ bet) {
    int c = blockIdx.x*blockDim.x + threadIdx.x;
    if (c >= Cch) return;
    double s = 0.0, s2 = 0.0;
    for (int i = 0; i < nblk; i++) { s += (double)g_ps[(size_t)i*Cch+c]; s2 += (double)g_ps2[(size_t)i*Cch+c]; }
    double mean = s / (double)M_;
    double var  = s2 / (double)M_ - mean*mean;
    if (var < 0.0) var = 0.0;
    float rs = (float)(1.0 / sqrt(var + (double)EPS_));
    float a  = gam[c]*rs;
    g_an[c] = a;
    g_bn[c] = bet[c] - (float)mean*a;
}

// ---------------- final: out = bn3(t3) + xc ----------------
__global__ void final_add_kernel(float* __restrict__ out) {
    int idx4 = blockIdx.x*blockDim.x + threadIdx.x;
    if (idx4 >= M_*C_/4) return;
    int idx = idx4*4;
    int c = idx % C_;
    float4 t = *(const float4*)(g_t3 + idx);
    float4 xv= *(const float4*)(g_xc + idx);
    float4 a = *(const float4*)(g_an + c);
    float4 bb= *(const float4*)(g_bn + c);
    float4 r;
    r.x = t.x*a.x + bb.x + xv.x;
    r.y = t.y*a.y + bb.y + xv.y;
    r.z = t.z*a.z + bb.z + xv.z;
    r.w = t.w*a.w + bb.w + xv.w;
    *(float4*)(out + idx) = r;
}

// =======================================================================================
extern "C" void kernel_launch(void* const* d_in, const int* in_sizes, int n_in,
                              void* d_out, int out_size) {
    const float* x        = (const float*)d_in[0];
    const float* dc_weight= (const float*)d_in[1];
    const float* dc_bias  = (const float*)d_in[2];
    const float* dc_p1w   = (const float*)d_in[3];
    const float* dc_p1b   = (const float*)d_in[4];
    const float* dc_p2w   = (const float*)d_in[5];
    const float* dc_p2b   = (const float*)d_in[6];
    const float* at_qw    = (const float*)d_in[7];
    const float* at_qb    = (const float*)d_in[8];
    const float* at_kvw   = (const float*)d_in[9];
    const float* at_kvb   = (const float*)d_in[10];
    const float* at_lcw   = (const float*)d_in[11];
    const float* at_lcb   = (const float*)d_in[12];
    const float* pj_dww   = (const float*)d_in[13];
    const float* pj_dwb   = (const float*)d_in[14];
    const float* pj_bn1g  = (const float*)d_in[15];
    const float* pj_bn1b  = (const float*)d_in[16];
    const float* pj_c1w   = (const float*)d_in[17];
    const float* pj_c1b   = (const float*)d_in[18];
    const float* pj_bn2g  = (const float*)d_in[19];
    const float* pj_bn2b  = (const float*)d_in[20];
    const float* pj_c2w   = (const float*)d_in[21];
    const float* pj_c2b   = (const float*)d_in[22];
    const float* pj_bn3g  = (const float*)d_in[23];
    const float* pj_bn3b  = (const float*)d_in[24];
    float* out = (float*)d_out;

    float *pq, *pkvin, *pkv, *pt1, *pt2, *pt3, *pan, *pbn;
    cudaGetSymbolAddress((void**)&pq,    g_q);
    cudaGetSymbolAddress((void**)&pkvin, g_kvin);
    cudaGetSymbolAddress((void**)&pkv,   g_kv);
    cudaGetSymbolAddress((void**)&pt1,   g_t1);
    cudaGetSymbolAddress((void**)&pt2,   g_t2);
    cudaGetSymbolAddress((void**)&pt3,   g_t3);
    cudaGetSymbolAddress((void**)&pan,   g_an);
    cudaGetSymbolAddress((void**)&pbn,   g_bn);

    // ---- branch 1: dynamic conv ----
    pooled_kernel<<<96, C2_>>>(x);
    dcmlp_kernel<<<B_, C2_>>>(dc_p1w, dc_p1b, dc_p2w, dc_p2b, dc_weight, dc_bias);
    dconv_kernel<<<dim3(125, B_), 768>>>(x);

    // ---- branch 2: attention ----
    kvin_kernel<<<dim3(125, B_), 768>>>(x, at_lcw, at_lcb);
    gemm_kernel<<<dim3(63, 6), 256>>>(x + C2_, C_, at_qw, at_qb,
                                      pq, C2_, M_, C2_, C2_, nullptr, nullptr, 0);
    gemm_kernel<<<dim3(63, 12), 256>>>(pkvin, C2_, at_kvw, at_kvb,
                                       pkv, C_, M_, C_, C2_, nullptr, nullptr, 0);
    attn_kernel<<<dim3(8, H_, B_), 256>>>();

    // ---- projection: dw3 + gelu, then BN1 stats ----
    pjdw_kernel<<<dim3(250, B_), 768>>>(pj_dww, pj_dwb);
    stats_partial_kernel<<<127, C_>>>(pt1, C_);
    stats_finalize_kernel<<<3, 256>>>(127, C_, pj_bn1g, pj_bn1b);

    // ---- c1 (bn1 folded into A) + gelu ----
    gemm_kernel<<<dim3(63, 2), 256>>>(pt1, C_, pj_c1w, pj_c1b,
                                      pt2, PJIN_, M_, PJIN_, C_, pan, pbn, 1);
    stats_partial_kernel<<<127, PJIN_>>>(pt2, PJIN_);
    stats_finalize_kernel<<<1, 256>>>(127, PJIN_, pj_bn2g, pj_bn2b);

    // ---- c2 (bn2 folded into A) ----
    gemm_kernel<<<dim3(63, 12), 256>>>(pt2, PJIN_, pj_c2w, pj_c2b,
                                       pt3, C_, M_, C_, PJIN_, pan, pbn, 0);
    stats_partial_kernel<<<127, C_>>>(pt3, C_);
    stats_finalize_kernel<<<3, 256>>>(127, C_, pj_bn3g, pj_bn3b);

    // ---- bn3 + residual ----
    final_add_kernel<<<(M_*C_/4 + 255)/256, 256>>>(out);
}

// round 10
// speedup vs baseline: 2.5242x; 1.0238x over previous
#include <cuda_runtime.h>
#include <math.h>

#define B_    8
#define L_    999
#define C_    768
#define C2_   384
#define H_    8
#define HD_   48
#define K_    3
#define DCIN_ 96
#define PJIN_ 96
#define M_    (B_*L_)          /* 7992 tokens */
#define SCALE_ 0.14433756729740643f
#define EPS_   1e-5f

__device__ __forceinline__ float gelu_f(float v) {
    return 0.5f * v * (1.0f + erff(v * 0.7071067811865475f));
}

// ---- tf32 mma helpers (validated R7/R8) ----
__device__ __forceinline__ unsigned f2tf(float f) {
    unsigned r; asm("cvt.rna.tf32.f32 %0, %1;" : "=r"(r) : "f"(f)); return r;
}
__device__ __forceinline__ void mma_tf32(float* c, const unsigned* a, const unsigned* b) {
    asm volatile("mma.sync.aligned.m16n8k8.row.col.f32.tf32.tf32.f32 "
                 "{%0,%1,%2,%3}, {%4,%5,%6,%7}, {%8,%9}, {%0,%1,%2,%3};"
                 : "+f"(c[0]), "+f"(c[1]), "+f"(c[2]), "+f"(c[3])
                 : "r"(a[0]), "r"(a[1]), "r"(a[2]), "r"(a[3]),
                   "r"(b[0]), "r"(b[1]));
}

// ---------------- scratch (device globals; no allocation allowed) ----------------
__device__ float g_q    [(size_t)M_*C2_];
__device__ float g_kvin [(size_t)M_*C2_];
__device__ float g_kv   [(size_t)M_*C_];
__device__ float g_xc   [(size_t)M_*C_];
__device__ float g_t1   [(size_t)M_*C_];
__device__ float g_t2   [(size_t)M_*PJIN_];
__device__ float g_t3   [(size_t)M_*C_];
__device__ float g_wdyn [B_*C2_*K_];
__device__ float g_bdyn [B_*C2_];
__device__ float g_ps   [128*C_];
__device__ float g_ps2  [128*C_];
__device__ float g_an   [C_];
__device__ float g_bn   [C_];

// ---------------- stage 1: pooled partial sums (4-way split over rows) ----------------
__global__ void pooled_kernel(const float* __restrict__ x) {
    int blk = blockIdx.x;            // (b*3+kk)*4+sub
    int sub = blk & 3;
    int bk  = blk >> 2;
    int b   = bk / K_;
    int kk  = bk % K_;
    int c   = threadIdx.x;           // 384
    int r0 = kk*333 + sub*84;
    int r1 = kk*333 + min(sub*84 + 84, 333);
    const float* xb = x + (size_t)b*L_*C_ + c;
    float s = 0.f;
    for (int l = r0; l < r1; l++) s += xb[(size_t)l*C_];
    g_ps[(size_t)blk*C2_ + c] = s;
}

// ---------------- stage 2: dynamic-conv score MLP + softmax over G ----------------
__global__ void dcmlp_kernel(const float* __restrict__ p1w, const float* __restrict__ p1b,
                             const float* __restrict__ p2w, const float* __restrict__ p2b,
                             const float* __restrict__ dcw, const float* __restrict__ dcb) {
    int b   = blockIdx.x;
    int tid = threadIdx.x;                 // 384
    __shared__ float col[4][C2_];
    __shared__ float hid[4][DCIN_];
    __shared__ float sc [4][2*C2_];
    {
        float cc[3];
        #pragma unroll
        for (int kk = 0; kk < 3; kk++) {
            int base = (b*3+kk)*4;
            cc[kk] = (g_ps[(size_t)(base+0)*C2_+tid] + g_ps[(size_t)(base+1)*C2_+tid]
                    + g_ps[(size_t)(base+2)*C2_+tid] + g_ps[(size_t)(base+3)*C2_+tid]) * (1.0f/333.0f);
            col[kk][tid] = cc[kk];
        }
        col[3][tid] = (cc[0]+cc[1]+cc[2]) * (1.0f/3.0f);
    }
    __syncthreads();
    {
        int kk = tid / DCIN_;
        int i  = tid % DCIN_;
        float s = p1b[i];
        const float* wr = p1w + (size_t)i*C2_;
        #pragma unroll 8
        for (int c = 0; c < C2_; c++) s += wr[c]*col[kk][c];
        hid[kk][i] = gelu_f(s);
    }
    __syncthreads();
    for (int t = tid; t < 4*768; t += 384) {
        int kk = t / 768, o = t % 768;
        float s = p2b[o];
        const float* wr = p2w + (size_t)o*DCIN_;
        #pragma unroll 8
        for (int i = 0; i < DCIN_; i++) s += wr[i]*hid[kk][i];
        sc[kk][o] = s;
    }
    __syncthreads();
    {
        int c = tid;
        #pragma unroll
        for (int kk = 0; kk < 3; kk++) {
            float e0 = sc[kk][c], e1 = sc[kk][C2_+c];
            float mx = fmaxf(e0,e1);
            float a0 = expf(e0-mx), a1 = expf(e1-mx);
            float inv = 1.f/(a0+a1);
            g_wdyn[(b*C2_+c)*3+kk] = (a0*dcw[c*3+kk] + a1*dcw[(C2_+c)*3+kk])*inv;
        }
        float e0 = sc[3][c], e1 = sc[3][C2_+c];
        float mx = fmaxf(e0,e1);
        float a0 = expf(e0-mx), a1 = expf(e1-mx);
        g_bdyn[b*C2_+c] = (a0*dcb[c] + a1*dcb[C2_+c])/(a0+a1);
    }
}

// ---------------- stage 3: dynamic depthwise conv -> xc[:, :, 0:384] ----------------
__global__ void dconv_kernel(const float* __restrict__ x) {
    int b  = blockIdx.y;
    int tid = threadIdx.x;                 // 768: li 0..7, c4 0..95
    int l  = blockIdx.x*8 + (tid/96);
    int c  = (tid%96)*4;
    if (l >= L_) return;
    const float* wp = g_wdyn + ((size_t)b*C2_ + c)*3;
    float4 wA = *(const float4*)(wp);
    float4 wB = *(const float4*)(wp+4);
    float4 wC = *(const float4*)(wp+8);
    float4 bv = *(const float4*)(g_bdyn + (size_t)b*C2_ + c);
    const float* xb = x + ((size_t)b*L_ + l)*C_ + c;
    float4 zero = make_float4(0.f,0.f,0.f,0.f);
    float4 xm = (l > 0)      ? *(const float4*)(xb - C_) : zero;
    float4 x0 = *(const float4*)(xb);
    float4 xp = (l+1 < L_)   ? *(const float4*)(xb + C_) : zero;
    float4 r;
    r.x = xm.x*wA.x + x0.x*wA.y + xp.x*wA.z + bv.x;
    r.y = xm.y*wA.w + x0.y*wB.x + xp.y*wB.y + bv.y;
    r.z = xm.z*wB.z + x0.z*wB.w + xp.z*wC.x + bv.z;
    r.w = xm.w*wC.y + x0.w*wC.z + xp.w*wC.w + bv.w;
    *(float4*)(g_xc + ((size_t)b*L_ + l)*C_ + c) = r;
}

// ---------------- stage 4: kv_in = dw3(x2, lcw, lcb) + x2 ----------------
__global__ void kvin_kernel(const float* __restrict__ x,
                            const float* __restrict__ lcw, const float* __restrict__ lcb) {
    int b  = blockIdx.y;
    int tid = threadIdx.x;                 // 768
    int l  = blockIdx.x*8 + (tid/96);
    int c  = (tid%96)*4;
    if (l >= L_) return;
    const float* wp = lcw + (size_t)c*3;
    float4 wA = *(const float4*)(wp);
    float4 wB = *(const float4*)(wp+4);
    float4 wC = *(const float4*)(wp+8);
    float4 bv = *(const float4*)(lcb + c);
    const float* xb = x + ((size_t)b*L_ + l)*C_ + C2_ + c;
    float4 zero = make_float4(0.f,0.f,0.f,0.f);
    float4 xm = (l > 0)      ? *(const float4*)(xb - C_) : zero;
    float4 x0 = *(const float4*)(xb);
    float4 xp = (l+1 < L_)   ? *(const float4*)(xb + C_) : zero;
    float4 r;
    r.x = xm.x*wA.x + x0.x*wA.y + xp.x*wA.z + bv.x + x0.x;
    r.y = xm.y*wA.w + x0.y*wB.x + xp.y*wB.y + bv.y + x0.y;
    r.z = xm.z*wB.z + x0.z*wB.w + xp.z*wC.x + bv.z + x0.z;
    r.w = xm.w*wC.y + x0.w*wC.z + xp.w*wC.w + bv.w + x0.w;
    *(float4*)(g_kvin + ((size_t)b*L_ + l)*C2_ + c) = r;
}

// ---------------- GEMM v6: tf32 tensor cores, double-buffered smem pipeline ------------
// C[m,n] = sum_k a(A[m,k]) * W[n,k] + bias[n] ; optional per-k affine on A, gelu epilogue
__global__ void __launch_bounds__(256, 2)
gemm_kernel(const float* __restrict__ A, int lda,
            const float* __restrict__ W,
            const float* __restrict__ bias,
            float* __restrict__ Cmat, int ldc,
            int M, int N, int Kd,
            const float* __restrict__ ascale,
            const float* __restrict__ ashift,
            int dogelu)
{
    __shared__ unsigned As[2][128][20];
    __shared__ unsigned Ws[2][64][20];
    int tid  = threadIdx.x;                // 256 = 8 warps
    int wid  = tid >> 5, lane = tid & 31;
    int gid  = lane >> 2, tig = lane & 3;
    int m0 = blockIdx.x*128, n0 = blockIdx.y*64;
    int mw = (wid >> 1) * 32;
    int nw = (wid & 1) * 32;

    float acc[2][4][4];
    #pragma unroll
    for (int i = 0; i < 2; i++)
        #pragma unroll
        for (int j = 0; j < 4; j++)
            #pragma unroll
            for (int t = 0; t < 4; t++) acc[i][j][t] = 0.f;

    int alr = tid >> 1, alk = (tid & 1) << 3;   // A stage: row 0..127, k 0/8
    int wlr = tid >> 2, wlk = (tid & 3) << 2;   // W stage: row 0..63,  k 0/4/8/12
    float4 zero = make_float4(0.f,0.f,0.f,0.f);
    float4 a0, a1, w0;

    auto loadc = [&](int k0) {
        a0 = zero; a1 = zero; w0 = zero;
        int gm = m0 + alr;
        if (gm < M) {
            const float* ap = A + (size_t)gm*lda + k0 + alk;
            a0 = *(const float4*)(ap);
            a1 = *(const float4*)(ap+4);
        }
        if (ascale) {
            int kb = k0 + alk;
            a0.x = a0.x*ascale[kb+0] + ashift[kb+0];
            a0.y = a0.y*ascale[kb+1] + ashift[kb+1];
            a0.z = a0.z*ascale[kb+2] + ashift[kb+2];
            a0.w = a0.w*ascale[kb+3] + ashift[kb+3];
            a1.x = a1.x*ascale[kb+4] + ashift[kb+4];
            a1.y = a1.y*ascale[kb+5] + ashift[kb+5];
            a1.z = a1.z*ascale[kb+6] + ashift[kb+6];
            a1.w = a1.w*ascale[kb+7] + ashift[kb+7];
        }
        int gn = n0 + wlr;
        if (gn < N) w0 = *(const float4*)(W + (size_t)gn*Kd + k0 + wlk);
    };
    auto storec = [&](int st) {
        As[st][alr][alk+0]=f2tf(a0.x); As[st][alr][alk+1]=f2tf(a0.y);
        As[st][alr][alk+2]=f2tf(a0.z); As[st][alr][alk+3]=f2tf(a0.w);
        As[st][alr][alk+4]=f2tf(a1.x); As[st][alr][alk+5]=f2tf(a1.y);
        As[st][alr][alk+6]=f2tf(a1.z); As[st][alr][alk+7]=f2tf(a1.w);
        Ws[st][wlr][wlk+0]=f2tf(w0.x); Ws[st][wlr][wlk+1]=f2tf(w0.y);
        Ws[st][wlr][wlk+2]=f2tf(w0.z); Ws[st][wlr][wlk+3]=f2tf(w0.w);
    };

    int nk = Kd >> 4;
    loadc(0);
    storec(0);
    __syncthreads();

    for (int i = 0; i < nk; i++) {
        int buf = i & 1;
        if (i+1 < nk) loadc((i+1) << 4);     // prefetch next chunk (hidden behind mma)
        #pragma unroll
        for (int k8 = 0; k8 < 16; k8 += 8) {
            unsigned bfr[4][2];
            #pragma unroll
            for (int nt = 0; nt < 4; nt++) {
                int nb = nw + nt*8 + gid;
                bfr[nt][0] = Ws[buf][nb][k8 + tig];
                bfr[nt][1] = Ws[buf][nb][k8 + 4 + tig];
            }
            #pragma unroll
            for (int mt = 0; mt < 2; mt++) {
                int mb = mw + mt*16 + gid;
                unsigned afr[4];
                afr[0] = As[buf][mb    ][k8 + tig];
                afr[1] = As[buf][mb + 8][k8 + tig];
                afr[2] = As[buf][mb    ][k8 + 4 + tig];
                afr[3] = As[buf][mb + 8][k8 + 4 + tig];
                #pragma unroll
                for (int nt = 0; nt < 4; nt++)
                    mma_tf32(acc[mt][nt], afr, bfr[nt]);
            }
        }
        if (i+1 < nk) {
            storec(buf ^ 1);                 // stage last read in iter i-1 (sync-separated)
            __syncthreads();
        }
    }

    #pragma unroll
    for (int mt = 0; mt < 2; mt++) {
        #pragma unroll
        for (int nt = 0; nt < 4; nt++) {
            int gn = n0 + nw + nt*8 + 2*tig;
            if (gn >= N) continue;
            float b0v = bias[gn], b1v = bias[gn+1];
            int gm0 = m0 + mw + mt*16 + gid;
            if (gm0 < M) {
                float v0 = acc[mt][nt][0] + b0v;
                float v1 = acc[mt][nt][1] + b1v;
                if (dogelu) { v0 = gelu_f(v0); v1 = gelu_f(v1); }
                *(float2*)(Cmat + (size_t)gm0*ldc + gn) = make_float2(v0, v1);
            }
            int gm1 = gm0 + 8;
            if (gm1 < M) {
                float v2 = acc[mt][nt][2] + b0v;
                float v3 = acc[mt][nt][3] + b1v;
                if (dogelu) { v2 = gelu_f(v2); v3 = gelu_f(v3); }
                *(float2*)(Cmat + (size_t)gm1*ldc + gn) = make_float2(v2, v3);
            }
        }
    }
}

// ---------------- stage 7: flash attention v4 (tf32 mma) -> xc[:, :, 384:768] ----------
// Block: 128 q-rows, 8 warps; warp = private 16-row q-group over full 64-key tiles.
// Output reproduces the reference transpose+flat-reshape reinterpretation:
// (c = h*HD+d, l) -> flat = c*L + l -> xc[b, flat/C2, C2 + flat%C2].
__global__ void __launch_bounds__(256, 2) attn_kernel() {
    // smem: sh_ps (union: Q staging [128][52] / K tile [64][52] / P [128][68]) + V [64][56]
    __shared__ unsigned sh_ps[128*68];     // 34816 B
    __shared__ unsigned sh_vs[64*56];      // 14336 B  (total 49152 = 48KB)
    int qt = blockIdx.x;                   // 8 q tiles of 128
    int h  = blockIdx.y;
    int b  = blockIdx.z;
    int tid = threadIdx.x;                 // 256
    int wid = tid >> 5, lane = tid & 31;
    int gid = lane >> 2, tig = lane & 3;
    int qw  = wid*16;

    const float* qb = g_q  + (size_t)b*L_*C2_ + h*HD_;
    const float* kb = g_kv + (size_t)b*L_*C_  + h*HD_;
    const float* vb = kb + C2_;

    // ---- Q staging (tf32) into sh_ps[row][d], stride 52 ----
    {
        int row = tid >> 1, dh = (tid & 1)*24;
        int gl = qt*128 + row;
        if (gl < L_) {
            #pragma unroll
            for (int t = 0; t < 6; t++) {
                float4 v = *(const float4*)(qb + (size_t)gl*C2_ + dh + t*4);
                sh_ps[row*52+dh+t*4+0]=f2tf(v.x); sh_ps[row*52+dh+t*4+1]=f2tf(v.y);
                sh_ps[row*52+dh+t*4+2]=f2tf(v.z); sh_ps[row*52+dh+t*4+3]=f2tf(v.w);
            }
        } else {
            #pragma unroll
            for (int t = 0; t < 24; t++) sh_ps[row*52+dh+t] = 0u;
        }
    }
    __syncthreads();
    // ---- Q A-fragments resident in registers ----
    unsigned qfr[6][4];
    {
        int r0 = qw + gid, r1 = r0 + 8;
        #pragma unroll
        for (int k8i = 0; k8i < 6; k8i++) {
            int d = k8i*8;
            qfr[k8i][0] = sh_ps[r0*52 + d + tig];
            qfr[k8i][1] = sh_ps[r1*52 + d + tig];
            qfr[k8i][2] = sh_ps[r0*52 + d + tig + 4];
            qfr[k8i][3] = sh_ps[r1*52 + d + tig + 4];
        }
    }

    float m[2]    = {-1e30f, -1e30f};
    float lsum[2] = {0.f, 0.f};
    float o[6][4];
    #pragma unroll
    for (int nt = 0; nt < 6; nt++)
        #pragma unroll
        for (int t = 0; t < 4; t++) o[nt][t] = 0.f;

    for (int kt = 0; kt < 16; kt++) {
        __syncthreads();   // prev stage2 (ps/vs reads) and Q-frag reads done
        {   // cooperative K,V tile load (tf32): ks = sh_ps[key][d] stride 52; vs stride 56
            int key = tid >> 2, dp = (tid & 3)*12;
            int gl = kt*64 + key;
            if (gl < L_) {
                #pragma unroll
                for (int t = 0; t < 3; t++) {
                    float4 kv = *(const float4*)(kb + (size_t)gl*C_ + dp + t*4);
                    sh_ps[key*52+dp+t*4+0]=f2tf(kv.x); sh_ps[key*52+dp+t*4+1]=f2tf(kv.y);
                    sh_ps[key*52+dp+t*4+2]=f2tf(kv.z); sh_ps[key*52+dp+t*4+3]=f2tf(kv.w);
                    float4 vv = *(const float4*)(vb + (size_t)gl*C_ + dp + t*4);
                    sh_vs[key*56+dp+t*4+0]=f2tf(vv.x); sh_vs[key*56+dp+t*4+1]=f2tf(vv.y);
                    sh_vs[key*56+dp+t*4+2]=f2tf(vv.z); sh_vs[key*56+dp+t*4+3]=f2tf(vv.w);
                }
            } else {
                #pragma unroll
                for (int t = 0; t < 12; t++) { sh_ps[key*52+dp+t]=0u; sh_vs[key*56+dp+t]=0u; }
            }
        }
        __syncthreads();

        // ---- stage 1: S = Q K^T over 8 n-tiles (64 keys) ----
        float s[8][4];
        #pragma unroll
        for (int nt = 0; nt < 8; nt++)
            #pragma unroll
            for (int t = 0; t < 4; t++) s[nt][t] = 0.f;
        #pragma unroll
        for (int k8i = 0; k8i < 6; k8i++) {
            #pragma unroll
            for (int nt = 0; nt < 8; nt++) {
                unsigned bfr[2];
                int nb = (nt*8 + gid)*52 + k8i*8;
                bfr[0] = sh_ps[nb + tig];
                bfr[1] = sh_ps[nb + tig + 4];
                mma_tf32(s[nt], qfr[k8i], bfr);
            }
        }

        // ---- warp-local running softmax (rows gid / gid+8 of this warp's 16) ----
        float corr[2];
        int kbase = kt*64 + 2*tig;
        #pragma unroll
        for (int r = 0; r < 2; r++) {
            int i0 = 2*r;
            float mx = -1e30f;
            #pragma unroll
            for (int nt = 0; nt < 8; nt++) {
                int c0 = kbase + nt*8;
                float v0 = (c0   < L_) ? s[nt][i0  ]*SCALE_ : -1e30f;
                float v1 = (c0+1 < L_) ? s[nt][i0+1]*SCALE_ : -1e30f;
                s[nt][i0] = v0; s[nt][i0+1] = v1;
                mx = fmaxf(mx, fmaxf(v0, v1));
            }
            mx = fmaxf(mx, __shfl_xor_sync(0xffffffffu, mx, 1));
            mx = fmaxf(mx, __shfl_xor_sync(0xffffffffu, mx, 2));
            float mnew = fmaxf(m[r], mx);
            corr[r] = __expf(m[r] - mnew);
            m[r] = mnew;
            float lp = 0.f;
            #pragma unroll
            for (int nt = 0; nt < 8; nt++) {
                float p0 = __expf(s[nt][i0  ] - mnew);
                float p1 = __expf(s[nt][i0+1] - mnew);
                s[nt][i0] = p0; s[nt][i0+1] = p1;
                lp += p0 + p1;
            }
            lp += __shfl_xor_sync(0xffffffffu, lp, 1);
            lp += __shfl_xor_sync(0xffffffffu, lp, 2);
            lsum[r] = lsum[r]*corr[r] + lp;
        }

        __syncthreads();   // ALL warps done reading K tile; safe to overwrite with P

        // ---- store P (tf32) to warp-private rows of sh_ps[q][key], stride 68 ----
        {
            int r0 = qw + gid, r1 = r0 + 8;
            #pragma unroll
            for (int nt = 0; nt < 8; nt++) {
                int col = nt*8 + 2*tig;
                *(uint2*)&sh_ps[r0*68 + col] = make_uint2(f2tf(s[nt][0]), f2tf(s[nt][1]));
                *(uint2*)&sh_ps[r1*68 + col] = make_uint2(f2tf(s[nt][2]), f2tf(s[nt][3]));
            }
        }
        __syncwarp();

        // ---- rescale O frags, then stage 2: O += P V ----
        #pragma unroll
        for (int nt = 0; nt < 6; nt++) {
            o[nt][0] *= corr[0]; o[nt][1] *= corr[0];
            o[nt][2] *= corr[1]; o[nt][3] *= corr[1];
        }
        {
            int r0 = qw + gid, r1 = r0 + 8;
            #pragma unroll
            for (int k8i = 0; k8i < 8; k8i++) {
                int kk = k8i*8;
                unsigned afr[4];
                afr[0] = sh_ps[r0*68 + kk + tig];
                afr[1] = sh_ps[r1*68 + kk + tig];
                afr[2] = sh_ps[r0*68 + kk + tig + 4];
                afr[3] = sh_ps[r1*68 + kk + tig + 4];
                #pragma unroll
                for (int nt = 0; nt < 6; nt++) {
                    unsigned bfr[2];
                    bfr[0] = sh_vs[(kk + tig    )*56 + nt*8 + gid];
                    bfr[1] = sh_vs[(kk + tig + 4)*56 + nt*8 + gid];
                    mma_tf32(o[nt], afr, bfr);
                }
            }
        }
    }

    // ---- epilogue: normalize and scatter via the flat-reshape mapping ----
    {
        float inv0 = 1.f/lsum[0], inv1 = 1.f/lsum[1];
        int q0 = qt*128 + qw + gid, q1 = q0 + 8;
        float* xcb = g_xc + (size_t)b*L_*C_;
        #pragma unroll
        for (int nt = 0; nt < 6; nt++) {
            #pragma unroll
            for (int j = 0; j < 2; j++) {
                int d = nt*8 + 2*tig + j;
                int c = h*HD_ + d;
                if (q0 < L_) {
                    int flat = c*L_ + q0;
                    int lp2 = flat / C2_;
                    int cp  = flat - lp2*C2_;
                    xcb[(size_t)lp2*C_ + C2_ + cp] = o[nt][j]*inv0;
                }
                if (q1 < L_) {
                    int flat = c*L_ + q1;
                    int lp2 = flat / C2_;
                    int cp  = flat - lp2*C2_;
                    xcb[(size_t)lp2*C_ + C2_ + cp] = o[nt][j+2]*inv1;
                }
            }
        }
    }
}

// ---------------- stage 8a: t1 = gelu(dw3(xc)) ----------------
__global__ void pjdw_kernel(const float* __restrict__ dww, const float* __restrict__ dwb) {
    int b  = blockIdx.y;
    int tid = threadIdx.x;                 // 768: li 0..3, c4 0..191
    int l  = blockIdx.x*4 + (tid/192);
    int c  = (tid%192)*4;
    if (l >= L_) return;
    const float* wp = dww + (size_t)c*3;
    float4 wA = *(const float4*)(wp);
    float4 wB = *(const float4*)(wp+4);
    float4 wC = *(const float4*)(wp+8);
    float4 bv = *(const float4*)(dwb + c);
    const float* xb = g_xc + ((size_t)b*L_ + l)*C_ + c;
    float4 zero = make_float4(0.f,0.f,0.f,0.f);
    float4 xm = (l > 0)    ? *(const float4*)(xb - C_) : zero;
    float4 x0 = *(const float4*)(xb);
    float4 xp = (l+1 < L_) ? *(const float4*)(xb + C_) : zero;
    float4 r;
    r.x = gelu_f(xm.x*wA.x + x0.x*wA.y + xp.x*wA.z + bv.x);
    r.y = gelu_f(xm.y*wA.w + x0.y*wB.x + xp.y*wB.y + bv.y);
    r.z = gelu_f(xm.z*wB.z + x0.z*wB.w + xp.z*wC.x + bv.z);
    r.w = gelu_f(xm.w*wC.y + x0.w*wC.z + xp.w*wC.w + bv.w);
    *(float4*)(g_t1 + ((size_t)b*L_ + l)*C_ + c) = r;
}

// ---------------- deterministic BN stats: partials + finalize -> affine (a,b) ----------
__global__ void stats_partial_kernel(const float* __restrict__ X, int Cch) {
    int blk = blockIdx.x;                  // 127 chunks of 63 rows
    int c   = threadIdx.x;
    int r0 = blk*63, r1 = min(r0+63, M_);
    float s = 0.f, s2 = 0.f;
    for (int r = r0; r < r1; r++) {
        float v = X[(size_t)r*Cch + c];
        s += v; s2 += v*v;
    }
    g_ps [(size_t)blk*Cch + c] = s;
    g_ps2[(size_t)blk*Cch + c] = s2;
}

__global__ void stats_finalize_kernel(int nblk, int Cch,
                                      const float* __restrict__ gam,
                                      const float* __restrict__ bet) {
    int c = blockIdx.x*blockDim.x + threadIdx.x;
    if (c >= Cch) return;
    double s = 0.0, s2 = 0.0;
    for (int i = 0; i < nblk; i++) { s += (double)g_ps[(size_t)i*Cch+c]; s2 += (double)g_ps2[(size_t)i*Cch+c]; }
    double mean = s / (double)M_;
    double var  = s2 / (double)M_ - mean*mean;
    if (var < 0.0) var = 0.0;
    float rs = (float)(1.0 / sqrt(var + (double)EPS_));
    float a  = gam[c]*rs;
    g_an[c] = a;
    g_bn[c] = bet[c] - (float)mean*a;
}

// ---------------- final: out = bn3(t3) + xc ----------------
__global__ void final_add_kernel(float* __restrict__ out) {
    int idx4 = blockIdx.x*blockDim.x + threadIdx.x;
    if (idx4 >= M_*C_/4) return;
    int idx = idx4*4;
    int c = idx % C_;
    float4 t = *(const float4*)(g_t3 + idx);
    float4 xv= *(const float4*)(g_xc + idx);
    float4 a = *(const float4*)(g_an + c);
    float4 bb= *(const float4*)(g_bn + c);
    float4 r;
    r.x = t.x*a.x + bb.x + xv.x;
    r.y = t.y*a.y + bb.y + xv.y;
    r.z = t.z*a.z + bb.z + xv.z;
    r.w = t.w*a.w + bb.w + xv.w;
    *(float4*)(out + idx) = r;
}

// =======================================================================================
extern "C" void kernel_launch(void* const* d_in, const int* in_sizes, int n_in,
                              void* d_out, int out_size) {
    const float* x        = (const float*)d_in[0];
    const float* dc_weight= (const float*)d_in[1];
    const float* dc_bias  = (const float*)d_in[2];
    const float* dc_p1w   = (const float*)d_in[3];
    const float* dc_p1b   = (const float*)d_in[4];
    const float* dc_p2w   = (const float*)d_in[5];
    const float* dc_p2b   = (const float*)d_in[6];
    const float* at_qw    = (const float*)d_in[7];
    const float* at_qb    = (const float*)d_in[8];
    const float* at_kvw   = (const float*)d_in[9];
    const float* at_kvb   = (const float*)d_in[10];
    const float* at_lcw   = (const float*)d_in[11];
    const float* at_lcb   = (const float*)d_in[12];
    const float* pj_dww   = (const float*)d_in[13];
    const float* pj_dwb   = (const float*)d_in[14];
    const float* pj_bn1g  = (const float*)d_in[15];
    const float* pj_bn1b  = (const float*)d_in[16];
    const float* pj_c1w   = (const float*)d_in[17];
    const float* pj_c1b   = (const float*)d_in[18];
    const float* pj_bn2g  = (const float*)d_in[19];
    const float* pj_bn2b  = (const float*)d_in[20];
    const float* pj_c2w   = (const float*)d_in[21];
    const float* pj_c2b   = (const float*)d_in[22];
    const float* pj_bn3g  = (const float*)d_in[23];
    const float* pj_bn3b  = (const float*)d_in[24];
    float* out = (float*)d_out;

    float *pq, *pkvin, *pkv, *pt1, *pt2, *pt3, *pan, *pbn;
    cudaGetSymbolAddress((void**)&pq,    g_q);
    cudaGetSymbolAddress((void**)&pkvin, g_kvin);
    cudaGetSymbolAddress((void**)&pkv,   g_kv);
    cudaGetSymbolAddress((void**)&pt1,   g_t1);
    cudaGetSymbolAddress((void**)&pt2,   g_t2);
    cudaGetSymbolAddress((void**)&pt3,   g_t3);
    cudaGetSymbolAddress((void**)&pan,   g_an);
    cudaGetSymbolAddress((void**)&pbn,   g_bn);

    // ---- branch 1: dynamic conv ----
    pooled_kernel<<<96, C2_>>>(x);
    dcmlp_kernel<<<B_, C2_>>>(dc_p1w, dc_p1b, dc_p2w, dc_p2b, dc_weight, dc_bias);
    dconv_kernel<<<dim3(125, B_), 768>>>(x);

    // ---- branch 2: attention ----
    kvin_kernel<<<dim3(125, B_), 768>>>(x, at_lcw, at_lcb);
    gemm_kernel<<<dim3(63, 6), 256>>>(x + C2_, C_, at_qw, at_qb,
                                      pq, C2_, M_, C2_, C2_, nullptr, nullptr, 0);
    gemm_kernel<<<dim3(63, 12), 256>>>(pkvin, C2_, at_kvw, at_kvb,
                                       pkv, C_, M_, C_, C2_, nullptr, nullptr, 0);
    attn_kernel<<<dim3(8, H_, B_), 256>>>();

    // ---- projection: dw3 + gelu, then BN1 stats ----
    pjdw_kernel<<<dim3(250, B_), 768>>>(pj_dww, pj_dwb);
    stats_partial_kernel<<<127, C_>>>(pt1, C_);
    stats_finalize_kernel<<<3, 256>>>(127, C_, pj_bn1g, pj_bn1b);

    // ---- c1 (bn1 folded into A) + gelu ----
    gemm_kernel<<<dim3(63, 2), 256>>>(pt1, C_, pj_c1w, pj_c1b,
                                      pt2, PJIN_, M_, PJIN_, C_, pan, pbn, 1);
    stats_partial_kernel<<<127, PJIN_>>>(pt2, PJIN_);
    stats_finalize_kernel<<<1, 256>>>(127, PJIN_, pj_bn2g, pj_bn2b);

    // ---- c2 (bn2 folded into A) ----
    gemm_kernel<<<dim3(63, 12), 256>>>(pt2, PJIN_, pj_c2w, pj_c2b,
                                       pt3, C_, M_, C_, PJIN_, pan, pbn, 0);
    stats_partial_kernel<<<127, C_>>>(pt3, C_);
    stats_finalize_kernel<<<3, 256>>>(127, C_, pj_bn3g, pj_bn3b);

    // ---- bn3 + residual ----
    final_add_kernel<<<(M_*C_/4 + 255)/256, 256>>>(out);
}

// round 11
// speedup vs baseline: 2.5378x; 1.0054x over previous
#include <cuda_runtime.h>
#include <math.h>

#define B_    8
#define L_    999
#define C_    768
#define C2_   384
#define H_    8
#define HD_   48
#define K_    3
#define DCIN_ 96
#define PJIN_ 96
#define M_    (B_*L_)          /* 7992 tokens */
#define SCALE_ 0.14433756729740643f
#define EPS_   1e-5f

__device__ __forceinline__ float gelu_f(float v) {
    return 0.5f * v * (1.0f + erff(v * 0.7071067811865475f));
}

// ---- tf32 mma helpers (validated R7/R8) ----
__device__ __forceinline__ unsigned f2tf(float f) {
    unsigned r; asm("cvt.rna.tf32.f32 %0, %1;" : "=r"(r) : "f"(f)); return r;
}
__device__ __forceinline__ void mma_tf32(float* c, const unsigned* a, const unsigned* b) {
    asm volatile("mma.sync.aligned.m16n8k8.row.col.f32.tf32.tf32.f32 "
                 "{%0,%1,%2,%3}, {%4,%5,%6,%7}, {%8,%9}, {%0,%1,%2,%3};"
                 : "+f"(c[0]), "+f"(c[1]), "+f"(c[2]), "+f"(c[3])
                 : "r"(a[0]), "r"(a[1]), "r"(a[2]), "r"(a[3]),
                   "r"(b[0]), "r"(b[1]));
}

// ---------------- scratch (device globals; no allocation allowed) ----------------
__device__ float g_q    [(size_t)M_*C2_];
__device__ float g_kvin [(size_t)M_*C2_];
__device__ float g_kv   [(size_t)M_*C_];
__device__ float g_xc   [(size_t)M_*C_];
__device__ float g_t1   [(size_t)M_*C_];
__device__ float g_t2   [(size_t)M_*PJIN_];
__device__ float g_t3   [(size_t)M_*C_];
__device__ float g_wdyn [B_*C2_*K_];
__device__ float g_bdyn [B_*C2_];
__device__ float g_ps   [128*C_];
__device__ float g_ps2  [128*C_];
__device__ float g_an   [C_];
__device__ float g_bn   [C_];

// ---------------- stage 1: pooled partial sums (4-way split over rows) ----------------
__global__ void pooled_kernel(const float* __restrict__ x) {
    int blk = blockIdx.x;            // (b*3+kk)*4+sub
    int sub = blk & 3;
    int bk  = blk >> 2;
    int b   = bk / K_;
    int kk  = bk % K_;
    int c   = threadIdx.x;           // 384
    int r0 = kk*333 + sub*84;
    int r1 = kk*333 + min(sub*84 + 84, 333);
    const float* xb = x + (size_t)b*L_*C_ + c;
    float s = 0.f;
    for (int l = r0; l < r1; l++) s += xb[(size_t)l*C_];
    g_ps[(size_t)blk*C2_ + c] = s;
}

// ---------------- stage 2: dynamic-conv score MLP + softmax over G ----------------
__global__ void dcmlp_kernel(const float* __restrict__ p1w, const float* __restrict__ p1b,
                             const float* __restrict__ p2w, const float* __restrict__ p2b,
                             const float* __restrict__ dcw, const float* __restrict__ dcb) {
    int b   = blockIdx.x;
    int tid = threadIdx.x;                 // 384
    __shared__ float col[4][C2_];
    __shared__ float hid[4][DCIN_];
    __shared__ float sc [4][2*C2_];
    {
        float cc[3];
        #pragma unroll
        for (int kk = 0; kk < 3; kk++) {
            int base = (b*3+kk)*4;
            cc[kk] = (g_ps[(size_t)(base+0)*C2_+tid] + g_ps[(size_t)(base+1)*C2_+tid]
                    + g_ps[(size_t)(base+2)*C2_+tid] + g_ps[(size_t)(base+3)*C2_+tid]) * (1.0f/333.0f);
            col[kk][tid] = cc[kk];
        }
        col[3][tid] = (cc[0]+cc[1]+cc[2]) * (1.0f/3.0f);
    }
    __syncthreads();
    {
        int kk = tid / DCIN_;
        int i  = tid % DCIN_;
        float s = p1b[i];
        const float* wr = p1w + (size_t)i*C2_;
        #pragma unroll 8
        for (int c = 0; c < C2_; c++) s += wr[c]*col[kk][c];
        hid[kk][i] = gelu_f(s);
    }
    __syncthreads();
    for (int t = tid; t < 4*768; t += 384) {
        int kk = t / 768, o = t % 768;
        float s = p2b[o];
        const float* wr = p2w + (size_t)o*DCIN_;
        #pragma unroll 8
        for (int i = 0; i < DCIN_; i++) s += wr[i]*hid[kk][i];
        sc[kk][o] = s;
    }
    __syncthreads();
    {
        int c = tid;
        #pragma unroll
        for (int kk = 0; kk < 3; kk++) {
            float e0 = sc[kk][c], e1 = sc[kk][C2_+c];
            float mx = fmaxf(e0,e1);
            float a0 = expf(e0-mx), a1 = expf(e1-mx);
            float inv = 1.f/(a0+a1);
            g_wdyn[(b*C2_+c)*3+kk] = (a0*dcw[c*3+kk] + a1*dcw[(C2_+c)*3+kk])*inv;
        }
        float e0 = sc[3][c], e1 = sc[3][C2_+c];
        float mx = fmaxf(e0,e1);
        float a0 = expf(e0-mx), a1 = expf(e1-mx);
        g_bdyn[b*C2_+c] = (a0*dcb[c] + a1*dcb[C2_+c])/(a0+a1);
    }
}

// ---------------- stage 3+4 merged: dynamic depthwise conv + kv_in ----------------
__global__ void dckv_kernel(const float* __restrict__ x,
                            const float* __restrict__ lcw, const float* __restrict__ lcb) {
    int b  = blockIdx.y;
    int tid = threadIdx.x;                 // 768: li 0..7, c4 0..95
    int l  = blockIdx.x*8 + (tid/96);
    int c  = (tid%96)*4;
    if (l >= L_) return;
    float4 zero = make_float4(0.f,0.f,0.f,0.f);
    {   // ---- dconv: x[:, :, c] -> xc[:, :, c] ----
        const float* wp = g_wdyn + ((size_t)b*C2_ + c)*3;
        float4 wA = *(const float4*)(wp);
        float4 wB = *(const float4*)(wp+4);
        float4 wC = *(const float4*)(wp+8);
        float4 bv = *(const float4*)(g_bdyn + (size_t)b*C2_ + c);
        const float* xb = x + ((size_t)b*L_ + l)*C_ + c;
        float4 xm = (l > 0)      ? *(const float4*)(xb - C_) : zero;
        float4 x0 = *(const float4*)(xb);
        float4 xp = (l+1 < L_)   ? *(const float4*)(xb + C_) : zero;
        float4 r;
        r.x = xm.x*wA.x + x0.x*wA.y + xp.x*wA.z + bv.x;
        r.y = xm.y*wA.w + x0.y*wB.x + xp.y*wB.y + bv.y;
        r.z = xm.z*wB.z + x0.z*wB.w + xp.z*wC.x + bv.z;
        r.w = xm.w*wC.y + x0.w*wC.z + xp.w*wC.w + bv.w;
        *(float4*)(g_xc + ((size_t)b*L_ + l)*C_ + c) = r;
    }
    {   // ---- kvin: x[:, :, C2+c] -> kvin[:, :, c] ----
        const float* wp = lcw + (size_t)c*3;
        float4 wA = *(const float4*)(wp);
        float4 wB = *(const float4*)(wp+4);
        float4 wC = *(const float4*)(wp+8);
        float4 bv = *(const float4*)(lcb + c);
        const float* xb = x + ((size_t)b*L_ + l)*C_ + C2_ + c;
        float4 xm = (l > 0)      ? *(const float4*)(xb - C_) : zero;
        float4 x0 = *(const float4*)(xb);
        float4 xp = (l+1 < L_)   ? *(const float4*)(xb + C_) : zero;
        float4 r;
        r.x = xm.x*wA.x + x0.x*wA.y + xp.x*wA.z + bv.x + x0.x;
        r.y = xm.y*wA.w + x0.y*wB.x + xp.y*wB.y + bv.y + x0.y;
        r.z = xm.z*wB.z + x0.z*wB.w + xp.z*wC.x + bv.z + x0.z;
        r.w = xm.w*wC.y + x0.w*wC.z + xp.w*wC.w + bv.w + x0.w;
        *(float4*)(g_kvin + ((size_t)b*L_ + l)*C2_ + c) = r;
    }
}

// ---------------- GEMM v7: tf32 tensor cores, double-buffered, fused BN-stats ----------
// C[m,n] = sum_k a(A[m,k]) * W[n,k] + bias[n] ; optional per-k affine on A, gelu epilogue;
// optional per-(row-block, channel) stats partials (ps/ps2) for downstream BatchNorm.
__global__ void __launch_bounds__(256, 2)
gemm_kernel(const float* __restrict__ A, int lda,
            const float* __restrict__ W,
            const float* __restrict__ bias,
            float* __restrict__ Cmat, int ldc,
            int M, int N, int Kd,
            const float* __restrict__ ascale,
            const float* __restrict__ ashift,
            int dogelu,
            float* __restrict__ ps, float* __restrict__ ps2)
{
    __shared__ unsigned As[2][128][20];
    __shared__ unsigned Ws[2][64][20];
    __shared__ float sred[8][32][2];
    int tid  = threadIdx.x;                // 256 = 8 warps
    int wid  = tid >> 5, lane = tid & 31;
    int gid  = lane >> 2, tig = lane & 3;
    int m0 = blockIdx.x*128, n0 = blockIdx.y*64;
    int mw = (wid >> 1) * 32;
    int nw = (wid & 1) * 32;

    float acc[2][4][4];
    #pragma unroll
    for (int i = 0; i < 2; i++)
        #pragma unroll
        for (int j = 0; j < 4; j++)
            #pragma unroll
            for (int t = 0; t < 4; t++) acc[i][j][t] = 0.f;

    int alr = tid >> 1, alk = (tid & 1) << 3;   // A stage: row 0..127, k 0/8
    int wlr = tid >> 2, wlk = (tid & 3) << 2;   // W stage: row 0..63,  k 0/4/8/12
    float4 zero = make_float4(0.f,0.f,0.f,0.f);
    float4 a0, a1, w0;

    auto loadc = [&](int k0) {
        a0 = zero; a1 = zero; w0 = zero;
        int gm = m0 + alr;
        if (gm < M) {
            const float* ap = A + (size_t)gm*lda + k0 + alk;
            a0 = *(const float4*)(ap);
            a1 = *(const float4*)(ap+4);
        }
        if (ascale) {
            int kb = k0 + alk;
            a0.x = a0.x*ascale[kb+0] + ashift[kb+0];
            a0.y = a0.y*ascale[kb+1] + ashift[kb+1];
            a0.z = a0.z*ascale[kb+2] + ashift[kb+2];
            a0.w = a0.w*ascale[kb+3] + ashift[kb+3];
            a1.x = a1.x*ascale[kb+4] + ashift[kb+4];
            a1.y = a1.y*ascale[kb+5] + ashift[kb+5];
            a1.z = a1.z*ascale[kb+6] + ashift[kb+6];
            a1.w = a1.w*ascale[kb+7] + ashift[kb+7];
        }
        int gn = n0 + wlr;
        if (gn < N) w0 = *(const float4*)(W + (size_t)gn*Kd + k0 + wlk);
    };
    auto storec = [&](int st) {
        As[st][alr][alk+0]=f2tf(a0.x); As[st][alr][alk+1]=f2tf(a0.y);
        As[st][alr][alk+2]=f2tf(a0.z); As[st][alr][alk+3]=f2tf(a0.w);
        As[st][alr][alk+4]=f2tf(a1.x); As[st][alr][alk+5]=f2tf(a1.y);
        As[st][alr][alk+6]=f2tf(a1.z); As[st][alr][alk+7]=f2tf(a1.w);
        Ws[st][wlr][wlk+0]=f2tf(w0.x); Ws[st][wlr][wlk+1]=f2tf(w0.y);
        Ws[st][wlr][wlk+2]=f2tf(w0.z); Ws[st][wlr][wlk+3]=f2tf(w0.w);
    };

    int nk = Kd >> 4;
    loadc(0);
    storec(0);
    __syncthreads();

    for (int i = 0; i < nk; i++) {
        int buf = i & 1;
        if (i+1 < nk) loadc((i+1) << 4);     // prefetch next chunk (hidden behind mma)
        #pragma unroll
        for (int k8 = 0; k8 < 16; k8 += 8) {
            unsigned bfr[4][2];
            #pragma unroll
            for (int nt = 0; nt < 4; nt++) {
                int nb = nw + nt*8 + gid;
                bfr[nt][0] = Ws[buf][nb][k8 + tig];
                bfr[nt][1] = Ws[buf][nb][k8 + 4 + tig];
            }
            #pragma unroll
            for (int mt = 0; mt < 2; mt++) {
                int mb = mw + mt*16 + gid;
                unsigned afr[4];
                afr[0] = As[buf][mb    ][k8 + tig];
                afr[1] = As[buf][mb + 8][k8 + tig];
                afr[2] = As[buf][mb    ][k8 + 4 + tig];
                afr[3] = As[buf][mb + 8][k8 + 4 + tig];
                #pragma unroll
                for (int nt = 0; nt < 4; nt++)
                    mma_tf32(acc[mt][nt], afr, bfr[nt]);
            }
        }
        if (i+1 < nk) {
            storec(buf ^ 1);                 // stage last read in iter i-1 (sync-separated)
            __syncthreads();
        }
    }

    // ---- epilogue: bias (+gelu) in-place in acc, store, then optional BN-stats ----
    #pragma unroll
    for (int mt = 0; mt < 2; mt++) {
        #pragma unroll
        for (int nt = 0; nt < 4; nt++) {
            int gn = n0 + nw + nt*8 + 2*tig;
            if (gn < N) {
                float b0v = bias[gn], b1v = bias[gn+1];
                acc[mt][nt][0] += b0v; acc[mt][nt][1] += b1v;
                acc[mt][nt][2] += b0v; acc[mt][nt][3] += b1v;
                if (dogelu) {
                    acc[mt][nt][0] = gelu_f(acc[mt][nt][0]);
                    acc[mt][nt][1] = gelu_f(acc[mt][nt][1]);
                    acc[mt][nt][2] = gelu_f(acc[mt][nt][2]);
                    acc[mt][nt][3] = gelu_f(acc[mt][nt][3]);
                }
                int gm0 = m0 + mw + mt*16 + gid;
                if (gm0 < M)
                    *(float2*)(Cmat + (size_t)gm0*ldc + gn) = make_float2(acc[mt][nt][0], acc[mt][nt][1]);
                int gm1 = gm0 + 8;
                if (gm1 < M)
                    *(float2*)(Cmat + (size_t)gm1*ldc + gn) = make_float2(acc[mt][nt][2], acc[mt][nt][3]);
            } else {
                acc[mt][nt][0]=0.f; acc[mt][nt][1]=0.f; acc[mt][nt][2]=0.f; acc[mt][nt][3]=0.f;
            }
        }
    }

    if (ps) {
        // per-column (s, s^2) over this block's valid rows
        #pragma unroll
        for (int nt = 0; nt < 4; nt++) {
            #pragma unroll
            for (int j = 0; j < 2; j++) {
                float s = 0.f, s2 = 0.f;
                #pragma unroll
                for (int mt = 0; mt < 2; mt++) {
                    int gm0 = m0 + mw + mt*16 + gid;
                    if (gm0 < M)     { float t = acc[mt][nt][j];   s += t; s2 += t*t; }
                    if (gm0 + 8 < M) { float t = acc[mt][nt][j+2]; s += t; s2 += t*t; }
                }
                // reduce over the 8 row-groups (gid) within the warp
                s  += __shfl_xor_sync(0xffffffffu, s,  4);
                s  += __shfl_xor_sync(0xffffffffu, s,  8);
                s  += __shfl_xor_sync(0xffffffffu, s, 16);
                s2 += __shfl_xor_sync(0xffffffffu, s2,  4);
                s2 += __shfl_xor_sync(0xffffffffu, s2,  8);
                s2 += __shfl_xor_sync(0xffffffffu, s2, 16);
                if (gid == 0) {
                    int colw = nt*8 + 2*tig + j;
                    sred[wid][colw][0] = s;
                    sred[wid][colw][1] = s2;
                }
            }
        }
        __syncthreads();
        if (tid < 128) {
            int g   = tid >> 6;          // n-half (0/1)
            int col = (tid >> 1) & 31;
            int q   = tid & 1;
            float t = sred[g][col][q] + sred[g+2][col][q] + sred[g+4][col][q] + sred[g+6][col][q];
            int gn = n0 + g*32 + col;
            if (gn < N) {
                float* dst = q ? ps2 : ps;
                dst[(size_t)blockIdx.x*N + gn] = t;
            }
        }
    }
}

// ---------------- stage 7: flash attention v4 (tf32 mma) -> xc[:, :, 384:768] ----------
// Block: 128 q-rows, 8 warps; warp = private 16-row q-group over full 64-key tiles.
// Output reproduces the reference transpose+flat-reshape reinterpretation:
// (c = h*HD+d, l) -> flat = c*L + l -> xc[b, flat/C2, C2 + flat%C2].
__global__ void __launch_bounds__(256, 2) attn_kernel() {
    // smem: sh_ps (union: Q staging [128][52] / K tile [64][52] / P [128][68]) + V [64][56]
    __shared__ unsigned sh_ps[128*68];     // 34816 B
    __shared__ unsigned sh_vs[64*56];      // 14336 B  (total 49152 = 48KB)
    int qt = blockIdx.x;                   // 8 q tiles of 128
    int h  = blockIdx.y;
    int b  = blockIdx.z;
    int tid = threadIdx.x;                 // 256
    int wid = tid >> 5, lane = tid & 31;
    int gid = lane >> 2, tig = lane & 3;
    int qw  = wid*16;

    const float* qb = g_q  + (size_t)b*L_*C2_ + h*HD_;
    const float* kb = g_kv + (size_t)b*L_*C_  + h*HD_;
    const float* vb = kb + C2_;

    // ---- Q staging (tf32) into sh_ps[row][d], stride 52 ----
    {
        int row = tid >> 1, dh = (tid & 1)*24;
        int gl = qt*128 + row;
        if (gl < L_) {
            #pragma unroll
            for (int t = 0; t < 6; t++) {
                float4 v = *(const float4*)(qb + (size_t)gl*C2_ + dh + t*4);
                sh_ps[row*52+dh+t*4+0]=f2tf(v.x); sh_ps[row*52+dh+t*4+1]=f2tf(v.y);
                sh_ps[row*52+dh+t*4+2]=f2tf(v.z); sh_ps[row*52+dh+t*4+3]=f2tf(v.w);
            }
        } else {
            #pragma unroll
            for (int t = 0; t < 24; t++) sh_ps[row*52+dh+t] = 0u;
        }
    }
    __syncthreads();
    // ---- Q A-fragments resident in registers ----
    unsigned qfr[6][4];
    {
        int r0 = qw + gid, r1 = r0 + 8;
        #pragma unroll
        for (int k8i = 0; k8i < 6; k8i++) {
            int d = k8i*8;
            qfr[k8i][0] = sh_ps[r0*52 + d + tig];
            qfr[k8i][1] = sh_ps[r1*52 + d + tig];
            qfr[k8i][2] = sh_ps[r0*52 + d + tig + 4];
            qfr[k8i][3] = sh_ps[r1*52 + d + tig + 4];
        }
    }

    float m[2]    = {-1e30f, -1e30f};
    float lsum[2] = {0.f, 0.f};
    float o[6][4];
    #pragma unroll
    for (int nt = 0; nt < 6; nt++)
        #pragma unroll
        for (int t = 0; t < 4; t++) o[nt][t] = 0.f;

    for (int kt = 0; kt < 16; kt++) {
        __syncthreads();   // prev stage2 (ps/vs reads) and Q-frag reads done
        {   // cooperative K,V tile load (tf32): ks = sh_ps[key][d] stride 52; vs stride 56
            int key = tid >> 2, dp = (tid & 3)*12;
            int gl = kt*64 + key;
            if (gl < L_) {
                #pragma unroll
                for (int t = 0; t < 3; t++) {
                    float4 kv = *(const float4*)(kb + (size_t)gl*C_ + dp + t*4);
                    sh_ps[key*52+dp+t*4+0]=f2tf(kv.x); sh_ps[key*52+dp+t*4+1]=f2tf(kv.y);
                    sh_ps[key*52+dp+t*4+2]=f2tf(kv.z); sh_ps[key*52+dp+t*4+3]=f2tf(kv.w);
                    float4 vv = *(const float4*)(vb + (size_t)gl*C_ + dp + t*4);
                    sh_vs[key*56+dp+t*4+0]=f2tf(vv.x); sh_vs[key*56+dp+t*4+1]=f2tf(vv.y);
                    sh_vs[key*56+dp+t*4+2]=f2tf(vv.z); sh_vs[key*56+dp+t*4+3]=f2tf(vv.w);
                }
            } else {
                #pragma unroll
                for (int t = 0; t < 12; t++) { sh_ps[key*52+dp+t]=0u; sh_vs[key*56+dp+t]=0u; }
            }
        }
        __syncthreads();

        // ---- stage 1: S = Q K^T over 8 n-tiles (64 keys) ----
        float s[8][4];
        #pragma unroll
        for (int nt = 0; nt < 8; nt++)
            #pragma unroll
            for (int t = 0; t < 4; t++) s[nt][t] = 0.f;
        #pragma unroll
        for (int k8i = 0; k8i < 6; k8i++) {
            #pragma unroll
            for (int nt = 0; nt < 8; nt++) {
                unsigned bfr[2];
                int nb = (nt*8 + gid)*52 + k8i*8;
                bfr[0] = sh_ps[nb + tig];
                bfr[1] = sh_ps[nb + tig + 4];
                mma_tf32(s[nt], qfr[k8i], bfr);
            }
        }

        // ---- warp-local running softmax (rows gid / gid+8 of this warp's 16) ----
        float corr[2];
        int kbase = kt*64 + 2*tig;
        #pragma unroll
        for (int r = 0; r < 2; r++) {
            int i0 = 2*r;
            float mx = -1e30f;
            #pragma unroll
            for (int nt = 0; nt < 8; nt++) {
                int c0 = kbase + nt*8;
                float v0 = (c0   < L_) ? s[nt][i0  ]*SCALE_ : -1e30f;
                float v1 = (c0+1 < L_) ? s[nt][i0+1]*SCALE_ : -1e30f;
                s[nt][i0] = v0; s[nt][i0+1] = v1;
                mx = fmaxf(mx, fmaxf(v0, v1));
            }
            mx = fmaxf(mx, __shfl_xor_sync(0xffffffffu, mx, 1));
            mx = fmaxf(mx, __shfl_xor_sync(0xffffffffu, mx, 2));
            float mnew = fmaxf(m[r], mx);
            corr[r] = __expf(m[r] - mnew);
            m[r] = mnew;
            float lp = 0.f;
            #pragma unroll
            for (int nt = 0; nt < 8; nt++) {
                float p0 = __expf(s[nt][i0  ] - mnew);
                float p1 = __expf(s[nt][i0+1] - mnew);
                s[nt][i0] = p0; s[nt][i0+1] = p1;
                lp += p0 + p1;
            }
            lp += __shfl_xor_sync(0xffffffffu, lp, 1);
            lp += __shfl_xor_sync(0xffffffffu, lp, 2);
            lsum[r] = lsum[r]*corr[r] + lp;
        }

        __syncthreads();   // ALL warps done reading K tile; safe to overwrite with P

        // ---- store P (tf32) to warp-private rows of sh_ps[q][key], stride 68 ----
        {
            int r0 = qw + gid, r1 = r0 + 8;
            #pragma unroll
            for (int nt = 0; nt < 8; nt++) {
                int col = nt*8 + 2*tig;
                *(uint2*)&sh_ps[r0*68 + col] = make_uint2(f2tf(s[nt][0]), f2tf(s[nt][1]));
                *(uint2*)&sh_ps[r1*68 + col] = make_uint2(f2tf(s[nt][2]), f2tf(s[nt][3]));
            }
        }
        __syncwarp();

        // ---- rescale O frags, then stage 2: O += P V ----
        #pragma unroll
        for (int nt = 0; nt < 6; nt++) {
            o[nt][0] *= corr[0]; o[nt][1] *= corr[0];
            o[nt][2] *= corr[1]; o[nt][3] *= corr[1];
        }
        {
            int r0 = qw + gid, r1 = r0 + 8;
            #pragma unroll
            for (int k8i = 0; k8i < 8; k8i++) {
                int kk = k8i*8;
                unsigned afr[4];
                afr[0] = sh_ps[r0*68 + kk + tig];
                afr[1] = sh_ps[r1*68 + kk + tig];
                afr[2] = sh_ps[r0*68 + kk + tig + 4];
                afr[3] = sh_ps[r1*68 + kk + tig + 4];
                #pragma unroll
                for (int nt = 0; nt < 6; nt++) {
                    unsigned bfr[2];
                    bfr[0] = sh_vs[(kk + tig    )*56 + nt*8 + gid];
                    bfr[1] = sh_vs[(kk + tig + 4)*56 + nt*8 + gid];
                    mma_tf32(o[nt], afr, bfr);
                }
            }
        }
    }

    // ---- epilogue: normalize and scatter via the flat-reshape mapping ----
    {
        float inv0 = 1.f/lsum[0], inv1 = 1.f/lsum[1];
        int q0 = qt*128 + qw + gid, q1 = q0 + 8;
        float* xcb = g_xc + (size_t)b*L_*C_;
        #pragma unroll
        for (int nt = 0; nt < 6; nt++) {
            #pragma unroll
            for (int j = 0; j < 2; j++) {
                int d = nt*8 + 2*tig + j;
                int c = h*HD_ + d;
                if (q0 < L_) {
                    int flat = c*L_ + q0;
                    int lp2 = flat / C2_;
                    int cp  = flat - lp2*C2_;
                    xcb[(size_t)lp2*C_ + C2_ + cp] = o[nt][j]*inv0;
                }
                if (q1 < L_) {
                    int flat = c*L_ + q1;
                    int lp2 = flat / C2_;
                    int cp  = flat - lp2*C2_;
                    xcb[(size_t)lp2*C_ + C2_ + cp] = o[nt][j+2]*inv1;
                }
            }
        }
    }
}

// ---------------- stage 8a: t1 = gelu(dw3(xc)) with fused BN1 partials ----------------
__global__ void pjdw_kernel(const float* __restrict__ dww, const float* __restrict__ dwb) {
    int b = blockIdx.y, chunk = blockIdx.x;   // 8 x 8
    int c = threadIdx.x;                      // 768
    int l0 = chunk*125, l1 = min(l0+125, L_);
    float w0 = dww[c*3], w1 = dww[c*3+1], w2 = dww[c*3+2], bb = dwb[c];
    const float* xb = g_xc + (size_t)b*L_*C_ + c;
    float*       yb = g_t1 + (size_t)b*L_*C_ + c;
    float s = 0.f, s2 = 0.f;
    float xm1 = (l0 > 0) ? xb[(size_t)(l0-1)*C_] : 0.f;
    float x0  = xb[(size_t)l0*C_];
    for (int l = l0; l < l1; l++) {
        float xp1 = (l+1 < L_) ? xb[(size_t)(l+1)*C_] : 0.f;
        float v = gelu_f(xm1*w0 + x0*w1 + xp1*w2 + bb);
        yb[(size_t)l*C_] = v;
        s += v; s2 += v*v;
        xm1 = x0; x0 = xp1;
    }
    int blk = b*8 + chunk;
    g_ps [(size_t)blk*C_ + c] = s;
    g_ps2[(size_t)blk*C_ + c] = s2;
}

// ---------------- deterministic BN finalize: partials -> affine (a,b) ----------
__global__ void stats_finalize_kernel(int nblk, int Cch,
                                      const float* __restrict__ gam,
                                      const float* __restrict__ bet) {
    int c = blockIdx.x*blockDim.x + threadIdx.x;
    if (c >= Cch) return;
    double s = 0.0, s2 = 0.0;
    for (int i = 0; i < nblk; i++) { s += (double)g_ps[(size_t)i*Cch+c]; s2 += (double)g_ps2[(size_t)i*Cch+c]; }
    double mean = s / (double)M_;
    double var  = s2 / (double)M_ - mean*mean;
    if (var < 0.0) var = 0.0;
    float rs = (float)(1.0 / sqrt(var + (double)EPS_));
    float a  = gam[c]*rs;
    g_an[c] = a;
    g_bn[c] = bet[c] - (float)mean*a;
}

// ---------------- final: out = bn3(t3) + xc ----------------
__global__ void final_add_kernel(float* __restrict__ out) {
    int idx4 = blockIdx.x*blockDim.x + threadIdx.x;
    if (idx4 >= M_*C_/4) return;
    int idx = idx4*4;
    int c = idx % C_;
    float4 t = *(const float4*)(g_t3 + idx);
    float4 xv= *(const float4*)(g_xc + idx);
    float4 a = *(const float4*)(g_an + c);
    float4 bb= *(const float4*)(g_bn + c);
    float4 r;
    r.x = t.x*a.x + bb.x + xv.x;
    r.y = t.y*a.y + bb.y + xv.y;
    r.z = t.z*a.z + bb.z + xv.z;
    r.w = t.w*a.w + bb.w + xv.w;
    *(float4*)(out + idx) = r;
}

// =======================================================================================
extern "C" void kernel_launch(void* const* d_in, const int* in_sizes, int n_in,
                              void* d_out, int out_size) {
    const float* x        = (const float*)d_in[0];
    const float* dc_weight= (const float*)d_in[1];
    const float* dc_bias  = (const float*)d_in[2];
    const float* dc_p1w   = (const float*)d_in[3];
    const float* dc_p1b   = (const float*)d_in[4];
    const float* dc_p2w   = (const float*)d_in[5];
    const float* dc_p2b   = (const float*)d_in[6];
    const float* at_qw    = (const float*)d_in[7];
    const float* at_qb    = (const float*)d_in[8];
    const float* at_kvw   = (const float*)d_in[9];
    const float* at_kvb   = (const float*)d_in[10];
    const float* at_lcw   = (const float*)d_in[11];
    const float* at_lcb   = (const float*)d_in[12];
    const float* pj_dww   = (const float*)d_in[13];
    const float* pj_dwb   = (const float*)d_in[14];
    const float* pj_bn1g  = (const float*)d_in[15];
    const float* pj_bn1b  = (const float*)d_in[16];
    const float* pj_c1w   = (const float*)d_in[17];
    const float* pj_c1b   = (const float*)d_in[18];
    const float* pj_bn2g  = (const float*)d_in[19];
    const float* pj_bn2b  = (const float*)d_in[20];
    const float* pj_c2w   = (const float*)d_in[21];
    const float* pj_c2b   = (const float*)d_in[22];
    const float* pj_bn3g  = (const float*)d_in[23];
    const float* pj_bn3b  = (const float*)d_in[24];
    float* out = (float*)d_out;

    float *pq, *pkvin, *pkv, *pt1, *pt2, *pt3, *pan, *pbn, *pps, *pps2;
    cudaGetSymbolAddress((void**)&pq,    g_q);
    cudaGetSymbolAddress((void**)&pkvin, g_kvin);
    cudaGetSymbolAddress((void**)&pkv,   g_kv);
    cudaGetSymbolAddress((void**)&pt1,   g_t1);
    cudaGetSymbolAddress((void**)&pt2,   g_t2);
    cudaGetSymbolAddress((void**)&pt3,   g_t3);
    cudaGetSymbolAddress((void**)&pan,   g_an);
    cudaGetSymbolAddress((void**)&pbn,   g_bn);
    cudaGetSymbolAddress((void**)&pps,   g_ps);
    cudaGetSymbolAddress((void**)&pps2,  g_ps2);

    // ---- branch 1: dynamic conv scores ----
    pooled_kernel<<<96, C2_>>>(x);
    dcmlp_kernel<<<B_, C2_>>>(dc_p1w, dc_p1b, dc_p2w, dc_p2b, dc_weight, dc_bias);
    // ---- dconv + kvin (merged) ----
    dckv_kernel<<<dim3(125, B_), 768>>>(x, at_lcw, at_lcb);

    // ---- attention ----
    gemm_kernel<<<dim3(63, 6), 256>>>(x + C2_, C_, at_qw, at_qb,
                                      pq, C2_, M_, C2_, C2_, nullptr, nullptr, 0, nullptr, nullptr);
    gemm_kernel<<<dim3(63, 12), 256>>>(pkvin, C2_, at_kvw, at_kvb,
                                       pkv, C_, M_, C_, C2_, nullptr, nullptr, 0, nullptr, nullptr);
    attn_kernel<<<dim3(8, H_, B_), 256>>>();

    // ---- projection: dw3 + gelu with fused BN1 partials ----
    pjdw_kernel<<<dim3(8, B_), C_>>>(pj_dww, pj_dwb);
    stats_finalize_kernel<<<3, 256>>>(64, C_, pj_bn1g, pj_bn1b);

    // ---- c1 (bn1 folded into A) + gelu + fused BN2 partials ----
    gemm_kernel<<<dim3(63, 2), 256>>>(pt1, C_, pj_c1w, pj_c1b,
                                      pt2, PJIN_, M_, PJIN_, C_, pan, pbn, 1, pps, pps2);
    stats_finalize_kernel<<<1, 256>>>(63, PJIN_, pj_bn2g, pj_bn2b);

    // ---- c2 (bn2 folded into A) + fused BN3 partials ----
    gemm_kernel<<<dim3(63, 12), 256>>>(pt2, PJIN_, pj_c2w, pj_c2b,
                                       pt3, C_, M_, C_, PJIN_, pan, pbn, 0, pps, pps2);
    stats_finalize_kernel<<<3, 256>>>(63, C_, pj_bn3g, pj_bn3b);

    // ---- bn3 + residual ----
    final_add_kernel<<<(M_*C_/4 + 255)/256, 256>>>(out);
}

// round 13
// speedup vs baseline: 2.5808x; 1.0169x over previous
#include <cuda_runtime.h>
#include <math.h>

#define B_    8
#define L_    999
#define C_    768
#define C2_   384
#define H_    8
#define HD_   48
#define K_    3
#define DCIN_ 96
#define PJIN_ 96
#define M_    (B_*L_)          /* 7992 tokens */
#define SCALE_ 0.14433756729740643f
#define EPS_   1e-5f

__device__ __forceinline__ float gelu_f(float v) {
    return 0.5f * v * (1.0f + erff(v * 0.7071067811865475f));
}

// ---- tf32 mma helpers (validated R7/R8) ----
__device__ __forceinline__ unsigned f2tf(float f) {
    unsigned r; asm("cvt.rna.tf32.f32 %0, %1;" : "=r"(r) : "f"(f)); return r;
}
__device__ __forceinline__ void mma_tf32(float* c, const unsigned* a, const unsigned* b) {
    asm volatile("mma.sync.aligned.m16n8k8.row.col.f32.tf32.tf32.f32 "
                 "{%0,%1,%2,%3}, {%4,%5,%6,%7}, {%8,%9}, {%0,%1,%2,%3};"
                 : "+f"(c[0]), "+f"(c[1]), "+f"(c[2]), "+f"(c[3])
                 : "r"(a[0]), "r"(a[1]), "r"(a[2]), "r"(a[3]),
                   "r"(b[0]), "r"(b[1]));
}

// ---------------- scratch (device globals; no allocation allowed) ----------------
__device__ float g_q    [(size_t)M_*C2_];
__device__ float g_kvin [(size_t)M_*C2_];
__device__ float g_kv   [(size_t)M_*C_];
__device__ float g_xc   [(size_t)M_*C_];
__device__ float g_t1   [(size_t)M_*C_];
__device__ float g_t2   [(size_t)M_*PJIN_];
__device__ float g_t3   [(size_t)M_*C_];
__device__ float g_wdyn [B_*C2_*K_];
__device__ float g_bdyn [B_*C2_];
__device__ float g_ps   [128*C_];
__device__ float g_ps2  [128*C_];
__device__ float g_an   [C_];
__device__ float g_bn   [C_];

// ---------------- stage 1: pooled partial sums (4-way split over rows) ----------------
__global__ void pooled_kernel(const float* __restrict__ x) {
    int blk = blockIdx.x;            // (b*3+kk)*4+sub
    int sub = blk & 3;
    int bk  = blk >> 2;
    int b   = bk / K_;
    int kk  = bk % K_;
    int c   = threadIdx.x;           // 384
    int r0 = kk*333 + sub*84;
    int r1 = kk*333 + min(sub*84 + 84, 333);
    const float* xb = x + (size_t)b*L_*C_ + c;
    float s = 0.f;
    for (int l = r0; l < r1; l++) s += xb[(size_t)l*C_];
    g_ps[(size_t)blk*C2_ + c] = s;
}

// ---------------- stage 2: dynamic-conv score MLP + softmax over G ----------------
__global__ void dcmlp_kernel(const float* __restrict__ p1w, const float* __restrict__ p1b,
                             const float* __restrict__ p2w, const float* __restrict__ p2b,
                             const float* __restrict__ dcw, const float* __restrict__ dcb) {
    int b   = blockIdx.x;
    int tid = threadIdx.x;                 // 384
    __shared__ float col[4][C2_];
    __shared__ float hid[4][DCIN_];
    __shared__ float sc [4][2*C2_];
    {
        float cc[3];
        #pragma unroll
        for (int kk = 0; kk < 3; kk++) {
            int base = (b*3+kk)*4;
            cc[kk] = (g_ps[(size_t)(base+0)*C2_+tid] + g_ps[(size_t)(base+1)*C2_+tid]
                    + g_ps[(size_t)(base+2)*C2_+tid] + g_ps[(size_t)(base+3)*C2_+tid]) * (1.0f/333.0f);
            col[kk][tid] = cc[kk];
        }
        col[3][tid] = (cc[0]+cc[1]+cc[2]) * (1.0f/3.0f);
    }
    __syncthreads();
    {
        int kk = tid / DCIN_;
        int i  = tid % DCIN_;
        float s = p1b[i];
        const float* wr = p1w + (size_t)i*C2_;
        #pragma unroll 8
        for (int c = 0; c < C2_; c++) s += wr[c]*col[kk][c];
        hid[kk][i] = gelu_f(s);
    }
    __syncthreads();
    for (int t = tid; t < 4*768; t += 384) {
        int kk = t / 768, o = t % 768;
        float s = p2b[o];
        const float* wr = p2w + (size_t)o*DCIN_;
        #pragma unroll 8
        for (int i = 0; i < DCIN_; i++) s += wr[i]*hid[kk][i];
        sc[kk][o] = s;
    }
    __syncthreads();
    {
        int c = tid;
        #pragma unroll
        for (int kk = 0; kk < 3; kk++) {
            float e0 = sc[kk][c], e1 = sc[kk][C2_+c];
            float mx = fmaxf(e0,e1);
            float a0 = expf(e0-mx), a1 = expf(e1-mx);
            float inv = 1.f/(a0+a1);
            g_wdyn[(b*C2_+c)*3+kk] = (a0*dcw[c*3+kk] + a1*dcw[(C2_+c)*3+kk])*inv;
        }
        float e0 = sc[3][c], e1 = sc[3][C2_+c];
        float mx = fmaxf(e0,e1);
        float a0 = expf(e0-mx), a1 = expf(e1-mx);
        g_bdyn[b*C2_+c] = (a0*dcb[c] + a1*dcb[C2_+c])/(a0+a1);
    }
}

// ---------------- stage 3+4 merged: dynamic depthwise conv + kv_in ----------------
__global__ void dckv_kernel(const float* __restrict__ x,
                            const float* __restrict__ lcw, const float* __restrict__ lcb) {
    int b  = blockIdx.y;
    int tid = threadIdx.x;                 // 768: li 0..7, c4 0..95
    int l  = blockIdx.x*8 + (tid/96);
    int c  = (tid%96)*4;
    if (l >= L_) return;
    float4 zero = make_float4(0.f,0.f,0.f,0.f);
    {   // ---- dconv: x[:, :, c] -> xc[:, :, c] ----
        const float* wp = g_wdyn + ((size_t)b*C2_ + c)*3;
        float4 wA = *(const float4*)(wp);
        float4 wB = *(const float4*)(wp+4);
        float4 wC = *(const float4*)(wp+8);
        float4 bv = *(const float4*)(g_bdyn + (size_t)b*C2_ + c);
        const float* xb = x + ((size_t)b*L_ + l)*C_ + c;
        float4 xm = (l > 0)      ? *(const float4*)(xb - C_) : zero;
        float4 x0 = *(const float4*)(xb);
        float4 xp = (l+1 < L_)   ? *(const float4*)(xb + C_) : zero;
        float4 r;
        r.x = xm.x*wA.x + x0.x*wA.y + xp.x*wA.z + bv.x;
        r.y = xm.y*wA.w + x0.y*wB.x + xp.y*wB.y + bv.y;
        r.z = xm.z*wB.z + x0.z*wB.w + xp.z*wC.x + bv.z;
        r.w = xm.w*wC.y + x0.w*wC.z + xp.w*wC.w + bv.w;
        *(float4*)(g_xc + ((size_t)b*L_ + l)*C_ + c) = r;
    }
    {   // ---- kvin: x[:, :, C2+c] -> kvin[:, :, c] ----
        const float* wp = lcw + (size_t)c*3;
        float4 wA = *(const float4*)(wp);
        float4 wB = *(const float4*)(wp+4);
        float4 wC = *(const float4*)(wp+8);
        float4 bv = *(const float4*)(lcb + c);
        const float* xb = x + ((size_t)b*L_ + l)*C_ + C2_ + c;
        float4 xm = (l > 0)      ? *(const float4*)(xb - C_) : zero;
        float4 x0 = *(const float4*)(xb);
        float4 xp = (l+1 < L_)   ? *(const float4*)(xb + C_) : zero;
        float4 r;
        r.x = xm.x*wA.x + x0.x*wA.y + xp.x*wA.z + bv.x + x0.x;
        r.y = xm.y*wA.w + x0.y*wB.x + xp.y*wB.y + bv.y + x0.y;
        r.z = xm.z*wB.z + x0.z*wB.w + xp.z*wC.x + bv.z + x0.z;
        r.w = xm.w*wC.y + x0.w*wC.z + xp.w*wC.w + bv.w + x0.w;
        *(float4*)(g_kvin + ((size_t)b*L_ + l)*C2_ + c) = r;
    }
}

// ---------------- GEMM body: tf32 tensor cores, double-buffered, fused BN-stats --------
// smem passed in (flat): As 2*128*20, Ws 2*64*20, sred 8*32*2
__device__ __forceinline__ void
gemm_body(unsigned* As, unsigned* Ws, float* sred,
          const float* __restrict__ A, int lda,
          const float* __restrict__ W,
          const float* __restrict__ bias,
          float* __restrict__ Cmat, int ldc,
          int M, int N, int Kd,
          const float* __restrict__ ascale,
          const float* __restrict__ ashift,
          int dogelu,
          float* __restrict__ ps, float* __restrict__ ps2,
          int blkx, int blky)
{
    int tid  = threadIdx.x;                // 256 = 8 warps
    int wid  = tid >> 5, lane = tid & 31;
    int gid  = lane >> 2, tig = lane & 3;
    int m0 = blkx*128, n0 = blky*64;
    int mw = (wid >> 1) * 32;
    int nw = (wid & 1) * 32;

    float acc[2][4][4];
    #pragma unroll
    for (int i = 0; i < 2; i++)
        #pragma unroll
        for (int j = 0; j < 4; j++)
            #pragma unroll
            for (int t = 0; t < 4; t++) acc[i][j][t] = 0.f;

    int alr = tid >> 1, alk = (tid & 1) << 3;   // A stage: row 0..127, k 0/8
    int wlr = tid >> 2, wlk = (tid & 3) << 2;   // W stage: row 0..63,  k 0/4/8/12
    float4 zero = make_float4(0.f,0.f,0.f,0.f);
    float4 a0, a1, w0;

    auto loadc = [&](int k0) {
        a0 = zero; a1 = zero; w0 = zero;
        int gm = m0 + alr;
        if (gm < M) {
            const float* ap = A + (size_t)gm*lda + k0 + alk;
            a0 = *(const float4*)(ap);
            a1 = *(const float4*)(ap+4);
        }
        if (ascale) {
            int kb = k0 + alk;
            a0.x = a0.x*ascale[kb+0] + ashift[kb+0];
            a0.y = a0.y*ascale[kb+1] + ashift[kb+1];
            a0.z = a0.z*ascale[kb+2] + ashift[kb+2];
            a0.w = a0.w*ascale[kb+3] + ashift[kb+3];
            a1.x = a1.x*ascale[kb+4] + ashift[kb+4];
            a1.y = a1.y*ascale[kb+5] + ashift[kb+5];
            a1.z = a1.z*ascale[kb+6] + ashift[kb+6];
            a1.w = a1.w*ascale[kb+7] + ashift[kb+7];
        }
        int gn = n0 + wlr;
        if (gn < N) w0 = *(const float4*)(W + (size_t)gn*Kd + k0 + wlk);
    };
    auto storec = [&](int st) {
        unsigned* Ar = As + ((size_t)st*128 + alr)*20 + alk;
        Ar[0]=f2tf(a0.x); Ar[1]=f2tf(a0.y); Ar[2]=f2tf(a0.z); Ar[3]=f2tf(a0.w);
        Ar[4]=f2tf(a1.x); Ar[5]=f2tf(a1.y); Ar[6]=f2tf(a1.z); Ar[7]=f2tf(a1.w);
        unsigned* Wr = Ws + ((size_t)st*64 + wlr)*20 + wlk;
        Wr[0]=f2tf(w0.x); Wr[1]=f2tf(w0.y); Wr[2]=f2tf(w0.z); Wr[3]=f2tf(w0.w);
    };

    int nk = Kd >> 4;
    loadc(0);
    storec(0);
    __syncthreads();

    for (int i = 0; i < nk; i++) {
        int buf = i & 1;
        if (i+1 < nk) loadc((i+1) << 4);     // prefetch next chunk (hidden behind mma)
        const unsigned* Ab = As + (size_t)buf*128*20;
        const unsigned* Wb = Ws + (size_t)buf*64*20;
        #pragma unroll
        for (int k8 = 0; k8 < 16; k8 += 8) {
            unsigned bfr[4][2];
            #pragma unroll
            for (int nt = 0; nt < 4; nt++) {
                int nb = nw + nt*8 + gid;
                bfr[nt][0] = Wb[nb*20 + k8 + tig];
                bfr[nt][1] = Wb[nb*20 + k8 + 4 + tig];
            }
            #pragma unroll
            for (int mt = 0; mt < 2; mt++) {
                int mb = mw + mt*16 + gid;
                unsigned afr[4];
                afr[0] = Ab[mb*20       + k8 + tig];
                afr[1] = Ab[(mb+8)*20   + k8 + tig];
                afr[2] = Ab[mb*20       + k8 + 4 + tig];
                afr[3] = Ab[(mb+8)*20   + k8 + 4 + tig];
                #pragma unroll
                for (int nt = 0; nt < 4; nt++)
                    mma_tf32(acc[mt][nt], afr, bfr[nt]);
            }
        }
        if (i+1 < nk) {
            storec(buf ^ 1);                 // stage last read in iter i-1 (sync-separated)
            __syncthreads();
        }
    }

    // ---- epilogue: bias (+gelu) in-place in acc, store, then optional BN-stats ----
    #pragma unroll
    for (int mt = 0; mt < 2; mt++) {
        #pragma unroll
        for (int nt = 0; nt < 4; nt++) {
            int gn = n0 + nw + nt*8 + 2*tig;
            if (gn < N) {
                float b0v = bias[gn], b1v = bias[gn+1];
                acc[mt][nt][0] += b0v; acc[mt][nt][1] += b1v;
                acc[mt][nt][2] += b0v; acc[mt][nt][3] += b1v;
                if (dogelu) {
                    acc[mt][nt][0] = gelu_f(acc[mt][nt][0]);
                    acc[mt][nt][1] = gelu_f(acc[mt][nt][1]);
                    acc[mt][nt][2] = gelu_f(acc[mt][nt][2]);
                    acc[mt][nt][3] = gelu_f(acc[mt][nt][3]);
                }
                int gm0 = m0 + mw + mt*16 + gid;
                if (gm0 < M)
                    *(float2*)(Cmat + (size_t)gm0*ldc + gn) = make_float2(acc[mt][nt][0], acc[mt][nt][1]);
                int gm1 = gm0 + 8;
                if (gm1 < M)
                    *(float2*)(Cmat + (size_t)gm1*ldc + gn) = make_float2(acc[mt][nt][2], acc[mt][nt][3]);
            } else {
                acc[mt][nt][0]=0.f; acc[mt][nt][1]=0.f; acc[mt][nt][2]=0.f; acc[mt][nt][3]=0.f;
            }
        }
    }

    if (ps) {
        // per-column (s, s^2) over this block's valid rows
        #pragma unroll
        for (int nt = 0; nt < 4; nt++) {
            #pragma unroll
            for (int j = 0; j < 2; j++) {
                float s = 0.f, s2 = 0.f;
                #pragma unroll
                for (int mt = 0; mt < 2; mt++) {
                    int gm0 = m0 + mw + mt*16 + gid;
                    if (gm0 < M)     { float t = acc[mt][nt][j];   s += t; s2 += t*t; }
                    if (gm0 + 8 < M) { float t = acc[mt][nt][j+2]; s += t; s2 += t*t; }
                }
                s  += __shfl_xor_sync(0xffffffffu, s,  4);
                s  += __shfl_xor_sync(0xffffffffu, s,  8);
                s  += __shfl_xor_sync(0xffffffffu, s, 16);
                s2 += __shfl_xor_sync(0xffffffffu, s2,  4);
                s2 += __shfl_xor_sync(0xffffffffu, s2,  8);
                s2 += __shfl_xor_sync(0xffffffffu, s2, 16);
                if (gid == 0) {
                    int colw = nt*8 + 2*tig + j;
                    sred[(wid*32 + colw)*2 + 0] = s;
                    sred[(wid*32 + colw)*2 + 1] = s2;
                }
            }
        }
        __syncthreads();
        if (tid < 128) {
            int g   = tid >> 6;          // n-half (0/1)
            int col = (tid >> 1) & 31;
            int q   = tid & 1;
            float t = sred[((g  )*32 + col)*2 + q] + sred[((g+2)*32 + col)*2 + q]
                    + sred[((g+4)*32 + col)*2 + q] + sred[((g+6)*32 + col)*2 + q];
            int gn = n0 + g*32 + col;
            if (gn < N) {
                float* dst = q ? ps2 : ps;
                dst[(size_t)blkx*N + gn] = t;
            }
        }
    }
}

// ---------------- generic GEMM wrapper ----------------
__global__ void __launch_bounds__(256, 2)
gemm_kernel(const float* __restrict__ A, int lda,
            const float* __restrict__ W,
            const float* __restrict__ bias,
            float* __restrict__ Cmat, int ldc,
            int M, int N, int Kd,
            const float* __restrict__ ascale,
            const float* __restrict__ ashift,
            int dogelu,
            float* __restrict__ ps, float* __restrict__ ps2)
{
    __shared__ unsigned As[2*128*20];
    __shared__ unsigned Ws[2*64*20];
    __shared__ float sred[8*32*2];
    gemm_body(As, Ws, sred, A, lda, W, bias, Cmat, ldc, M, N, Kd,
              ascale, ashift, dogelu, ps, ps2, blockIdx.x, blockIdx.y);
}

// ---------------- merged q + kv projection GEMM (one launch, z-free y dispatch) --------
__global__ void __launch_bounds__(256, 2)
qkv_kernel(const float* __restrict__ x,
           const float* __restrict__ qw,  const float* __restrict__ qb,
           const float* __restrict__ kvw, const float* __restrict__ kvb)
{
    __shared__ unsigned As[2*128*20];
    __shared__ unsigned Ws[2*64*20];
    __shared__ float sred[8*32*2];
    if (blockIdx.y < 6) {
        gemm_body(As, Ws, sred, x + C2_, C_, qw, qb, g_q, C2_, M_, C2_, C2_,
                  nullptr, nullptr, 0, nullptr, nullptr, blockIdx.x, blockIdx.y);
    } else {
        gemm_body(As, Ws, sred, g_kvin, C2_, kvw, kvb, g_kv, C_, M_, C_, C2_,
                  nullptr, nullptr, 0, nullptr, nullptr, blockIdx.x, blockIdx.y - 6);
    }
}

// ---------------- stage 7: flash attention v4 (tf32 mma) -> xc[:, :, 384:768] ----------
// Block: 128 q-rows, 8 warps; warp = private 16-row q-group over full 64-key tiles.
// Output reproduces the reference transpose+flat-reshape reinterpretation:
// (c = h*HD+d, l) -> flat = c*L + l -> xc[b, flat/C2, C2 + flat%C2].
__global__ void __launch_bounds__(256, 2) attn_kernel() {
    // smem: sh_ps (union: Q staging [128][52] / K tile [64][52] / P [128][68]) + V [64][56]
    __shared__ unsigned sh_ps[128*68];     // 34816 B
    __shared__ unsigned sh_vs[64*56];      // 14336 B  (total 49152 = 48KB)
    int qt = blockIdx.x;                   // 8 q tiles of 128
    int h  = blockIdx.y;
    int b  = blockIdx.z;
    int tid = threadIdx.x;                 // 256
    int wid = tid >> 5, lane = tid & 31;
    int gid = lane >> 2, tig = lane & 3;
    int qw  = wid*16;

    const float* qb = g_q  + (size_t)b*L_*C2_ + h*HD_;
    const float* kb = g_kv + (size_t)b*L_*C_  + h*HD_;
    const float* vb = kb + C2_;

    // ---- Q staging (tf32) into sh_ps[row][d], stride 52 ----
    {
        int row = tid >> 1, dh = (tid & 1)*24;
        int gl = qt*128 + row;
        if (gl < L_) {
            #pragma unroll
            for (int t = 0; t < 6; t++) {
                float4 v = *(const float4*)(qb + (size_t)gl*C2_ + dh + t*4);
                sh_ps[row*52+dh+t*4+0]=f2tf(v.x); sh_ps[row*52+dh+t*4+1]=f2tf(v.y);
                sh_ps[row*52+dh+t*4+2]=f2tf(v.z); sh_ps[row*52+dh+t*4+3]=f2tf(v.w);
            }
        } else {
            #pragma unroll
            for (int t = 0; t < 24; t++) sh_ps[row*52+dh+t] = 0u;
        }
    }
    __syncthreads();
    // ---- Q A-fragments resident in registers ----
    unsigned qfr[6][4];
    {
        int r0 = qw + gid, r1 = r0 + 8;
        #pragma unroll
        for (int k8i = 0; k8i < 6; k8i++) {
            int d = k8i*8;
            qfr[k8i][0] = sh_ps[r0*52 + d + tig];
            qfr[k8i][1] = sh_ps[r1*52 + d + tig];
            qfr[k8i][2] = sh_ps[r0*52 + d + tig + 4];
            qfr[k8i][3] = sh_ps[r1*52 + d + tig + 4];
        }
    }

    float m[2]    = {-1e30f, -1e30f};
    float lsum[2] = {0.f, 0.f};
    float o[6][4];
    #pragma unroll
    for (int nt = 0; nt < 6; nt++)
        #pragma unroll
        for (int t = 0; t < 4; t++) o[nt][t] = 0.f;

    for (int kt = 0; kt < 16; kt++) {
        __syncthreads();   // prev stage2 (ps/vs reads) and Q-frag reads done
        {   // cooperative K,V tile load (tf32): ks = sh_ps[key][d] stride 52; vs stride 56
            int key = tid >> 2, dp = (tid & 3)*12;
            int gl = kt*64 + key;
            if (gl < L_) {
                #pragma unroll
                for (int t = 0; t < 3; t++) {
                    float4 kv = *(const float4*)(kb + (size_t)gl*C_ + dp + t*4);
                    sh_ps[key*52+dp+t*4+0]=f2tf(kv.x); sh_ps[key*52+dp+t*4+1]=f2tf(kv.y);
                    sh_ps[key*52+dp+t*4+2]=f2tf(kv.z); sh_ps[key*52+dp+t*4+3]=f2tf(kv.w);
                    float4 vv = *(const float4*)(vb + (size_t)gl*C_ + dp + t*4);
                    sh_vs[key*56+dp+t*4+0]=f2tf(vv.x); sh_vs[key*56+dp+t*4+1]=f2tf(vv.y);
                    sh_vs[key*56+dp+t*4+2]=f2tf(vv.z); sh_vs[key*56+dp+t*4+3]=f2tf(vv.w);
                }
            } else {
                #pragma unroll
                for (int t = 0; t < 12; t++) { sh_ps[key*52+dp+t]=0u; sh_vs[key*56+dp+t]=0u; }
            }
        }
        __syncthreads();

        // ---- stage 1: S = Q K^T over 8 n-tiles (64 keys) ----
        float s[8][4];
        #pragma unroll
        for (int nt = 0; nt < 8; nt++)
            #pragma unroll
            for (int t = 0; t < 4; t++) s[nt][t] = 0.f;
        #pragma unroll
        for (int k8i = 0; k8i < 6; k8i++) {
            #pragma unroll
            for (int nt = 0; nt < 8; nt++) {
                unsigned bfr[2];
                int nb = (nt*8 + gid)*52 + k8i*8;
                bfr[0] = sh_ps[nb + tig];
                bfr[1] = sh_ps[nb + tig + 4];
                mma_tf32(s[nt], qfr[k8i], bfr);
            }
        }

        // ---- warp-local running softmax (rows gid / gid+8 of this warp's 16) ----
        float corr[2];
        int kbase = kt*64 + 2*tig;
        #pragma unroll
        for (int r = 0; r < 2; r++) {
            int i0 = 2*r;
            float mx = -1e30f;
            #pragma unroll
            for (int nt = 0; nt < 8; nt++) {
                int c0 = kbase + nt*8;
                float v0 = (c0   < L_) ? s[nt][i0  ]*SCALE_ : -1e30f;
                float v1 = (c0+1 < L_) ? s[nt][i0+1]*SCALE_ : -1e30f;
                s[nt][i0] = v0; s[nt][i0+1] = v1;
                mx = fmaxf(mx, fmaxf(v0, v1));
            }
            mx = fmaxf(mx, __shfl_xor_sync(0xffffffffu, mx, 1));
            mx = fmaxf(mx, __shfl_xor_sync(0xffffffffu, mx, 2));
            float mnew = fmaxf(m[r], mx);
            corr[r] = __expf(m[r] - mnew);
            m[r] = mnew;
            float lp = 0.f;
            #pragma unroll
            for (int nt = 0; nt < 8; nt++) {
                float p0 = __expf(s[nt][i0  ] - mnew);
                float p1 = __expf(s[nt][i0+1] - mnew);
                s[nt][i0] = p0; s[nt][i0+1] = p1;
                lp += p0 + p1;
            }
            lp += __shfl_xor_sync(0xffffffffu, lp, 1);
            lp += __shfl_xor_sync(0xffffffffu, lp, 2);
            lsum[r] = lsum[r]*corr[r] + lp;
        }

        __syncthreads();   // ALL warps done reading K tile; safe to overwrite with P

        // ---- store P (tf32) to warp-private rows of sh_ps[q][key], stride 68 ----
        {
            int r0 = qw + gid, r1 = r0 + 8;
            #pragma unroll
            for (int nt = 0; nt < 8; nt++) {
                int col = nt*8 + 2*tig;
                *(uint2*)&sh_ps[r0*68 + col] = make_uint2(f2tf(s[nt][0]), f2tf(s[nt][1]));
                *(uint2*)&sh_ps[r1*68 + col] = make_uint2(f2tf(s[nt][2]), f2tf(s[nt][3]));
            }
        }
        __syncwarp();

        // ---- rescale O frags, then stage 2: O += P V ----
        #pragma unroll
        for (int nt = 0; nt < 6; nt++) {
            o[nt][0] *= corr[0]; o[nt][1] *= corr[0];
            o[nt][2] *= corr[1]; o[nt][3] *= corr[1];
        }
        {
            int r0 = qw + gid, r1 = r0 + 8;
            #pragma unroll
            for (int k8i = 0; k8i < 8; k8i++) {
                int kk = k8i*8;
                unsigned afr[4];
                afr[0] = sh_ps[r0*68 + kk + tig];
                afr[1] = sh_ps[r1*68 + kk + tig];
                afr[2] = sh_ps[r0*68 + kk + tig + 4];
                afr[3] = sh_ps[r1*68 + kk + tig + 4];
                #pragma unroll
                for (int nt = 0; nt < 6; nt++) {
                    unsigned bfr[2];
                    bfr[0] = sh_vs[(kk + tig    )*56 + nt*8 + gid];
                    bfr[1] = sh_vs[(kk + tig + 4)*56 + nt*8 + gid];
                    mma_tf32(o[nt], afr, bfr);
                }
            }
        }
    }

    // ---- epilogue: normalize and scatter via the flat-reshape mapping ----
    {
        float inv0 = 1.f/lsum[0], inv1 = 1.f/lsum[1];
        int q0 = qt*128 + qw + gid, q1 = q0 + 8;
        float* xcb = g_xc + (size_t)b*L_*C_;
        #pragma unroll
        for (int nt = 0; nt < 6; nt++) {
            #pragma unroll
            for (int j = 0; j < 2; j++) {
                int d = nt*8 + 2*tig + j;
                int c = h*HD_ + d;
                if (q0 < L_) {
                    int flat = c*L_ + q0;
                    int lp2 = flat / C2_;
                    int cp  = flat - lp2*C2_;
                    xcb[(size_t)lp2*C_ + C2_ + cp] = o[nt][j]*inv0;
                }
                if (q1 < L_) {
                    int flat = c*L_ + q1;
                    int lp2 = flat / C2_;
                    int cp  = flat - lp2*C2_;
                    xcb[(size_t)lp2*C_ + C2_ + cp] = o[nt][j+2]*inv1;
                }
            }
        }
    }
}

// ---------------- stage 8a: t1 = gelu(dw3(xc)) with fused BN1 partials ----------------
__global__ void pjdw_kernel(const float* __restrict__ dww, const float* __restrict__ dwb) {
    int b = blockIdx.y, chunk = blockIdx.x;   // 8 x 8
    int c = threadIdx.x;                      // 768
    int l0 = chunk*125, l1 = min(l0+125, L_);
    float w0 = dww[c*3], w1 = dww[c*3+1], w2 = dww[c*3+2], bb = dwb[c];
    const float* xb = g_xc + (size_t)b*L_*C_ + c;
    float*       yb = g_t1 + (size_t)b*L_*C_ + c;
    float s = 0.f, s2 = 0.f;
    float xm1 = (l0 > 0) ? xb[(size_t)(l0-1)*C_] : 0.f;
    float x0  = xb[(size_t)l0*C_];
    for (int l = l0; l < l1; l++) {
        float xp1 = (l+1 < L_) ? xb[(size_t)(l+1)*C_] : 0.f;
        float v = gelu_f(xm1*w0 + x0*w1 + xp1*w2 + bb);
        yb[(size_t)l*C_] = v;
        s += v; s2 += v*v;
        xm1 = x0; x0 = xp1;
    }
    int blk = b*8 + chunk;
    g_ps [(size_t)blk*C_ + c] = s;
    g_ps2[(size_t)blk*C_ + c] = s2;
}

// ---------------- deterministic BN finalize: partials -> affine (a,b) ----------
__global__ void stats_finalize_kernel(int nblk, int Cch,
                                      const float* __restrict__ gam,
                                      const float* __restrict__ bet) {
    int c = blockIdx.x*blockDim.x + threadIdx.x;
    if (c >= Cch) return;
    double s = 0.0, s2 = 0.0;
    for (int i = 0; i < nblk; i++) { s += (double)g_ps[(size_t)i*Cch+c]; s2 += (double)g_ps2[(size_t)i*Cch+c]; }
    double mean = s / (double)M_;
    double var  = s2 / (double)M_ - mean*mean;
    if (var < 0.0) var = 0.0;
    float rs = (float)(1.0 / sqrt(var + (double)EPS_));
    float a  = gam[c]*rs;
    g_an[c] = a;
    g_bn[c] = bet[c] - (float)mean*a;
}

// ---------------- final: out = bn3(t3) + xc ----------------
__global__ void final_add_kernel(float* __restrict__ out) {
    int idx4 = blockIdx.x*blockDim.x + threadIdx.x;
    if (idx4 >= M_*C_/4) return;
    int idx = idx4*4;
    int c = idx % C_;
    float4 t = *(const float4*)(g_t3 + idx);
    float4 xv= *(const float4*)(g_xc + idx);
    float4 a = *(const float4*)(g_an + c);
    float4 bb= *(const float4*)(g_bn + c);
    float4 r;
    r.x = t.x*a.x + bb.x + xv.x;
    r.y = t.y*a.y + bb.y + xv.y;
    r.z = t.z*a.z + bb.z + xv.z;
    r.w = t.w*a.w + bb.w + xv.w;
    *(float4*)(out + idx) = r;
}

// =======================================================================================
extern "C" void kernel_launch(void* const* d_in, const int* in_sizes, int n_in,
                              void* d_out, int out_size) {
    const float* x        = (const float*)d_in[0];
    const float* dc_weight= (const float*)d_in[1];
    const float* dc_bias  = (const float*)d_in[2];
    const float* dc_p1w   = (const float*)d_in[3];
    const float* dc_p1b   = (const float*)d_in[4];
    const float* dc_p2w   = (const float*)d_in[5];
    const float* dc_p2b   = (const float*)d_in[6];
    const float* at_qw    = (const float*)d_in[7];
    const float* at_qb    = (const float*)d_in[8];
    const float* at_kvw   = (const float*)d_in[9];
    const float* at_kvb   = (const float*)d_in[10];
    const float* at_lcw   = (const float*)d_in[11];
    const float* at_lcb   = (const float*)d_in[12];
    const float* pj_dww   = (const float*)d_in[13];
    const float* pj_dwb   = (const float*)d_in[14];
    const float* pj_bn1g  = (const float*)d_in[15];
    const float* pj_bn1b  = (const float*)d_in[16];
    const float* pj_c1w   = (const float*)d_in[17];
    const float* pj_c1b   = (const float*)d_in[18];
    const float* pj_bn2g  = (const float*)d_in[19];
    const float* pj_bn2b  = (const float*)d_in[20];
    const float* pj_c2w   = (const float*)d_in[21];
    const float* pj_c2b   = (const float*)d_in[22];
    const float* pj_bn3g  = (const float*)d_in[23];
    const float* pj_bn3b  = (const float*)d_in[24];
    float* out = (float*)d_out;

    float *pq, *pkvin, *pkv, *pt1, *pt2, *pt3, *pan, *pbn, *pps, *pps2;
    cudaGetSymbolAddress((void**)&pq,    g_q);
    cudaGetSymbolAddress((void**)&pkvin, g_kvin);
    cudaGetSymbolAddress((void**)&pkv,   g_kv);
    cudaGetSymbolAddress((void**)&pt1,   g_t1);
    cudaGetSymbolAddress((void**)&pt2,   g_t2);
    cudaGetSymbolAddress((void**)&pt3,   g_t3);
    cudaGetSymbolAddress((void**)&pan,   g_an);
    cudaGetSymbolAddress((void**)&pbn,   g_bn);
    cudaGetSymbolAddress((void**)&pps,   g_ps);
    cudaGetSymbolAddress((void**)&pps2,  g_ps2);

    // ---- branch 1: dynamic conv scores ----
    pooled_kernel<<<96, C2_>>>(x);
    dcmlp_kernel<<<B_, C2_>>>(dc_p1w, dc_p1b, dc_p2w, dc_p2b, dc_weight, dc_bias);
    // ---- dconv + kvin (merged) ----
    dckv_kernel<<<dim3(125, B_), 768>>>(x, at_lcw, at_lcb);

    // ---- attention: merged q + kv projection, then flash attention ----
    qkv_kernel<<<dim3(63, 18), 256>>>(x, at_qw, at_qb, at_kvw, at_kvb);
    attn_kernel<<<dim3(8, H_, B_), 256>>>();

    // ---- projection: dw3 + gelu with fused BN1 partials ----
    pjdw_kernel<<<dim3(8, B_), C_>>>(pj_dww, pj_dwb);
    stats_finalize_kernel<<<3, 256>>>(64, C_, pj_bn1g, pj_bn1b);

    // ---- c1 (bn1 folded into A) + gelu + fused BN2 partials ----
    gemm_kernel<<<dim3(63, 2), 256>>>(pt1, C_, pj_c1w, pj_c1b,
                                      pt2, PJIN_, M_, PJIN_, C_, pan, pbn, 1, pps, pps2);
    stats_finalize_kernel<<<1, 256>>>(63, PJIN_, pj_bn2g, pj_bn2b);

    // ---- c2 (bn2 folded into A) + fused BN3 partials ----
    gemm_kernel<<<dim3(63, 12), 256>>>(pt2, PJIN_, pj_c2w, pj_c2b,
                                       pt3, C_, M_, C_, PJIN_, pan, pbn, 0, pps, pps2);
    stats_finalize_kernel<<<3, 256>>>(63, C_, pj_bn3g, pj_bn3b);

    // ---- bn3 + residual ----
    final_add_kernel<<<(M_*C_/4 + 255)/256, 256>>>(out);
}

// round 14
// speedup vs baseline: 2.5888x; 1.0031x over previous
#include <cuda_runtime.h>
#include <math.h>

#define B_    8
#define L_    999
#define C_    768
#define C2_   384
#define H_    8
#define HD_   48
#define K_    3
#define DCIN_ 96
#define PJIN_ 96
#define M_    (B_*L_)          /* 7992 tokens */
#define SCALE_ 0.14433756729740643f
#define EPS_   1e-5f

__device__ __forceinline__ float gelu_f(float v) {
    return 0.5f * v * (1.0f + erff(v * 0.7071067811865475f));
}

// ---- tf32 mma helpers (validated R7/R8) ----
__device__ __forceinline__ unsigned f2tf(float f) {
    unsigned r; asm("cvt.rna.tf32.f32 %0, %1;" : "=r"(r) : "f"(f)); return r;
}
__device__ __forceinline__ void mma_tf32(float* c, const unsigned* a, const unsigned* b) {
    asm volatile("mma.sync.aligned.m16n8k8.row.col.f32.tf32.tf32.f32 "
                 "{%0,%1,%2,%3}, {%4,%5,%6,%7}, {%8,%9}, {%0,%1,%2,%3};"
                 : "+f"(c[0]), "+f"(c[1]), "+f"(c[2]), "+f"(c[3])
                 : "r"(a[0]), "r"(a[1]), "r"(a[2]), "r"(a[3]),
                   "r"(b[0]), "r"(b[1]));
}

// ---------------- scratch (device globals; no allocation allowed) ----------------
__device__ float g_q    [(size_t)M_*C2_];
__device__ float g_kvin [(size_t)M_*C2_];
__device__ float g_kv   [(size_t)M_*C_];
__device__ float g_xc   [(size_t)M_*C_];
__device__ float g_t1   [(size_t)M_*C_];
__device__ float g_t2   [(size_t)M_*PJIN_];
__device__ float g_t3   [(size_t)M_*C_];
__device__ float g_wdyn [B_*C2_*K_];
__device__ float g_bdyn [B_*C2_];
__device__ float g_ps   [128*C_];
__device__ float g_ps2  [128*C_];
__device__ float g_an   [C_];
__device__ float g_bn   [C_];

// ---------------- stage 1: pooled partial sums (4-way split over rows) ----------------
__global__ void pooled_kernel(const float* __restrict__ x) {
    int blk = blockIdx.x;            // (b*3+kk)*4+sub
    int sub = blk & 3;
    int bk  = blk >> 2;
    int b   = bk / K_;
    int kk  = bk % K_;
    int c   = threadIdx.x;           // 384
    int r0 = kk*333 + sub*84;
    int r1 = kk*333 + min(sub*84 + 84, 333);
    const float* xb = x + (size_t)b*L_*C_ + c;
    float s = 0.f;
    for (int l = r0; l < r1; l++) s += xb[(size_t)l*C_];
    g_ps[(size_t)blk*C2_ + c] = s;
}

// ---------------- stage 2: dynamic-conv score MLP + softmax over G ----------------
__global__ void dcmlp_kernel(const float* __restrict__ p1w, const float* __restrict__ p1b,
                             const float* __restrict__ p2w, const float* __restrict__ p2b,
                             const float* __restrict__ dcw, const float* __restrict__ dcb) {
    int b   = blockIdx.x;
    int tid = threadIdx.x;                 // 384
    __shared__ float col[4][C2_];
    __shared__ float hid[4][DCIN_];
    __shared__ float sc [4][2*C2_];
    {
        float cc[3];
        #pragma unroll
        for (int kk = 0; kk < 3; kk++) {
            int base = (b*3+kk)*4;
            cc[kk] = (g_ps[(size_t)(base+0)*C2_+tid] + g_ps[(size_t)(base+1)*C2_+tid]
                    + g_ps[(size_t)(base+2)*C2_+tid] + g_ps[(size_t)(base+3)*C2_+tid]) * (1.0f/333.0f);
            col[kk][tid] = cc[kk];
        }
        col[3][tid] = (cc[0]+cc[1]+cc[2]) * (1.0f/3.0f);
    }
    __syncthreads();
    {
        int kk = tid / DCIN_;
        int i  = tid % DCIN_;
        float s = p1b[i];
        const float* wr = p1w + (size_t)i*C2_;
        #pragma unroll 8
        for (int c = 0; c < C2_; c++) s += wr[c]*col[kk][c];
        hid[kk][i] = gelu_f(s);
    }
    __syncthreads();
    for (int t = tid; t < 4*768; t += 384) {
        int kk = t / 768, o = t % 768;
        float s = p2b[o];
        const float* wr = p2w + (size_t)o*DCIN_;
        #pragma unroll 8
        for (int i = 0; i < DCIN_; i++) s += wr[i]*hid[kk][i];
        sc[kk][o] = s;
    }
    __syncthreads();
    {
        int c = tid;
        #pragma unroll
        for (int kk = 0; kk < 3; kk++) {
            float e0 = sc[kk][c], e1 = sc[kk][C2_+c];
            float mx = fmaxf(e0,e1);
            float a0 = expf(e0-mx), a1 = expf(e1-mx);
            float inv = 1.f/(a0+a1);
            g_wdyn[(b*C2_+c)*3+kk] = (a0*dcw[c*3+kk] + a1*dcw[(C2_+c)*3+kk])*inv;
        }
        float e0 = sc[3][c], e1 = sc[3][C2_+c];
        float mx = fmaxf(e0,e1);
        float a0 = expf(e0-mx), a1 = expf(e1-mx);
        g_bdyn[b*C2_+c] = (a0*dcb[c] + a1*dcb[C2_+c])/(a0+a1);
    }
}

// ---------------- stage 3+4 merged: dynamic depthwise conv + kv_in ----------------
__global__ void dckv_kernel(const float* __restrict__ x,
                            const float* __restrict__ lcw, const float* __restrict__ lcb) {
    int b  = blockIdx.y;
    int tid = threadIdx.x;                 // 768: li 0..7, c4 0..95
    int l  = blockIdx.x*8 + (tid/96);
    int c  = (tid%96)*4;
    if (l >= L_) return;
    float4 zero = make_float4(0.f,0.f,0.f,0.f);
    {   // ---- dconv: x[:, :, c] -> xc[:, :, c] ----
        const float* wp = g_wdyn + ((size_t)b*C2_ + c)*3;
        float4 wA = *(const float4*)(wp);
        float4 wB = *(const float4*)(wp+4);
        float4 wC = *(const float4*)(wp+8);
        float4 bv = *(const float4*)(g_bdyn + (size_t)b*C2_ + c);
        const float* xb = x + ((size_t)b*L_ + l)*C_ + c;
        float4 xm = (l > 0)      ? *(const float4*)(xb - C_) : zero;
        float4 x0 = *(const float4*)(xb);
        float4 xp = (l+1 < L_)   ? *(const float4*)(xb + C_) : zero;
        float4 r;
        r.x = xm.x*wA.x + x0.x*wA.y + xp.x*wA.z + bv.x;
        r.y = xm.y*wA.w + x0.y*wB.x + xp.y*wB.y + bv.y;
        r.z = xm.z*wB.z + x0.z*wB.w + xp.z*wC.x + bv.z;
        r.w = xm.w*wC.y + x0.w*wC.z + xp.w*wC.w + bv.w;
        *(float4*)(g_xc + ((size_t)b*L_ + l)*C_ + c) = r;
    }
    {   // ---- kvin: x[:, :, C2+c] -> kvin[:, :, c] ----
        const float* wp = lcw + (size_t)c*3;
        float4 wA = *(const float4*)(wp);
        float4 wB = *(const float4*)(wp+4);
        float4 wC = *(const float4*)(wp+8);
        float4 bv = *(const float4*)(lcb + c);
        const float* xb = x + ((size_t)b*L_ + l)*C_ + C2_ + c;
        float4 xm = (l > 0)      ? *(const float4*)(xb - C_) : zero;
        float4 x0 = *(const float4*)(xb);
        float4 xp = (l+1 < L_)   ? *(const float4*)(xb + C_) : zero;
        float4 r;
        r.x = xm.x*wA.x + x0.x*wA.y + xp.x*wA.z + bv.x + x0.x;
        r.y = xm.y*wA.w + x0.y*wB.x + xp.y*wB.y + bv.y + x0.y;
        r.z = xm.z*wB.z + x0.z*wB.w + xp.z*wC.x + bv.z + x0.z;
        r.w = xm.w*wC.y + x0.w*wC.z + xp.w*wC.w + bv.w + x0.w;
        *(float4*)(g_kvin + ((size_t)b*L_ + l)*C2_ + c) = r;
    }
}

// ---------------- GEMM body v8: 128x128 block, 32x64 warp tile, double-buffered --------
// smem flat: As 2*128*20, Ws 2*128*20, sred 8*64*2
__device__ __forceinline__ void
gemm_body(unsigned* As, unsigned* Ws, float* sred,
          const float* __restrict__ A, int lda,
          const float* __restrict__ W,
          const float* __restrict__ bias,
          float* __restrict__ Cmat, int ldc,
          int M, int N, int Kd,
          const float* __restrict__ ascale,
          const float* __restrict__ ashift,
          int dogelu,
          float* __restrict__ ps, float* __restrict__ ps2,
          int blkx, int blky)
{
    int tid  = threadIdx.x;                // 256 = 8 warps
    int wid  = tid >> 5, lane = tid & 31;
    int gid  = lane >> 2, tig = lane & 3;
    int m0 = blkx*128, n0 = blky*128;
    int mw = (wid >> 1) * 32;              // 0/32/64/96
    int nw = (wid & 1) * 64;               // 0/64

    float acc[2][8][4];                    // [m16][n8 x8]
    #pragma unroll
    for (int i = 0; i < 2; i++)
        #pragma unroll
        for (int j = 0; j < 8; j++)
            #pragma unroll
            for (int t = 0; t < 4; t++) acc[i][j][t] = 0.f;

    int lr = tid >> 1, lk = (tid & 1) << 3;   // stage: row 0..127, k 0/8 (A and W identical)
    float4 zero = make_float4(0.f,0.f,0.f,0.f);
    float4 a0, a1, w0, w1;

    auto loadc = [&](int k0) {
        a0 = zero; a1 = zero; w0 = zero; w1 = zero;
        int gm = m0 + lr;
        if (gm < M) {
            const float* ap = A + (size_t)gm*lda + k0 + lk;
            a0 = *(const float4*)(ap);
            a1 = *(const float4*)(ap+4);
        }
        if (ascale) {
            int kb = k0 + lk;
            a0.x = a0.x*ascale[kb+0] + ashift[kb+0];
            a0.y = a0.y*ascale[kb+1] + ashift[kb+1];
            a0.z = a0.z*ascale[kb+2] + ashift[kb+2];
            a0.w = a0.w*ascale[kb+3] + ashift[kb+3];
            a1.x = a1.x*ascale[kb+4] + ashift[kb+4];
            a1.y = a1.y*ascale[kb+5] + ashift[kb+5];
            a1.z = a1.z*ascale[kb+6] + ashift[kb+6];
            a1.w = a1.w*ascale[kb+7] + ashift[kb+7];
        }
        int gn = n0 + lr;
        if (gn < N) {
            const float* wptr = W + (size_t)gn*Kd + k0 + lk;
            w0 = *(const float4*)(wptr);
            w1 = *(const float4*)(wptr+4);
        }
    };
    auto storec = [&](int st) {
        unsigned* Ar = As + ((size_t)st*128 + lr)*20 + lk;
        Ar[0]=f2tf(a0.x); Ar[1]=f2tf(a0.y); Ar[2]=f2tf(a0.z); Ar[3]=f2tf(a0.w);
        Ar[4]=f2tf(a1.x); Ar[5]=f2tf(a1.y); Ar[6]=f2tf(a1.z); Ar[7]=f2tf(a1.w);
        unsigned* Wr = Ws + ((size_t)st*128 + lr)*20 + lk;
        Wr[0]=f2tf(w0.x); Wr[1]=f2tf(w0.y); Wr[2]=f2tf(w0.z); Wr[3]=f2tf(w0.w);
        Wr[4]=f2tf(w1.x); Wr[5]=f2tf(w1.y); Wr[6]=f2tf(w1.z); Wr[7]=f2tf(w1.w);
    };

    int nk = Kd >> 4;
    loadc(0);
    storec(0);
    __syncthreads();

    for (int i = 0; i < nk; i++) {
        int buf = i & 1;
        if (i+1 < nk) loadc((i+1) << 4);     // prefetch next chunk (hidden behind mma)
        const unsigned* Ab = As + (size_t)buf*128*20;
        const unsigned* Wb = Ws + (size_t)buf*128*20;
        #pragma unroll
        for (int k8 = 0; k8 < 16; k8 += 8) {
            #pragma unroll
            for (int mt = 0; mt < 2; mt++) {
                int mb = mw + mt*16 + gid;
                unsigned afr[4];
                afr[0] = Ab[mb*20     + k8 + tig];
                afr[1] = Ab[(mb+8)*20 + k8 + tig];
                afr[2] = Ab[mb*20     + k8 + 4 + tig];
                afr[3] = Ab[(mb+8)*20 + k8 + 4 + tig];
                #pragma unroll
                for (int nt = 0; nt < 8; nt++) {
                    unsigned bfr[2];
                    int nb = nw + nt*8 + gid;
                    bfr[0] = Wb[nb*20 + k8 + tig];
                    bfr[1] = Wb[nb*20 + k8 + 4 + tig];
                    mma_tf32(acc[mt][nt], afr, bfr);
                }
            }
        }
        if (i+1 < nk) {
            storec(buf ^ 1);                 // stage last read in iter i-1 (sync-separated)
            __syncthreads();
        }
    }

    // ---- epilogue: bias (+gelu) in-place in acc, store, then optional BN-stats ----
    #pragma unroll
    for (int mt = 0; mt < 2; mt++) {
        #pragma unroll
        for (int nt = 0; nt < 8; nt++) {
            int gn = n0 + nw + nt*8 + 2*tig;
            if (gn < N) {
                float b0v = bias[gn], b1v = bias[gn+1];
                acc[mt][nt][0] += b0v; acc[mt][nt][1] += b1v;
                acc[mt][nt][2] += b0v; acc[mt][nt][3] += b1v;
                if (dogelu) {
                    acc[mt][nt][0] = gelu_f(acc[mt][nt][0]);
                    acc[mt][nt][1] = gelu_f(acc[mt][nt][1]);
                    acc[mt][nt][2] = gelu_f(acc[mt][nt][2]);
                    acc[mt][nt][3] = gelu_f(acc[mt][nt][3]);
                }
                int gm0 = m0 + mw + mt*16 + gid;
                if (gm0 < M)
                    *(float2*)(Cmat + (size_t)gm0*ldc + gn) = make_float2(acc[mt][nt][0], acc[mt][nt][1]);
                int gm1 = gm0 + 8;
                if (gm1 < M)
                    *(float2*)(Cmat + (size_t)gm1*ldc + gn) = make_float2(acc[mt][nt][2], acc[mt][nt][3]);
            } else {
                acc[mt][nt][0]=0.f; acc[mt][nt][1]=0.f; acc[mt][nt][2]=0.f; acc[mt][nt][3]=0.f;
            }
        }
    }

    if (ps) {
        // per-column (s, s^2) over this block's valid rows; warp covers 64 cols (nw..nw+63)
        #pragma unroll
        for (int nt = 0; nt < 8; nt++) {
            #pragma unroll
            for (int j = 0; j < 2; j++) {
                float s = 0.f, s2 = 0.f;
                #pragma unroll
                for (int mt = 0; mt < 2; mt++) {
                    int gm0 = m0 + mw + mt*16 + gid;
                    if (gm0 < M)     { float t = acc[mt][nt][j];   s += t; s2 += t*t; }
                    if (gm0 + 8 < M) { float t = acc[mt][nt][j+2]; s += t; s2 += t*t; }
                }
                s  += __shfl_xor_sync(0xffffffffu, s,  4);
                s  += __shfl_xor_sync(0xffffffffu, s,  8);
                s  += __shfl_xor_sync(0xffffffffu, s, 16);
                s2 += __shfl_xor_sync(0xffffffffu, s2,  4);
                s2 += __shfl_xor_sync(0xffffffffu, s2,  8);
                s2 += __shfl_xor_sync(0xffffffffu, s2, 16);
                if (gid == 0) {
                    int colw = nt*8 + 2*tig + j;               // 0..63 within warp range
                    sred[(wid*64 + colw)*2 + 0] = s;
                    sred[(wid*64 + colw)*2 + 1] = s2;
                }
            }
        }
        __syncthreads();
        if (tid < 256) {
            int g   = tid >> 7;              // n-half (0/1): warps with (wid&1)==g
            int col = (tid >> 1) & 63;
            int q   = tid & 1;
            // sum warps {g, g+2, g+4, g+6}
            float t = sred[((g  )*64 + col)*2 + q] + sred[((g+2)*64 + col)*2 + q]
                    + sred[((g+4)*64 + col)*2 + q] + sred[((g+6)*64 + col)*2 + q];
            int gn = n0 + g*64 + col;
            if (gn < N) {
                float* dst = q ? ps2 : ps;
                dst[(size_t)blkx*N + gn] = t;
            }
        }
    }
}

// ---------------- generic GEMM wrapper ----------------
__global__ void __launch_bounds__(256, 2)
gemm_kernel(const float* __restrict__ A, int lda,
            const float* __restrict__ W,
            const float* __restrict__ bias,
            float* __restrict__ Cmat, int ldc,
            int M, int N, int Kd,
            const float* __restrict__ ascale,
            const float* __restrict__ ashift,
            int dogelu,
            float* __restrict__ ps, float* __restrict__ ps2)
{
    __shared__ unsigned As[2*128*20];
    __shared__ unsigned Ws[2*128*20];
    __shared__ float sred[8*64*2];
    gemm_body(As, Ws, sred, A, lda, W, bias, Cmat, ldc, M, N, Kd,
              ascale, ashift, dogelu, ps, ps2, blockIdx.x, blockIdx.y);
}

// ---------------- merged q + kv projection GEMM (one launch) --------
__global__ void __launch_bounds__(256, 2)
qkv_kernel(const float* __restrict__ x,
           const float* __restrict__ qw,  const float* __restrict__ qb,
           const float* __restrict__ kvw, const float* __restrict__ kvb)
{
    __shared__ unsigned As[2*128*20];
    __shared__ unsigned Ws[2*128*20];
    __shared__ float sred[8*64*2];
    if (blockIdx.y < 3) {
        gemm_body(As, Ws, sred, x + C2_, C_, qw, qb, g_q, C2_, M_, C2_, C2_,
                  nullptr, nullptr, 0, nullptr, nullptr, blockIdx.x, blockIdx.y);
    } else {
        gemm_body(As, Ws, sred, g_kvin, C2_, kvw, kvb, g_kv, C_, M_, C_, C2_,
                  nullptr, nullptr, 0, nullptr, nullptr, blockIdx.x, blockIdx.y - 3);
    }
}

// ---------------- stage 7: flash attention v4 (tf32 mma) -> xc[:, :, 384:768] ----------
// Block: 128 q-rows, 8 warps; warp = private 16-row q-group over full 64-key tiles.
// Output reproduces the reference transpose+flat-reshape reinterpretation:
// (c = h*HD+d, l) -> flat = c*L + l -> xc[b, flat/C2, C2 + flat%C2].
__global__ void __launch_bounds__(256, 2) attn_kernel() {
    // smem: sh_ps (union: Q staging [128][52] / K tile [64][52] / P [128][68]) + V [64][56]
    __shared__ unsigned sh_ps[128*68];     // 34816 B
    __shared__ unsigned sh_vs[64*56];      // 14336 B  (total 49152 = 48KB)
    int qt = blockIdx.x;                   // 8 q tiles of 128
    int h  = blockIdx.y;
    int b  = blockIdx.z;
    int tid = threadIdx.x;                 // 256
    int wid = tid >> 5, lane = tid & 31;
    int gid = lane >> 2, tig = lane & 3;
    int qw  = wid*16;

    const float* qb = g_q  + (size_t)b*L_*C2_ + h*HD_;
    const float* kb = g_kv + (size_t)b*L_*C_  + h*HD_;
    const float* vb = kb + C2_;

    // ---- Q staging (tf32) into sh_ps[row][d], stride 52 ----
    {
        int row = tid >> 1, dh = (tid & 1)*24;
        int gl = qt*128 + row;
        if (gl < L_) {
            #pragma unroll
            for (int t = 0; t < 6; t++) {
                float4 v = *(const float4*)(qb + (size_t)gl*C2_ + dh + t*4);
                sh_ps[row*52+dh+t*4+0]=f2tf(v.x); sh_ps[row*52+dh+t*4+1]=f2tf(v.y);
                sh_ps[row*52+dh+t*4+2]=f2tf(v.z); sh_ps[row*52+dh+t*4+3]=f2tf(v.w);
            }
        } else {
            #pragma unroll
            for (int t = 0; t < 24; t++) sh_ps[row*52+dh+t] = 0u;
        }
    }
    __syncthreads();
    // ---- Q A-fragments resident in registers ----
    unsigned qfr[6][4];
    {
        int r0 = qw + gid, r1 = r0 + 8;
        #pragma unroll
        for (int k8i = 0; k8i < 6; k8i++) {
            int d = k8i*8;
            qfr[k8i][0] = sh_ps[r0*52 + d + tig];
            qfr[k8i][1] = sh_ps[r1*52 + d + tig];
            qfr[k8i][2] = sh_ps[r0*52 + d + tig + 4];
            qfr[k8i][3] = sh_ps[r1*52 + d + tig + 4];
        }
    }

    float m[2]    = {-1e30f, -1e30f};
    float lsum[2] = {0.f, 0.f};
    float o[6][4];
    #pragma unroll
    for (int nt = 0; nt < 6; nt++)
        #pragma unroll
        for (int t = 0; t < 4; t++) o[nt][t] = 0.f;

    for (int kt = 0; kt < 16; kt++) {
        __syncthreads();   // prev stage2 (ps/vs reads) and Q-frag reads done
        {   // cooperative K,V tile load (tf32): ks = sh_ps[key][d] stride 52; vs stride 56
            int key = tid >> 2, dp = (tid & 3)*12;
            int gl = kt*64 + key;
            if (gl < L_) {
                #pragma unroll
                for (int t = 0; t < 3; t++) {
                    float4 kv = *(const float4*)(kb + (size_t)gl*C_ + dp + t*4);
                    sh_ps[key*52+dp+t*4+0]=f2tf(kv.x); sh_ps[key*52+dp+t*4+1]=f2tf(kv.y);
                    sh_ps[key*52+dp+t*4+2]=f2tf(kv.z); sh_ps[key*52+dp+t*4+3]=f2tf(kv.w);
                    float4 vv = *(const float4*)(vb + (size_t)gl*C_ + dp + t*4);
                    sh_vs[key*56+dp+t*4+0]=f2tf(vv.x); sh_vs[key*56+dp+t*4+1]=f2tf(vv.y);
                    sh_vs[key*56+dp+t*4+2]=f2tf(vv.z); sh_vs[key*56+dp+t*4+3]=f2tf(vv.w);
                }
            } else {
                #pragma unroll
                for (int t = 0; t < 12; t++) { sh_ps[key*52+dp+t]=0u; sh_vs[key*56+dp+t]=0u; }
            }
        }
        __syncthreads();

        // ---- stage 1: S = Q K^T over 8 n-tiles (64 keys) ----
        float s[8][4];
        #pragma unroll
        for (int nt = 0; nt < 8; nt++)
            #pragma unroll
            for (int t = 0; t < 4; t++) s[nt][t] = 0.f;
        #pragma unroll
        for (int k8i = 0; k8i < 6; k8i++) {
            #pragma unroll
            for (int nt = 0; nt < 8; nt++) {
                unsigned bfr[2];
                int nb = (nt*8 + gid)*52 + k8i*8;
                bfr[0] = sh_ps[nb + tig];
                bfr[1] = sh_ps[nb + tig + 4];
                mma_tf32(s[nt], qfr[k8i], bfr);
            }
        }

        // ---- warp-local running softmax (rows gid / gid+8 of this warp's 16) ----
        float corr[2];
        int kbase = kt*64 + 2*tig;
        #pragma unroll
        for (int r = 0; r < 2; r++) {
            int i0 = 2*r;
            float mx = -1e30f;
            #pragma unroll
            for (int nt = 0; nt < 8; nt++) {
                int c0 = kbase + nt*8;
                float v0 = (c0   < L_) ? s[nt][i0  ]*SCALE_ : -1e30f;
                float v1 = (c0+1 < L_) ? s[nt][i0+1]*SCALE_ : -1e30f;
                s[nt][i0] = v0; s[nt][i0+1] = v1;
                mx = fmaxf(mx, fmaxf(v0, v1));
            }
            mx = fmaxf(mx, __shfl_xor_sync(0xffffffffu, mx, 1));
            mx = fmaxf(mx, __shfl_xor_sync(0xffffffffu, mx, 2));
            float mnew = fmaxf(m[r], mx);
            corr[r] = __expf(m[r] - mnew);
            m[r] = mnew;
            float lp = 0.f;
            #pragma unroll
            for (int nt = 0; nt < 8; nt++) {
                float p0 = __expf(s[nt][i0  ] - mnew);
                float p1 = __expf(s[nt][i0+1] - mnew);
                s[nt][i0] = p0; s[nt][i0+1] = p1;
                lp += p0 + p1;
            }
            lp += __shfl_xor_sync(0xffffffffu, lp, 1);
            lp += __shfl_xor_sync(0xffffffffu, lp, 2);
            lsum[r] = lsum[r]*corr[r] + lp;
        }

        __syncthreads();   // ALL warps done reading K tile; safe to overwrite with P

        // ---- store P (tf32) to warp-private rows of sh_ps[q][key], stride 68 ----
        {
            int r0 = qw + gid, r1 = r0 + 8;
            #pragma unroll
            for (int nt = 0; nt < 8; nt++) {
                int col = nt*8 + 2*tig;
                *(uint2*)&sh_ps[r0*68 + col] = make_uint2(f2tf(s[nt][0]), f2tf(s[nt][1]));
                *(uint2*)&sh_ps[r1*68 + col] = make_uint2(f2tf(s[nt][2]), f2tf(s[nt][3]));
            }
        }
        __syncwarp();

        // ---- rescale O frags, then stage 2: O += P V ----
        #pragma unroll
        for (int nt = 0; nt < 6; nt++) {
            o[nt][0] *= corr[0]; o[nt][1] *= corr[0];
            o[nt][2] *= corr[1]; o[nt][3] *= corr[1];
        }
        {
            int r0 = qw + gid, r1 = r0 + 8;
            #pragma unroll
            for (int k8i = 0; k8i < 8; k8i++) {
                int kk = k8i*8;
                unsigned afr[4];
                afr[0] = sh_ps[r0*68 + kk + tig];
                afr[1] = sh_ps[r1*68 + kk + tig];
                afr[2] = sh_ps[r0*68 + kk + tig + 4];
                afr[3] = sh_ps[r1*68 + kk + tig + 4];
                #pragma unroll
                for (int nt = 0; nt < 6; nt++) {
                    unsigned bfr[2];
                    bfr[0] = sh_vs[(kk + tig    )*56 + nt*8 + gid];
                    bfr[1] = sh_vs[(kk + tig + 4)*56 + nt*8 + gid];
                    mma_tf32(o[nt], afr, bfr);
                }
            }
        }
    }

    // ---- epilogue: normalize and scatter via the flat-reshape mapping ----
    {
        float inv0 = 1.f/lsum[0], inv1 = 1.f/lsum[1];
        int q0 = qt*128 + qw + gid, q1 = q0 + 8;
        float* xcb = g_xc + (size_t)b*L_*C_;
        #pragma unroll
        for (int nt = 0; nt < 6; nt++) {
            #pragma unroll
            for (int j = 0; j < 2; j++) {
                int d = nt*8 + 2*tig + j;
                int c = h*HD_ + d;
                if (q0 < L_) {
                    int flat = c*L_ + q0;
                    int lp2 = flat / C2_;
                    int cp  = flat - lp2*C2_;
                    xcb[(size_t)lp2*C_ + C2_ + cp] = o[nt][j]*inv0;
                }
                if (q1 < L_) {
                    int flat = c*L_ + q1;
                    int lp2 = flat / C2_;
                    int cp  = flat - lp2*C2_;
                    xcb[(size_t)lp2*C_ + C2_ + cp] = o[nt][j+2]*inv1;
                }
            }
        }
    }
}

// ---------------- stage 8a: t1 = gelu(dw3(xc)) with fused BN1 partials ----------------
__global__ void pjdw_kernel(const float* __restrict__ dww, const float* __restrict__ dwb) {
    int b = blockIdx.y, chunk = blockIdx.x;   // 8 x 8
    int c = threadIdx.x;                      // 768
    int l0 = chunk*125, l1 = min(l0+125, L_);
    float w0 = dww[c*3], w1 = dww[c*3+1], w2 = dww[c*3+2], bb = dwb[c];
    const float* xb = g_xc + (size_t)b*L_*C_ + c;
    float*       yb = g_t1 + (size_t)b*L_*C_ + c;
    float s = 0.f, s2 = 0.f;
    float xm1 = (l0 > 0) ? xb[(size_t)(l0-1)*C_] : 0.f;
    float x0  = xb[(size_t)l0*C_];
    for (int l = l0; l < l1; l++) {
        float xp1 = (l+1 < L_) ? xb[(size_t)(l+1)*C_] : 0.f;
        float v = gelu_f(xm1*w0 + x0*w1 + xp1*w2 + bb);
        yb[(size_t)l*C_] = v;
        s += v; s2 += v*v;
        xm1 = x0; x0 = xp1;
    }
    int blk = b*8 + chunk;
    g_ps [(size_t)blk*C_ + c] = s;
    g_ps2[(size_t)blk*C_ + c] = s2;
}

// ---------------- deterministic BN finalize: partials -> affine (a,b) ----------
__global__ void stats_finalize_kernel(int nblk, int Cch,
                                      const float* __restrict__ gam,
                                      const float* __restrict__ bet) {
    int c = blockIdx.x*blockDim.x + threadIdx.x;
    if (c >= Cch) return;
    double s = 0.0, s2 = 0.0;
    for (int i = 0; i < nblk; i++) { s += (double)g_ps[(size_t)i*Cch+c]; s2 += (double)g_ps2[(size_t)i*Cch+c]; }
    double mean = s / (double)M_;
    double var  = s2 / (double)M_ - mean*mean;
    if (var < 0.0) var = 0.0;
    float rs = (float)(1.0 / sqrt(var + (double)EPS_));
    float a  = gam[c]*rs;
    g_an[c] = a;
    g_bn[c] = bet[c] - (float)mean*a;
}

// ---------------- final: out = bn3(t3) + xc ----------------
__global__ void final_add_kernel(float* __restrict__ out) {
    int idx4 = blockIdx.x*blockDim.x + threadIdx.x;
    if (idx4 >= M_*C_/4) return;
    int idx = idx4*4;
    int c = idx % C_;
    float4 t = *(const float4*)(g_t3 + idx);
    float4 xv= *(const float4*)(g_xc + idx);
    float4 a = *(const float4*)(g_an + c);
    float4 bb= *(const float4*)(g_bn + c);
    float4 r;
    r.x = t.x*a.x + bb.x + xv.x;
    r.y = t.y*a.y + bb.y + xv.y;
    r.z = t.z*a.z + bb.z + xv.z;
    r.w = t.w*a.w + bb.w + xv.w;
    *(float4*)(out + idx) = r;
}

// =======================================================================================
extern "C" void kernel_launch(void* const* d_in, const int* in_sizes, int n_in,
                              void* d_out, int out_size) {
    const float* x        = (const float*)d_in[0];
    const float* dc_weight= (const float*)d_in[1];
    const float* dc_bias  = (const float*)d_in[2];
    const float* dc_p1w   = (const float*)d_in[3];
    const float* dc_p1b   = (const float*)d_in[4];
    const float* dc_p2w   = (const float*)d_in[5];
    const float* dc_p2b   = (const float*)d_in[6];
    const float* at_qw    = (const float*)d_in[7];
    const float* at_qb    = (const float*)d_in[8];
    const float* at_kvw   = (const float*)d_in[9];
    const float* at_kvb   = (const float*)d_in[10];
    const float* at_lcw   = (const float*)d_in[11];
    const float* at_lcb   = (const float*)d_in[12];
    const float* pj_dww   = (const float*)d_in[13];
    const float* pj_dwb   = (const float*)d_in[14];
    const float* pj_bn1g  = (const float*)d_in[15];
    const float* pj_bn1b  = (const float*)d_in[16];
    const float* pj_c1w   = (const float*)d_in[17];
    const float* pj_c1b   = (const float*)d_in[18];
    const float* pj_bn2g  = (const float*)d_in[19];
    const float* pj_bn2b  = (const float*)d_in[20];
    const float* pj_c2w   = (const float*)d_in[21];
    const float* pj_c2b   = (const float*)d_in[22];
    const float* pj_bn3g  = (const float*)d_in[23];
    const float* pj_bn3b  = (const float*)d_in[24];
    float* out = (float*)d_out;

    float *pq, *pkvin, *pkv, *pt1, *pt2, *pt3, *pan, *pbn, *pps, *pps2;
    cudaGetSymbolAddress((void**)&pq,    g_q);
    cudaGetSymbolAddress((void**)&pkvin, g_kvin);
    cudaGetSymbolAddress((void**)&pkv,   g_kv);
    cudaGetSymbolAddress((void**)&pt1,   g_t1);
    cudaGetSymbolAddress((void**)&pt2,   g_t2);
    cudaGetSymbolAddress((void**)&pt3,   g_t3);
    cudaGetSymbolAddress((void**)&pan,   g_an);
    cudaGetSymbolAddress((void**)&pbn,   g_bn);
    cudaGetSymbolAddress((void**)&pps,   g_ps);
    cudaGetSymbolAddress((void**)&pps2,  g_ps2);

    // ---- branch 1: dynamic conv scores ----
    pooled_kernel<<<96, C2_>>>(x);
    dcmlp_kernel<<<B_, C2_>>>(dc_p1w, dc_p1b, dc_p2w, dc_p2b, dc_weight, dc_bias);
    // ---- dconv + kvin (merged) ----
    dckv_kernel<<<dim3(125, B_), 768>>>(x, at_lcw, at_lcb);

    // ---- attention: merged q + kv projection, then flash attention ----
    qkv_kernel<<<dim3(63, 9), 256>>>(x, at_qw, at_qb, at_kvw, at_kvb);
    attn_kernel<<<dim3(8, H_, B_), 256>>>();

    // ---- projection: dw3 + gelu with fused BN1 partials ----
    pjdw_kernel<<<dim3(8, B_), C_>>>(pj_dww, pj_dwb);
    stats_finalize_kernel<<<3, 256>>>(64, C_, pj_bn1g, pj_bn1b);

    // ---- c1 (bn1 folded into A) + gelu + fused BN2 partials ----
    gemm_kernel<<<dim3(63, 1), 256>>>(pt1, C_, pj_c1w, pj_c1b,
                                      pt2, PJIN_, M_, PJIN_, C_, pan, pbn, 1, pps, pps2);
    stats_finalize_kernel<<<1, 256>>>(63, PJIN_, pj_bn2g, pj_bn2b);

    // ---- c2 (bn2 folded into A) + fused BN3 partials ----
    gemm_kernel<<<dim3(63, 6), 256>>>(pt2, PJIN_, pj_c2w, pj_c2b,
                                      pt3, C_, M_, C_, PJIN_, pan, pbn, 0, pps, pps2);
    stats_finalize_kernel<<<3, 256>>>(63, C_, pj_bn3g, pj_bn3b);

    // ---- bn3 + residual ----
    final_add_kernel<<<(M_*C_/4 + 255)/256, 256>>>(out);
}

// round 16
// speedup vs baseline: 2.7773x; 1.0728x over previous
#include <cuda_runtime.h>
#include <math.h>

#define B_    8
#define L_    999
#define C_    768
#define C2_   384
#define H_    8
#define HD_   48
#define K_    3
#define DCIN_ 96
#define PJIN_ 96
#define M_    (B_*L_)          /* 7992 tokens */
#define SCALE_ 0.14433756729740643f
#define EPS_   1e-5f

__device__ __forceinline__ float gelu_f(float v) {
    return 0.5f * v * (1.0f + erff(v * 0.7071067811865475f));
}

// ---- tf32 mma helpers (validated R7/R8) ----
__device__ __forceinline__ unsigned f2tf(float f) {
    unsigned r; asm("cvt.rna.tf32.f32 %0, %1;" : "=r"(r) : "f"(f)); return r;
}
__device__ __forceinline__ void mma_tf32(float* c, const unsigned* a, const unsigned* b) {
    asm volatile("mma.sync.aligned.m16n8k8.row.col.f32.tf32.tf32.f32 "
                 "{%0,%1,%2,%3}, {%4,%5,%6,%7}, {%8,%9}, {%0,%1,%2,%3};"
                 : "+f"(c[0]), "+f"(c[1]), "+f"(c[2]), "+f"(c[3])
                 : "r"(a[0]), "r"(a[1]), "r"(a[2]), "r"(a[3]),
                   "r"(b[0]), "r"(b[1]));
}
// ---- bf16 helpers (attention) ----
__device__ __forceinline__ unsigned pkbf(float lo, float hi) {
    unsigned r; asm("cvt.rn.bf16x2.f32 %0, %1, %2;" : "=r"(r) : "f"(hi), "f"(lo)); return r;
}
__device__ __forceinline__ void mma_bf16(float* c, const unsigned* a, const unsigned* b) {
    asm volatile("mma.sync.aligned.m16n8k16.row.col.f32.bf16.bf16.f32 "
                 "{%0,%1,%2,%3}, {%4,%5,%6,%7}, {%8,%9}, {%0,%1,%2,%3};"
                 : "+f"(c[0]), "+f"(c[1]), "+f"(c[2]), "+f"(c[3])
                 : "r"(a[0]), "r"(a[1]), "r"(a[2]), "r"(a[3]),
                   "r"(b[0]), "r"(b[1]));
}

// ---------------- scratch (device globals; no allocation allowed) ----------------
__device__ float g_q    [(size_t)M_*C2_];
__device__ float g_kvin [(size_t)M_*C2_];
__device__ float g_kv   [(size_t)M_*C_];
__device__ float g_xc   [(size_t)M_*C_];
__device__ float g_t1   [(size_t)M_*C_];
__device__ float g_t2   [(size_t)M_*PJIN_];
__device__ float g_t3   [(size_t)M_*C_];
__device__ float g_wdyn [B_*C2_*K_];
__device__ float g_bdyn [B_*C2_];
__device__ float g_ps   [128*C_];
__device__ float g_ps2  [128*C_];
__device__ float g_an   [C_];
__device__ float g_bn   [C_];

// ---------------- stage 1: pooled partial sums (4-way split over rows) ----------------
__global__ void pooled_kernel(const float* __restrict__ x) {
    int blk = blockIdx.x;            // (b*3+kk)*4+sub
    int sub = blk & 3;
    int bk  = blk >> 2;
    int b   = bk / K_;
    int kk  = bk % K_;
    int c   = threadIdx.x;           // 384
    int r0 = kk*333 + sub*84;
    int r1 = kk*333 + min(sub*84 + 84, 333);
    const float* xb = x + (size_t)b*L_*C_ + c;
    float s = 0.f;
    for (int l = r0; l < r1; l++) s += xb[(size_t)l*C_];
    g_ps[(size_t)blk*C2_ + c] = s;
}

// ---------------- stage 2: dynamic-conv score MLP + softmax over G ----------------
__global__ void dcmlp_kernel(const float* __restrict__ p1w, const float* __restrict__ p1b,
                             const float* __restrict__ p2w, const float* __restrict__ p2b,
                             const float* __restrict__ dcw, const float* __restrict__ dcb) {
    int b   = blockIdx.x;
    int tid = threadIdx.x;                 // 384
    __shared__ float col[4][C2_];
    __shared__ float hid[4][DCIN_];
    __shared__ float sc [4][2*C2_];
    {
        float cc[3];
        #pragma unroll
        for (int kk = 0; kk < 3; kk++) {
            int base = (b*3+kk)*4;
            cc[kk] = (g_ps[(size_t)(base+0)*C2_+tid] + g_ps[(size_t)(base+1)*C2_+tid]
                    + g_ps[(size_t)(base+2)*C2_+tid] + g_ps[(size_t)(base+3)*C2_+tid]) * (1.0f/333.0f);
            col[kk][tid] = cc[kk];
        }
        col[3][tid] = (cc[0]+cc[1]+cc[2]) * (1.0f/3.0f);
    }
    __syncthreads();
    {
        int kk = tid / DCIN_;
        int i  = tid % DCIN_;
        float s = p1b[i];
        const float* wr = p1w + (size_t)i*C2_;
        #pragma unroll 8
        for (int c = 0; c < C2_; c++) s += wr[c]*col[kk][c];
        hid[kk][i] = gelu_f(s);
    }
    __syncthreads();
    for (int t = tid; t < 4*768; t += 384) {
        int kk = t / 768, o = t % 768;
        float s = p2b[o];
        const float* wr = p2w + (size_t)o*DCIN_;
        #pragma unroll 8
        for (int i = 0; i < DCIN_; i++) s += wr[i]*hid[kk][i];
        sc[kk][o] = s;
    }
    __syncthreads();
    {
        int c = tid;
        #pragma unroll
        for (int kk = 0; kk < 3; kk++) {
            float e0 = sc[kk][c], e1 = sc[kk][C2_+c];
            float mx = fmaxf(e0,e1);
            float a0 = expf(e0-mx), a1 = expf(e1-mx);
            float inv = 1.f/(a0+a1);
            g_wdyn[(b*C2_+c)*3+kk] = (a0*dcw[c*3+kk] + a1*dcw[(C2_+c)*3+kk])*inv;
        }
        float e0 = sc[3][c], e1 = sc[3][C2_+c];
        float mx = fmaxf(e0,e1);
        float a0 = expf(e0-mx), a1 = expf(e1-mx);
        g_bdyn[b*C2_+c] = (a0*dcb[c] + a1*dcb[C2_+c])/(a0+a1);
    }
}

// ---------------- stage 3+4 merged: dynamic depthwise conv + kv_in ----------------
__global__ void dckv_kernel(const float* __restrict__ x,
                            const float* __restrict__ lcw, const float* __restrict__ lcb) {
    int b  = blockIdx.y;
    int tid = threadIdx.x;                 // 768: li 0..7, c4 0..95
    int l  = blockIdx.x*8 + (tid/96);
    int c  = (tid%96)*4;
    if (l >= L_) return;
    float4 zero = make_float4(0.f,0.f,0.f,0.f);
    {   // ---- dconv: x[:, :, c] -> xc[:, :, c] ----
        const float* wp = g_wdyn + ((size_t)b*C2_ + c)*3;
        float4 wA = *(const float4*)(wp);
        float4 wB = *(const float4*)(wp+4);
        float4 wC = *(const float4*)(wp+8);
        float4 bv = *(const float4*)(g_bdyn + (size_t)b*C2_ + c);
        const float* xb = x + ((size_t)b*L_ + l)*C_ + c;
        float4 xm = (l > 0)      ? *(const float4*)(xb - C_) : zero;
        float4 x0 = *(const float4*)(xb);
        float4 xp = (l+1 < L_)   ? *(const float4*)(xb + C_) : zero;
        float4 r;
        r.x = xm.x*wA.x + x0.x*wA.y + xp.x*wA.z + bv.x;
        r.y = xm.y*wA.w + x0.y*wB.x + xp.y*wB.y + bv.y;
        r.z = xm.z*wB.z + x0.z*wB.w + xp.z*wC.x + bv.z;
        r.w = xm.w*wC.y + x0.w*wC.z + xp.w*wC.w + bv.w;
        *(float4*)(g_xc + ((size_t)b*L_ + l)*C_ + c) = r;
    }
    {   // ---- kvin: x[:, :, C2+c] -> kvin[:, :, c] ----
        const float* wp = lcw + (size_t)c*3;
        float4 wA = *(const float4*)(wp);
        float4 wB = *(const float4*)(wp+4);
        float4 wC = *(const float4*)(wp+8);
        float4 bv = *(const float4*)(lcb + c);
        const float* xb = x + ((size_t)b*L_ + l)*C_ + C2_ + c;
        float4 xm = (l > 0)      ? *(const float4*)(xb - C_) : zero;
        float4 x0 = *(const float4*)(xb);
        float4 xp = (l+1 < L_)   ? *(const float4*)(xb + C_) : zero;
        float4 r;
        r.x = xm.x*wA.x + x0.x*wA.y + xp.x*wA.z + bv.x + x0.x;
        r.y = xm.y*wA.w + x0.y*wB.x + xp.y*wB.y + bv.y + x0.y;
        r.z = xm.z*wB.z + x0.z*wB.w + xp.z*wC.x + bv.z + x0.z;
        r.w = xm.w*wC.y + x0.w*wC.z + xp.w*wC.w + bv.w + x0.w;
        *(float4*)(g_kvin + ((size_t)b*L_ + l)*C2_ + c) = r;
    }
}

// ---------------- GEMM body v8: 128x128 block, 32x64 warp tile, double-buffered --------
__device__ __forceinline__ void
gemm_body(unsigned* As, unsigned* Ws, float* sred,
          const float* __restrict__ A, int lda,
          const float* __restrict__ W,
          const float* __restrict__ bias,
          float* __restrict__ Cmat, int ldc,
          int M, int N, int Kd,
          const float* __restrict__ ascale,
          const float* __restrict__ ashift,
          int dogelu,
          float* __restrict__ ps, float* __restrict__ ps2,
          int blkx, int blky)
{
    int tid  = threadIdx.x;                // 256 = 8 warps
    int wid  = tid >> 5, lane = tid & 31;
    int gid  = lane >> 2, tig = lane & 3;
    int m0 = blkx*128, n0 = blky*128;
    int mw = (wid >> 1) * 32;              // 0/32/64/96
    int nw = (wid & 1) * 64;               // 0/64

    float acc[2][8][4];
    #pragma unroll
    for (int i = 0; i < 2; i++)
        #pragma unroll
        for (int j = 0; j < 8; j++)
            #pragma unroll
            for (int t = 0; t < 4; t++) acc[i][j][t] = 0.f;

    int lr = tid >> 1, lk = (tid & 1) << 3;
    float4 zero = make_float4(0.f,0.f,0.f,0.f);
    float4 a0, a1, w0, w1;

    auto loadc = [&](int k0) {
        a0 = zero; a1 = zero; w0 = zero; w1 = zero;
        int gm = m0 + lr;
        if (gm < M) {
            const float* ap = A + (size_t)gm*lda + k0 + lk;
            a0 = *(const float4*)(ap);
            a1 = *(const float4*)(ap+4);
        }
        if (ascale) {
            int kb = k0 + lk;
            a0.x = a0.x*ascale[kb+0] + ashift[kb+0];
            a0.y = a0.y*ascale[kb+1] + ashift[kb+1];
            a0.z = a0.z*ascale[kb+2] + ashift[kb+2];
            a0.w = a0.w*ascale[kb+3] + ashift[kb+3];
            a1.x = a1.x*ascale[kb+4] + ashift[kb+4];
            a1.y = a1.y*ascale[kb+5] + ashift[kb+5];
            a1.z = a1.z*ascale[kb+6] + ashift[kb+6];
            a1.w = a1.w*ascale[kb+7] + ashift[kb+7];
        }
        int gn = n0 + lr;
        if (gn < N) {
            const float* wptr = W + (size_t)gn*Kd + k0 + lk;
            w0 = *(const float4*)(wptr);
            w1 = *(const float4*)(wptr+4);
        }
    };
    auto storec = [&](int st) {
        unsigned* Ar = As + ((size_t)st*128 + lr)*20 + lk;
        Ar[0]=f2tf(a0.x); Ar[1]=f2tf(a0.y); Ar[2]=f2tf(a0.z); Ar[3]=f2tf(a0.w);
        Ar[4]=f2tf(a1.x); Ar[5]=f2tf(a1.y); Ar[6]=f2tf(a1.z); Ar[7]=f2tf(a1.w);
        unsigned* Wr = Ws + ((size_t)st*128 + lr)*20 + lk;
        Wr[0]=f2tf(w0.x); Wr[1]=f2tf(w0.y); Wr[2]=f2tf(w0.z); Wr[3]=f2tf(w0.w);
        Wr[4]=f2tf(w1.x); Wr[5]=f2tf(w1.y); Wr[6]=f2tf(w1.z); Wr[7]=f2tf(w1.w);
    };

    int nk = Kd >> 4;
    loadc(0);
    storec(0);
    __syncthreads();

    for (int i = 0; i < nk; i++) {
        int buf = i & 1;
        if (i+1 < nk) loadc((i+1) << 4);
        const unsigned* Ab = As + (size_t)buf*128*20;
        const unsigned* Wb = Ws + (size_t)buf*128*20;
        #pragma unroll
        for (int k8 = 0; k8 < 16; k8 += 8) {
            #pragma unroll
            for (int mt = 0; mt < 2; mt++) {
                int mb = mw + mt*16 + gid;
                unsigned afr[4];
                afr[0] = Ab[mb*20     + k8 + tig];
                afr[1] = Ab[(mb+8)*20 + k8 + tig];
                afr[2] = Ab[mb*20     + k8 + 4 + tig];
                afr[3] = Ab[(mb+8)*20 + k8 + 4 + tig];
                #pragma unroll
                for (int nt = 0; nt < 8; nt++) {
                    unsigned bfr[2];
                    int nb = nw + nt*8 + gid;
                    bfr[0] = Wb[nb*20 + k8 + tig];
                    bfr[1] = Wb[nb*20 + k8 + 4 + tig];
                    mma_tf32(acc[mt][nt], afr, bfr);
                }
            }
        }
        if (i+1 < nk) {
            storec(buf ^ 1);
            __syncthreads();
        }
    }

    #pragma unroll
    for (int mt = 0; mt < 2; mt++) {
        #pragma unroll
        for (int nt = 0; nt < 8; nt++) {
            int gn = n0 + nw + nt*8 + 2*tig;
            if (gn < N) {
                float b0v = bias[gn], b1v = bias[gn+1];
                acc[mt][nt][0] += b0v; acc[mt][nt][1] += b1v;
                acc[mt][nt][2] += b0v; acc[mt][nt][3] += b1v;
                if (dogelu) {
                    acc[mt][nt][0] = gelu_f(acc[mt][nt][0]);
                    acc[mt][nt][1] = gelu_f(acc[mt][nt][1]);
                    acc[mt][nt][2] = gelu_f(acc[mt][nt][2]);
                    acc[mt][nt][3] = gelu_f(acc[mt][nt][3]);
                }
                int gm0 = m0 + mw + mt*16 + gid;
                if (gm0 < M)
                    *(float2*)(Cmat + (size_t)gm0*ldc + gn) = make_float2(acc[mt][nt][0], acc[mt][nt][1]);
                int gm1 = gm0 + 8;
                if (gm1 < M)
                    *(float2*)(Cmat + (size_t)gm1*ldc + gn) = make_float2(acc[mt][nt][2], acc[mt][nt][3]);
            } else {
                acc[mt][nt][0]=0.f; acc[mt][nt][1]=0.f; acc[mt][nt][2]=0.f; acc[mt][nt][3]=0.f;
            }
        }
    }

    if (ps) {
        #pragma unroll
        for (int nt = 0; nt < 8; nt++) {
            #pragma unroll
            for (int j = 0; j < 2; j++) {
                float s = 0.f, s2 = 0.f;
                #pragma unroll
                for (int mt = 0; mt < 2; mt++) {
                    int gm0 = m0 + mw + mt*16 + gid;
                    if (gm0 < M)     { float t = acc[mt][nt][j];   s += t; s2 += t*t; }
                    if (gm0 + 8 < M) { float t = acc[mt][nt][j+2]; s += t; s2 += t*t; }
                }
                s  += __shfl_xor_sync(0xffffffffu, s,  4);
                s  += __shfl_xor_sync(0xffffffffu, s,  8);
                s  += __shfl_xor_sync(0xffffffffu, s, 16);
                s2 += __shfl_xor_sync(0xffffffffu, s2,  4);
                s2 += __shfl_xor_sync(0xffffffffu, s2,  8);
                s2 += __shfl_xor_sync(0xffffffffu, s2, 16);
                if (gid == 0) {
                    int colw = nt*8 + 2*tig + j;
                    sred[(wid*64 + colw)*2 + 0] = s;
                    sred[(wid*64 + colw)*2 + 1] = s2;
                }
            }
        }
        __syncthreads();
        if (tid < 256) {
            int g   = tid >> 7;
            int col = (tid >> 1) & 63;
            int q   = tid & 1;
            float t = sred[((g  )*64 + col)*2 + q] + sred[((g+2)*64 + col)*2 + q]
                    + sred[((g+4)*64 + col)*2 + q] + sred[((g+6)*64 + col)*2 + q];
            int gn = n0 + g*64 + col;
            if (gn < N) {
                float* dst = q ? ps2 : ps;
                dst[(size_t)blkx*N + gn] = t;
            }
        }
    }
}

// ---------------- generic GEMM wrapper ----------------
__global__ void __launch_bounds__(256, 2)
gemm_kernel(const float* __restrict__ A, int lda,
            const float* __restrict__ W,
            const float* __restrict__ bias,
            float* __restrict__ Cmat, int ldc,
            int M, int N, int Kd,
            const float* __restrict__ ascale,
            const float* __restrict__ ashift,
            int dogelu,
            float* __restrict__ ps, float* __restrict__ ps2)
{
    __shared__ unsigned As[2*128*20];
    __shared__ unsigned Ws[2*128*20];
    __shared__ float sred[8*64*2];
    gemm_body(As, Ws, sred, A, lda, W, bias, Cmat, ldc, M, N, Kd,
              ascale, ashift, dogelu, ps, ps2, blockIdx.x, blockIdx.y);
}

// ---------------- merged q + kv projection GEMM (one launch) --------
__global__ void __launch_bounds__(256, 2)
qkv_kernel(const float* __restrict__ x,
           const float* __restrict__ qw,  const float* __restrict__ qb,
           const float* __restrict__ kvw, const float* __restrict__ kvb)
{
    __shared__ unsigned As[2*128*20];
    __shared__ unsigned Ws[2*128*20];
    __shared__ float sred[8*64*2];
    if (blockIdx.y < 3) {
        gemm_body(As, Ws, sred, x + C2_, C_, qw, qb, g_q, C2_, M_, C2_, C2_,
                  nullptr, nullptr, 0, nullptr, nullptr, blockIdx.x, blockIdx.y);
    } else {
        gemm_body(As, Ws, sred, g_kvin, C2_, kvw, kvb, g_kv, C_, M_, C_, C2_,
                  nullptr, nullptr, 0, nullptr, nullptr, blockIdx.x, blockIdx.y - 3);
    }
}

// ---------------- stage 7: flash attention v5 (bf16 mma, P in registers) ----------------
// Block: 128 q-rows, 8 warps; warp = private 16-row q-group over 64-key tiles.
// bf16 m16n8k16: S C-fragments convert DIRECTLY into stage-2 A-fragments (packed
// consecutive-key pairs), so P needs no smem and no extra barrier.
// Output reproduces the reference transpose+flat-reshape reinterpretation:
// (c = h*HD+d, l) -> flat = c*L + l -> xc[b, flat/C2, C2 + flat%C2].
__global__ void __launch_bounds__(256, 2) attn_kernel() {
    __shared__ unsigned sh_q[128*28];   // Q bf16 pairs [row][dpair]   14336 B
    __shared__ unsigned sh_k[64*28];    // K bf16 pairs [key][dpair]    7168 B
    __shared__ unsigned sh_v[48*36];    // V bf16 pairs [d][keypair]    6912 B
    int qt = blockIdx.x;                // 8 q tiles of 128
    int h  = blockIdx.y;
    int b  = blockIdx.z;
    int tid = threadIdx.x;              // 256
    int lane = tid & 31;
    int gid = lane >> 2, tig = lane & 3;
    int qw  = (tid >> 5) * 16;

    const float* qb = g_q  + (size_t)b*L_*C2_ + h*HD_;
    const float* kb = g_kv + (size_t)b*L_*C_  + h*HD_;
    const float* vb = kb + C2_;

    // ---- Q staging (bf16 pairs along d) ----
    {
        int row = tid >> 1, dh = (tid & 1)*24;
        int gl = qt*128 + row;
        unsigned* qr = sh_q + row*28 + (tid & 1)*12;
        if (gl < L_) {
            #pragma unroll
            for (int t = 0; t < 6; t++) {
                float4 v = *(const float4*)(qb + (size_t)gl*C2_ + dh + t*4);
                qr[t*2+0] = pkbf(v.x, v.y);
                qr[t*2+1] = pkbf(v.z, v.w);
            }
        } else {
            #pragma unroll
            for (int t = 0; t < 12; t++) qr[t] = 0u;
        }
    }
    __syncthreads();
    // ---- Q A-fragments resident in registers (3 k16 blocks over d=48) ----
    unsigned qfr[3][4];
    {
        int r0 = qw + gid, r1 = r0 + 8;
        #pragma unroll
        for (int i = 0; i < 3; i++) {
            qfr[i][0] = sh_q[r0*28 + i*8 + tig];
            qfr[i][1] = sh_q[r1*28 + i*8 + tig];
            qfr[i][2] = sh_q[r0*28 + i*8 + 4 + tig];
            qfr[i][3] = sh_q[r1*28 + i*8 + 4 + tig];
        }
    }

    float m[2]    = {-1e30f, -1e30f};
    float lsum[2] = {0.f, 0.f};
    float o[6][4];
    #pragma unroll
    for (int nt = 0; nt < 6; nt++)
        #pragma unroll
        for (int t = 0; t < 4; t++) o[nt][t] = 0.f;

    for (int kt = 0; kt < 16; kt++) {
        __syncthreads();   // prior stage1/2 reads of sh_k / sh_v complete
        {   // ---- K staging: key = tid>>2, 12 d per thread -> 6 packed ----
            int key = tid >> 2, dp = (tid & 3)*12;
            int gl = kt*64 + key;
            unsigned* kr = sh_k + key*28 + (tid & 3)*6;
            if (gl < L_) {
                #pragma unroll
                for (int t = 0; t < 3; t++) {
                    float4 kv = *(const float4*)(kb + (size_t)gl*C_ + dp + t*4);
                    kr[t*2+0] = pkbf(kv.x, kv.y);
                    kr[t*2+1] = pkbf(kv.z, kv.w);
                }
            } else {
                #pragma unroll
                for (int t = 0; t < 6; t++) kr[t] = 0u;
            }
        }
        if (tid < 192) {   // ---- V staging: key-pair kp, 8 d per thread ----
            int dblk = tid >> 5, kp = tid & 31;
            int gl0 = kt*64 + 2*kp, gl1 = gl0 + 1;
            int d0 = dblk*8;
            float4 v0a = make_float4(0.f,0.f,0.f,0.f), v0b = v0a, v1a = v0a, v1b = v0a;
            if (gl0 < L_) {
                v0a = *(const float4*)(vb + (size_t)gl0*C_ + d0);
                v0b = *(const float4*)(vb + (size_t)gl0*C_ + d0 + 4);
            }
            if (gl1 < L_) {
                v1a = *(const float4*)(vb + (size_t)gl1*C_ + d0);
                v1b = *(const float4*)(vb + (size_t)gl1*C_ + d0 + 4);
            }
            sh_v[(d0+0)*36 + kp] = pkbf(v0a.x, v1a.x);
            sh_v[(d0+1)*36 + kp] = pkbf(v0a.y, v1a.y);
            sh_v[(d0+2)*36 + kp] = pkbf(v0a.z, v1a.z);
            sh_v[(d0+3)*36 + kp] = pkbf(v0a.w, v1a.w);
            sh_v[(d0+4)*36 + kp] = pkbf(v0b.x, v1b.x);
            sh_v[(d0+5)*36 + kp] = pkbf(v0b.y, v1b.y);
            sh_v[(d0+6)*36 + kp] = pkbf(v0b.z, v1b.z);
            sh_v[(d0+7)*36 + kp] = pkbf(v0b.w, v1b.w);
        }
        __syncthreads();

        // ---- stage 1: S = Q K^T (3 k16 blocks x 8 n-tiles) ----
        float s[8][4];
        #pragma unroll
        for (int nt = 0; nt < 8; nt++)
            #pragma unroll
            for (int t = 0; t < 4; t++) s[nt][t] = 0.f;
        #pragma unroll
        for (int i = 0; i < 3; i++) {
            #pragma unroll
            for (int nt = 0; nt < 8; nt++) {
                unsigned bfr[2];
                int nb = (nt*8 + gid)*28 + i*8;
                bfr[0] = sh_k[nb + tig];
                bfr[1] = sh_k[nb + 4 + tig];
                mma_bf16(s[nt], qfr[i], bfr);
            }
        }

        // ---- warp-local running softmax (rows gid / gid+8) ----
        float corr[2];
        int kbase = kt*64 + 2*tig;
        #pragma unroll
        for (int r = 0; r < 2; r++) {
            int i0 = 2*r;
            float mx = -1e30f;
            #pragma unroll
            for (int nt = 0; nt < 8; nt++) {
                int c0 = kbase + nt*8;
                float v0 = (c0   < L_) ? s[nt][i0  ]*SCALE_ : -1e30f;
                float v1 = (c0+1 < L_) ? s[nt][i0+1]*SCALE_ : -1e30f;
                s[nt][i0] = v0; s[nt][i0+1] = v1;
                mx = fmaxf(mx, fmaxf(v0, v1));
            }
            mx = fmaxf(mx, __shfl_xor_sync(0xffffffffu, mx, 1));
            mx = fmaxf(mx, __shfl_xor_sync(0xffffffffu, mx, 2));
            float mnew = fmaxf(m[r], mx);
            corr[r] = __expf(m[r] - mnew);
            m[r] = mnew;
            float lp = 0.f;
            #pragma unroll
            for (int nt = 0; nt < 8; nt++) {
                float p0 = __expf(s[nt][i0  ] - mnew);
                float p1 = __expf(s[nt][i0+1] - mnew);
                s[nt][i0] = p0; s[nt][i0+1] = p1;
                lp += p0 + p1;
            }
            lp += __shfl_xor_sync(0xffffffffu, lp, 1);
            lp += __shfl_xor_sync(0xffffffffu, lp, 2);
            lsum[r] = lsum[r]*corr[r] + lp;
        }

        // ---- rescale O frags, then stage 2: O += P V (P frags direct from s) ----
        #pragma unroll
        for (int nt = 0; nt < 6; nt++) {
            o[nt][0] *= corr[0]; o[nt][1] *= corr[0];
            o[nt][2] *= corr[1]; o[nt][3] *= corr[1];
        }
        #pragma unroll
        for (int j = 0; j < 4; j++) {          // k16 blocks over 64 keys
            unsigned afr[4];
            afr[0] = pkbf(s[2*j  ][0], s[2*j  ][1]);
            afr[1] = pkbf(s[2*j  ][2], s[2*j  ][3]);
            afr[2] = pkbf(s[2*j+1][0], s[2*j+1][1]);
            afr[3] = pkbf(s[2*j+1][2], s[2*j+1][3]);
            #pragma unroll
            for (int nt = 0; nt < 6; nt++) {
                unsigned bfr[2];
                int nb = (nt*8 + gid)*36 + j*8;
                bfr[0] = sh_v[nb + tig];
                bfr[1] = sh_v[nb + 4 + tig];
                mma_bf16(o[nt], afr, bfr);
            }
        }
    }

    // ---- epilogue: normalize and scatter via the flat-reshape mapping ----
    {
        float inv0 = 1.f/lsum[0], inv1 = 1.f/lsum[1];
        int q0 = qt*128 + qw + gid, q1 = q0 + 8;
        float* xcb = g_xc + (size_t)b*L_*C_;
        #pragma unroll
        for (int nt = 0; nt < 6; nt++) {
            #pragma unroll
            for (int j = 0; j < 2; j++) {
                int d = nt*8 + 2*tig + j;
                int c = h*HD_ + d;
                if (q0 < L_) {
                    int flat = c*L_ + q0;
                    int lp2 = flat / C2_;
                    int cp  = flat - lp2*C2_;
                    xcb[(size_t)lp2*C_ + C2_ + cp] = o[nt][j]*inv0;
                }
                if (q1 < L_) {
                    int flat = c*L_ + q1;
                    int lp2 = flat / C2_;
                    int cp  = flat - lp2*C2_;
                    xcb[(size_t)lp2*C_ + C2_ + cp] = o[nt][j+2]*inv1;
                }
            }
        }
    }
}

// ---------------- stage 8a: t1 = gelu(dw3(xc)) with fused BN1 partials ----------------
__global__ void pjdw_kernel(const float* __restrict__ dww, const float* __restrict__ dwb) {
    int b = blockIdx.y, chunk = blockIdx.x;   // 8 x 8
    int c = threadIdx.x;                      // 768
    int l0 = chunk*125, l1 = min(l0+125, L_);
    float w0 = dww[c*3], w1 = dww[c*3+1], w2 = dww[c*3+2], bb = dwb[c];
    const float* xb = g_xc + (size_t)b*L_*C_ + c;
    float*       yb = g_t1 + (size_t)b*L_*C_ + c;
    float s = 0.f, s2 = 0.f;
    float xm1 = (l0 > 0) ? xb[(size_t)(l0-1)*C_] : 0.f;
    float x0  = xb[(size_t)l0*C_];
    for (int l = l0; l < l1; l++) {
        float xp1 = (l+1 < L_) ? xb[(size_t)(l+1)*C_] : 0.f;
        float v = gelu_f(xm1*w0 + x0*w1 + xp1*w2 + bb);
        yb[(size_t)l*C_] = v;
        s += v; s2 += v*v;
        xm1 = x0; x0 = xp1;
    }
    int blk = b*8 + chunk;
    g_ps [(size_t)blk*C_ + c] = s;
    g_ps2[(size_t)blk*C_ + c] = s2;
}

// ---------------- deterministic BN finalize: partials -> affine (a,b) ----------
__global__ void stats_finalize_kernel(int nblk, int Cch,
                                      const float* __restrict__ gam,
                                      const float* __restrict__ bet) {
    int c = blockIdx.x*blockDim.x + threadIdx.x;
    if (c >= Cch) return;
    double s = 0.0, s2 = 0.0;
    for (int i = 0; i < nblk; i++) { s += (double)g_ps[(size_t)i*Cch+c]; s2 += (double)g_ps2[(size_t)i*Cch+c]; }
    double mean = s / (double)M_;
    double var  = s2 / (double)M_ - mean*mean;
    if (var < 0.0) var = 0.0;
    float rs = (float)(1.0 / sqrt(var + (double)EPS_));
    float a  = gam[c]*rs;
    g_an[c] = a;
    g_bn[c] = bet[c] - (float)mean*a;
}

// ---------------- final: out = bn3(t3) + xc ----------------
__global__ void final_add_kernel(float* __restrict__ out) {
    int idx4 = blockIdx.x*blockDim.x + threadIdx.x;
    if (idx4 >= M_*C_/4) return;
    int idx = idx4*4;
    int c = idx % C_;
    float4 t = *(const float4*)(g_t3 + idx);
    float4 xv= *(const float4*)(g_xc + idx);
    float4 a = *(const float4*)(g_an + c);
    float4 bb= *(const float4*)(g_bn + c);
    float4 r;
    r.x = t.x*a.x + bb.x + xv.x;
    r.y = t.y*a.y + bb.y + xv.y;
    r.z = t.z*a.z + bb.z + xv.z;
    r.w = t.w*a.w + bb.w + xv.w;
    *(float4*)(out + idx) = r;
}

// =======================================================================================
extern "C" void kernel_launch(void* const* d_in, const int* in_sizes, int n_in,
                              void* d_out, int out_size) {
    const float* x        = (const float*)d_in[0];
    const float* dc_weight= (const float*)d_in[1];
    const float* dc_bias  = (const float*)d_in[2];
    const float* dc_p1w   = (const float*)d_in[3];
    const float* dc_p1b   = (const float*)d_in[4];
    const float* dc_p2w   = (const float*)d_in[5];
    const float* dc_p2b   = (const float*)d_in[6];
    const float* at_qw    = (const float*)d_in[7];
    const float* at_qb    = (const float*)d_in[8];
    const float* at_kvw   = (const float*)d_in[9];
    const float* at_kvb   = (const float*)d_in[10];
    const float* at_lcw   = (const float*)d_in[11];
    const float* at_lcb   = (const float*)d_in[12];
    const float* pj_dww   = (const float*)d_in[13];
    const float* pj_dwb   = (const float*)d_in[14];
    const float* pj_bn1g  = (const float*)d_in[15];
    const float* pj_bn1b  = (const float*)d_in[16];
    const float* pj_c1w   = (const float*)d_in[17];
    const float* pj_c1b   = (const float*)d_in[18];
    const float* pj_bn2g  = (const float*)d_in[19];
    const float* pj_bn2b  = (const float*)d_in[20];
    const float* pj_c2w   = (const float*)d_in[21];
    const float* pj_c2b   = (const float*)d_in[22];
    const float* pj_bn3g  = (const float*)d_in[23];
    const float* pj_bn3b  = (const float*)d_in[24];
    float* out = (float*)d_out;

    float *pq, *pkvin, *pkv, *pt1, *pt2, *pt3, *pan, *pbn, *pps, *pps2;
    cudaGetSymbolAddress((void**)&pq,    g_q);
    cudaGetSymbolAddress((void**)&pkvin, g_kvin);
    cudaGetSymbolAddress((void**)&pkv,   g_kv);
    cudaGetSymbolAddress((void**)&pt1,   g_t1);
    cudaGetSymbolAddress((void**)&pt2,   g_t2);
    cudaGetSymbolAddress((void**)&pt3,   g_t3);
    cudaGetSymbolAddress((void**)&pan,   g_an);
    cudaGetSymbolAddress((void**)&pbn,   g_bn);
    cudaGetSymbolAddress((void**)&pps,   g_ps);
    cudaGetSymbolAddress((void**)&pps2,  g_ps2);

    // ---- branch 1: dynamic conv scores ----
    pooled_kernel<<<96, C2_>>>(x);
    dcmlp_kernel<<<B_, C2_>>>(dc_p1w, dc_p1b, dc_p2w, dc_p2b, dc_weight, dc_bias);
    // ---- dconv + kvin (merged) ----
    dckv_kernel<<<dim3(125, B_), 768>>>(x, at_lcw, at_lcb);

    // ---- attention: merged q + kv projection, then flash attention ----
    qkv_kernel<<<dim3(63, 9), 256>>>(x, at_qw, at_qb, at_kvw, at_kvb);
    attn_kernel<<<dim3(8, H_, B_), 256>>>();

    // ---- projection: dw3 + gelu with fused BN1 partials ----
    pjdw_kernel<<<dim3(8, B_), C_>>>(pj_dww, pj_dwb);
    stats_finalize_kernel<<<3, 256>>>(64, C_, pj_bn1g, pj_bn1b);

    // ---- c1 (bn1 folded into A) + gelu + fused BN2 partials ----
    gemm_kernel<<<dim3(63, 1), 256>>>(pt1, C_, pj_c1w, pj_c1b,
                                      pt2, PJIN_, M_, PJIN_, C_, pan, pbn, 1, pps, pps2);
    stats_finalize_kernel<<<1, 256>>>(63, PJIN_, pj_bn2g, pj_bn2b);

    // ---- c2 (bn2 folded into A) + fused BN3 partials ----
    gemm_kernel<<<dim3(63, 6), 256>>>(pt2, PJIN_, pj_c2w, pj_c2b,
                                      pt3, C_, M_, C_, PJIN_, pan, pbn, 0, pps, pps2);
    stats_finalize_kernel<<<3, 256>>>(63, C_, pj_bn3g, pj_bn3b);

    // ---- bn3 + residual ----
    final_add_kernel<<<(M_*C_/4 + 255)/256, 256>>>(out);
}

// round 17
// speedup vs baseline: 2.8582x; 1.0291x over previous
#include <cuda_runtime.h>
#include <math.h>

#define B_    8
#define L_    999
#define C_    768
#define C2_   384
#define H_    8
#define HD_   48
#define K_    3
#define DCIN_ 96
#define PJIN_ 96
#define M_    (B_*L_)          /* 7992 tokens */
#define SCALE_ 0.14433756729740643f
#define EPS_   1e-5f

__device__ __forceinline__ float gelu_f(float v) {
    return 0.5f * v * (1.0f + erff(v * 0.7071067811865475f));
}

// ---- tf32 mma helpers (validated R7/R8) ----
__device__ __forceinline__ unsigned f2tf(float f) {
    unsigned r; asm("cvt.rna.tf32.f32 %0, %1;" : "=r"(r) : "f"(f)); return r;
}
__device__ __forceinline__ void mma_tf32(float* c, const unsigned* a, const unsigned* b) {
    asm volatile("mma.sync.aligned.m16n8k8.row.col.f32.tf32.tf32.f32 "
                 "{%0,%1,%2,%3}, {%4,%5,%6,%7}, {%8,%9}, {%0,%1,%2,%3};"
                 : "+f"(c[0]), "+f"(c[1]), "+f"(c[2]), "+f"(c[3])
                 : "r"(a[0]), "r"(a[1]), "r"(a[2]), "r"(a[3]),
                   "r"(b[0]), "r"(b[1]));
}
// ---- bf16 helpers (attention) ----
__device__ __forceinline__ unsigned pkbf(float lo, float hi) {
    unsigned r; asm("cvt.rn.bf16x2.f32 %0, %1, %2;" : "=r"(r) : "f"(hi), "f"(lo)); return r;
}
__device__ __forceinline__ void mma_bf16(float* c, const unsigned* a, const unsigned* b) {
    asm volatile("mma.sync.aligned.m16n8k16.row.col.f32.bf16.bf16.f32 "
                 "{%0,%1,%2,%3}, {%4,%5,%6,%7}, {%8,%9}, {%0,%1,%2,%3};"
                 : "+f"(c[0]), "+f"(c[1]), "+f"(c[2]), "+f"(c[3])
                 : "r"(a[0]), "r"(a[1]), "r"(a[2]), "r"(a[3]),
                   "r"(b[0]), "r"(b[1]));
}
// ---- ldmatrix helpers ----
__device__ __forceinline__ unsigned sptr(const void* p) {
    return (unsigned)__cvta_generic_to_shared(p);
}
__device__ __forceinline__ void ldsm_x4(unsigned* r, unsigned addr) {
    asm volatile("ldmatrix.sync.aligned.m8n8.x4.shared.b16 {%0,%1,%2,%3}, [%4];"
                 : "=r"(r[0]), "=r"(r[1]), "=r"(r[2]), "=r"(r[3]) : "r"(addr));
}

// ---------------- scratch (device globals; no allocation allowed) ----------------
__device__ float g_q    [(size_t)M_*C2_];
__device__ float g_kvin [(size_t)M_*C2_];
__device__ float g_kv   [(size_t)M_*C_];
__device__ float g_xc   [(size_t)M_*C_];
__device__ float g_t1   [(size_t)M_*C_];
__device__ float g_t2   [(size_t)M_*PJIN_];
__device__ float g_t3   [(size_t)M_*C_];
__device__ float g_wdyn [B_*C2_*K_];
__device__ float g_bdyn [B_*C2_];
__device__ float g_ps   [128*C_];
__device__ float g_ps2  [128*C_];
__device__ float g_an   [C_];
__device__ float g_bn   [C_];

// ---------------- stage 1: pooled partial sums (4-way split over rows) ----------------
__global__ void pooled_kernel(const float* __restrict__ x) {
    int blk = blockIdx.x;            // (b*3+kk)*4+sub
    int sub = blk & 3;
    int bk  = blk >> 2;
    int b   = bk / K_;
    int kk  = bk % K_;
    int c   = threadIdx.x;           // 384
    int r0 = kk*333 + sub*84;
    int r1 = kk*333 + min(sub*84 + 84, 333);
    const float* xb = x + (size_t)b*L_*C_ + c;
    float s = 0.f;
    for (int l = r0; l < r1; l++) s += xb[(size_t)l*C_];
    g_ps[(size_t)blk*C2_ + c] = s;
}

// ---------------- stage 2: dynamic-conv score MLP + softmax over G ----------------
__global__ void dcmlp_kernel(const float* __restrict__ p1w, const float* __restrict__ p1b,
                             const float* __restrict__ p2w, const float* __restrict__ p2b,
                             const float* __restrict__ dcw, const float* __restrict__ dcb) {
    int b   = blockIdx.x;
    int tid = threadIdx.x;                 // 384
    __shared__ float col[4][C2_];
    __shared__ float hid[4][DCIN_];
    __shared__ float sc [4][2*C2_];
    {
        float cc[3];
        #pragma unroll
        for (int kk = 0; kk < 3; kk++) {
            int base = (b*3+kk)*4;
            cc[kk] = (g_ps[(size_t)(base+0)*C2_+tid] + g_ps[(size_t)(base+1)*C2_+tid]
                    + g_ps[(size_t)(base+2)*C2_+tid] + g_ps[(size_t)(base+3)*C2_+tid]) * (1.0f/333.0f);
            col[kk][tid] = cc[kk];
        }
        col[3][tid] = (cc[0]+cc[1]+cc[2]) * (1.0f/3.0f);
    }
    __syncthreads();
    {
        int kk = tid / DCIN_;
        int i  = tid % DCIN_;
        float s = p1b[i];
        const float* wr = p1w + (size_t)i*C2_;
        #pragma unroll 8
        for (int c = 0; c < C2_; c++) s += wr[c]*col[kk][c];
        hid[kk][i] = gelu_f(s);
    }
    __syncthreads();
    for (int t = tid; t < 4*768; t += 384) {
        int kk = t / 768, o = t % 768;
        float s = p2b[o];
        const float* wr = p2w + (size_t)o*DCIN_;
        #pragma unroll 8
        for (int i = 0; i < DCIN_; i++) s += wr[i]*hid[kk][i];
        sc[kk][o] = s;
    }
    __syncthreads();
    {
        int c = tid;
        #pragma unroll
        for (int kk = 0; kk < 3; kk++) {
            float e0 = sc[kk][c], e1 = sc[kk][C2_+c];
            float mx = fmaxf(e0,e1);
            float a0 = expf(e0-mx), a1 = expf(e1-mx);
            float inv = 1.f/(a0+a1);
            g_wdyn[(b*C2_+c)*3+kk] = (a0*dcw[c*3+kk] + a1*dcw[(C2_+c)*3+kk])*inv;
        }
        float e0 = sc[3][c], e1 = sc[3][C2_+c];
        float mx = fmaxf(e0,e1);
        float a0 = expf(e0-mx), a1 = expf(e1-mx);
        g_bdyn[b*C2_+c] = (a0*dcb[c] + a1*dcb[C2_+c])/(a0+a1);
    }
}

// ---------------- stage 3+4 merged: dynamic depthwise conv + kv_in ----------------
__global__ void dckv_kernel(const float* __restrict__ x,
                            const float* __restrict__ lcw, const float* __restrict__ lcb) {
    int b  = blockIdx.y;
    int tid = threadIdx.x;                 // 768: li 0..7, c4 0..95
    int l  = blockIdx.x*8 + (tid/96);
    int c  = (tid%96)*4;
    if (l >= L_) return;
    float4 zero = make_float4(0.f,0.f,0.f,0.f);
    {   // ---- dconv: x[:, :, c] -> xc[:, :, c] ----
        const float* wp = g_wdyn + ((size_t)b*C2_ + c)*3;
        float4 wA = *(const float4*)(wp);
        float4 wB = *(const float4*)(wp+4);
        float4 wC = *(const float4*)(wp+8);
        float4 bv = *(const float4*)(g_bdyn + (size_t)b*C2_ + c);
        const float* xb = x + ((size_t)b*L_ + l)*C_ + c;
        float4 xm = (l > 0)      ? *(const float4*)(xb - C_) : zero;
        float4 x0 = *(const float4*)(xb);
        float4 xp = (l+1 < L_)   ? *(const float4*)(xb + C_) : zero;
        float4 r;
        r.x = xm.x*wA.x + x0.x*wA.y + xp.x*wA.z + bv.x;
        r.y = xm.y*wA.w + x0.y*wB.x + xp.y*wB.y + bv.y;
        r.z = xm.z*wB.z + x0.z*wB.w + xp.z*wC.x + bv.z;
        r.w = xm.w*wC.y + x0.w*wC.z + xp.w*wC.w + bv.w;
        *(float4*)(g_xc + ((size_t)b*L_ + l)*C_ + c) = r;
    }
    {   // ---- kvin: x[:, :, C2+c] -> kvin[:, :, c] ----
        const float* wp = lcw + (size_t)c*3;
        float4 wA = *(const float4*)(wp);
        float4 wB = *(const float4*)(wp+4);
        float4 wC = *(const float4*)(wp+8);
        float4 bv = *(const float4*)(lcb + c);
        const float* xb = x + ((size_t)b*L_ + l)*C_ + C2_ + c;
        float4 xm = (l > 0)      ? *(const float4*)(xb - C_) : zero;
        float4 x0 = *(const float4*)(xb);
        float4 xp = (l+1 < L_)   ? *(const float4*)(xb + C_) : zero;
        float4 r;
        r.x = xm.x*wA.x + x0.x*wA.y + xp.x*wA.z + bv.x + x0.x;
        r.y = xm.y*wA.w + x0.y*wB.x + xp.y*wB.y + bv.y + x0.y;
        r.z = xm.z*wB.z + x0.z*wB.w + xp.z*wC.x + bv.z + x0.z;
        r.w = xm.w*wC.y + x0.w*wC.z + xp.w*wC.w + bv.w + x0.w;
        *(float4*)(g_kvin + ((size_t)b*L_ + l)*C2_ + c) = r;
    }
}

// ---------------- GEMM body v9: 128x128 block, 32x64 warp tile, ldmatrix fragments -----
__device__ __forceinline__ void
gemm_body(unsigned* As, unsigned* Ws, float* sred,
          const float* __restrict__ A, int lda,
          const float* __restrict__ W,
          const float* __restrict__ bias,
          float* __restrict__ Cmat, int ldc,
          int M, int N, int Kd,
          const float* __restrict__ ascale,
          const float* __restrict__ ashift,
          int dogelu,
          float* __restrict__ ps, float* __restrict__ ps2,
          int blkx, int blky)
{
    int tid  = threadIdx.x;                // 256 = 8 warps
    int wid  = tid >> 5, lane = tid & 31;
    int gid  = lane >> 2, tig = lane & 3;
    int m0 = blkx*128, n0 = blky*128;
    int mw = (wid >> 1) * 32;              // 0/32/64/96
    int nw = (wid & 1) * 64;               // 0/64

    // per-lane ldmatrix offsets (bytes): x4 layout rows {0-7, 8-15} x k-half {0, +4}
    unsigned x4off = ((((lane & 7) + ((lane >> 3) & 1)*8) * 20) + ((lane >> 4) & 1)*4) << 2;
    unsigned AsS = sptr(As), WsS = sptr(Ws);

    float acc[2][8][4];
    #pragma unroll
    for (int i = 0; i < 2; i++)
        #pragma unroll
        for (int j = 0; j < 8; j++)
            #pragma unroll
            for (int t = 0; t < 4; t++) acc[i][j][t] = 0.f;

    int lr = tid >> 1, lk = (tid & 1) << 3;
    float4 zero = make_float4(0.f,0.f,0.f,0.f);
    float4 a0, a1, w0, w1;

    auto loadc = [&](int k0) {
        a0 = zero; a1 = zero; w0 = zero; w1 = zero;
        int gm = m0 + lr;
        if (gm < M) {
            const float* ap = A + (size_t)gm*lda + k0 + lk;
            a0 = *(const float4*)(ap);
            a1 = *(const float4*)(ap+4);
        }
        if (ascale) {
            int kb = k0 + lk;
            a0.x = a0.x*ascale[kb+0] + ashift[kb+0];
            a0.y = a0.y*ascale[kb+1] + ashift[kb+1];
            a0.z = a0.z*ascale[kb+2] + ashift[kb+2];
            a0.w = a0.w*ascale[kb+3] + ashift[kb+3];
            a1.x = a1.x*ascale[kb+4] + ashift[kb+4];
            a1.y = a1.y*ascale[kb+5] + ashift[kb+5];
            a1.z = a1.z*ascale[kb+6] + ashift[kb+6];
            a1.w = a1.w*ascale[kb+7] + ashift[kb+7];
        }
        int gn = n0 + lr;
        if (gn < N) {
            const float* wptr = W + (size_t)gn*Kd + k0 + lk;
            w0 = *(const float4*)(wptr);
            w1 = *(const float4*)(wptr+4);
        }
    };
    auto storec = [&](int st) {
        unsigned* Ar = As + ((size_t)st*128 + lr)*20 + lk;
        Ar[0]=f2tf(a0.x); Ar[1]=f2tf(a0.y); Ar[2]=f2tf(a0.z); Ar[3]=f2tf(a0.w);
        Ar[4]=f2tf(a1.x); Ar[5]=f2tf(a1.y); Ar[6]=f2tf(a1.z); Ar[7]=f2tf(a1.w);
        unsigned* Wr = Ws + ((size_t)st*128 + lr)*20 + lk;
        Wr[0]=f2tf(w0.x); Wr[1]=f2tf(w0.y); Wr[2]=f2tf(w0.z); Wr[3]=f2tf(w0.w);
        Wr[4]=f2tf(w1.x); Wr[5]=f2tf(w1.y); Wr[6]=f2tf(w1.z); Wr[7]=f2tf(w1.w);
    };

    int nk = Kd >> 4;
    loadc(0);
    storec(0);
    __syncthreads();

    for (int i = 0; i < nk; i++) {
        int buf = i & 1;
        if (i+1 < nk) loadc((i+1) << 4);
        unsigned AbS = AsS + buf*128*20*4;
        unsigned WbS = WsS + buf*128*20*4;
        #pragma unroll
        for (int k8 = 0; k8 < 16; k8 += 8) {
            // B fragments for all 8 n-tiles: 4 x4-ldmatrix (2 n-tiles each)
            unsigned bf[4][4];
            #pragma unroll
            for (int np = 0; np < 4; np++)
                ldsm_x4(bf[np], WbS + (((nw + np*16)*20 + k8) << 2) + x4off);
            #pragma unroll
            for (int mt = 0; mt < 2; mt++) {
                unsigned afr[4];
                ldsm_x4(afr, AbS + (((mw + mt*16)*20 + k8) << 2) + x4off);
                #pragma unroll
                for (int np = 0; np < 4; np++) {
                    unsigned be[2] = { bf[np][0], bf[np][2] };
                    unsigned bo[2] = { bf[np][1], bf[np][3] };
                    mma_tf32(acc[mt][2*np  ], afr, be);
                    mma_tf32(acc[mt][2*np+1], afr, bo);
                }
            }
        }
        if (i+1 < nk) {
            storec(buf ^ 1);
            __syncthreads();
        }
    }

    #pragma unroll
    for (int mt = 0; mt < 2; mt++) {
        #pragma unroll
        for (int nt = 0; nt < 8; nt++) {
            int gn = n0 + nw + nt*8 + 2*tig;
            if (gn < N) {
                float b0v = bias[gn], b1v = bias[gn+1];
                acc[mt][nt][0] += b0v; acc[mt][nt][1] += b1v;
                acc[mt][nt][2] += b0v; acc[mt][nt][3] += b1v;
                if (dogelu) {
                    acc[mt][nt][0] = gelu_f(acc[mt][nt][0]);
                    acc[mt][nt][1] = gelu_f(acc[mt][nt][1]);
                    acc[mt][nt][2] = gelu_f(acc[mt][nt][2]);
                    acc[mt][nt][3] = gelu_f(acc[mt][nt][3]);
                }
                int gm0 = m0 + mw + mt*16 + gid;
                if (gm0 < M)
                    *(float2*)(Cmat + (size_t)gm0*ldc + gn) = make_float2(acc[mt][nt][0], acc[mt][nt][1]);
                int gm1 = gm0 + 8;
                if (gm1 < M)
                    *(float2*)(Cmat + (size_t)gm1*ldc + gn) = make_float2(acc[mt][nt][2], acc[mt][nt][3]);
            } else {
                acc[mt][nt][0]=0.f; acc[mt][nt][1]=0.f; acc[mt][nt][2]=0.f; acc[mt][nt][3]=0.f;
            }
        }
    }

    if (ps) {
        #pragma unroll
        for (int nt = 0; nt < 8; nt++) {
            #pragma unroll
            for (int j = 0; j < 2; j++) {
                float s = 0.f, s2 = 0.f;
                #pragma unroll
                for (int mt = 0; mt < 2; mt++) {
                    int gm0 = m0 + mw + mt*16 + gid;
                    if (gm0 < M)     { float t = acc[mt][nt][j];   s += t; s2 += t*t; }
                    if (gm0 + 8 < M) { float t = acc[mt][nt][j+2]; s += t; s2 += t*t; }
                }
                s  += __shfl_xor_sync(0xffffffffu, s,  4);
                s  += __shfl_xor_sync(0xffffffffu, s,  8);
                s  += __shfl_xor_sync(0xffffffffu, s, 16);
                s2 += __shfl_xor_sync(0xffffffffu, s2,  4);
                s2 += __shfl_xor_sync(0xffffffffu, s2,  8);
                s2 += __shfl_xor_sync(0xffffffffu, s2, 16);
                if (gid == 0) {
                    int colw = nt*8 + 2*tig + j;
                    sred[(wid*64 + colw)*2 + 0] = s;
                    sred[(wid*64 + colw)*2 + 1] = s2;
                }
            }
        }
        __syncthreads();
        if (tid < 256) {
            int g   = tid >> 7;
            int col = (tid >> 1) & 63;
            int q   = tid & 1;
            float t = sred[((g  )*64 + col)*2 + q] + sred[((g+2)*64 + col)*2 + q]
                    + sred[((g+4)*64 + col)*2 + q] + sred[((g+6)*64 + col)*2 + q];
            int gn = n0 + g*64 + col;
            if (gn < N) {
                float* dst = q ? ps2 : ps;
                dst[(size_t)blkx*N + gn] = t;
            }
        }
    }
}

// ---------------- generic GEMM wrapper ----------------
__global__ void __launch_bounds__(256, 2)
gemm_kernel(const float* __restrict__ A, int lda,
            const float* __restrict__ W,
            const float* __restrict__ bias,
            float* __restrict__ Cmat, int ldc,
            int M, int N, int Kd,
            const float* __restrict__ ascale,
            const float* __restrict__ ashift,
            int dogelu,
            float* __restrict__ ps, float* __restrict__ ps2)
{
    __shared__ unsigned As[2*128*20];
    __shared__ unsigned Ws[2*128*20];
    __shared__ float sred[8*64*2];
    gemm_body(As, Ws, sred, A, lda, W, bias, Cmat, ldc, M, N, Kd,
              ascale, ashift, dogelu, ps, ps2, blockIdx.x, blockIdx.y);
}

// ---------------- merged q + kv projection GEMM (one launch) --------
__global__ void __launch_bounds__(256, 2)
qkv_kernel(const float* __restrict__ x,
           const float* __restrict__ qw,  const float* __restrict__ qb,
           const float* __restrict__ kvw, const float* __restrict__ kvb)
{
    __shared__ unsigned As[2*128*20];
    __shared__ unsigned Ws[2*128*20];
    __shared__ float sred[8*64*2];
    if (blockIdx.y < 3) {
        gemm_body(As, Ws, sred, x + C2_, C_, qw, qb, g_q, C2_, M_, C2_, C2_,
                  nullptr, nullptr, 0, nullptr, nullptr, blockIdx.x, blockIdx.y);
    } else {
        gemm_body(As, Ws, sred, g_kvin, C2_, kvw, kvb, g_kv, C_, M_, C_, C2_,
                  nullptr, nullptr, 0, nullptr, nullptr, blockIdx.x, blockIdx.y - 3);
    }
}

// ---------------- stage 7: flash attention v6 (bf16 mma + ldmatrix) ---------------------
// Block: 128 q-rows, 8 warps; warp = private 16-row q-group over 64-key tiles.
// S C-fragments convert directly into stage-2 A-fragments (no P smem, 2 barriers/kt).
// Output reproduces the reference transpose+flat-reshape reinterpretation:
// (c = h*HD+d, l) -> flat = c*L + l -> xc[b, flat/C2, C2 + flat%C2].
__global__ void __launch_bounds__(256, 2) attn_kernel() {
    __shared__ unsigned sh_q[128*28];   // Q bf16 pairs [row][dpair]   14336 B
    __shared__ unsigned sh_k[64*28];    // K bf16 pairs [key][dpair]    7168 B
    __shared__ unsigned sh_v[48*36];    // V bf16 pairs [d][keypair]    6912 B
    int qt = blockIdx.x;                // 8 q tiles of 128
    int h  = blockIdx.y;
    int b  = blockIdx.z;
    int tid = threadIdx.x;              // 256
    int lane = tid & 31;
    int gid = lane >> 2, tig = lane & 3;
    int qw  = (tid >> 5) * 16;

    const float* qb = g_q  + (size_t)b*L_*C2_ + h*HD_;
    const float* kb = g_kv + (size_t)b*L_*C_  + h*HD_;
    const float* vb = kb + C2_;

    // per-lane x4 ldmatrix byte offsets for each stride
    int lrow8 = (lane & 7) + ((lane >> 3) & 1)*8;
    int lcol4 = ((lane >> 4) & 1)*4;
    unsigned qoff = ((lrow8*28) + lcol4) << 2;
    unsigned koff = ((lrow8*28) + lcol4) << 2;
    unsigned voff = ((lrow8*36) + lcol4) << 2;
    unsigned shqS = sptr(sh_q), shkS = sptr(sh_k), shvS = sptr(sh_v);

    // ---- Q staging (bf16 pairs along d) ----
    {
        int row = tid >> 1, dh = (tid & 1)*24;
        int gl = qt*128 + row;
        unsigned* qr = sh_q + row*28 + (tid & 1)*12;
        if (gl < L_) {
            #pragma unroll
            for (int t = 0; t < 6; t++) {
                float4 v = *(const float4*)(qb + (size_t)gl*C2_ + dh + t*4);
                qr[t*2+0] = pkbf(v.x, v.y);
                qr[t*2+1] = pkbf(v.z, v.w);
            }
        } else {
            #pragma unroll
            for (int t = 0; t < 12; t++) qr[t] = 0u;
        }
    }
    __syncthreads();
    // ---- Q A-fragments resident in registers (3 k16 blocks over d=48) ----
    unsigned qfr[3][4];
    #pragma unroll
    for (int i = 0; i < 3; i++)
        ldsm_x4(qfr[i], shqS + ((qw*28 + i*8) << 2) + qoff);

    float m[2]    = {-1e30f, -1e30f};
    float lsum[2] = {0.f, 0.f};
    float o[6][4];
    #pragma unroll
    for (int nt = 0; nt < 6; nt++)
        #pragma unroll
        for (int t = 0; t < 4; t++) o[nt][t] = 0.f;

    for (int kt = 0; kt < 16; kt++) {
        __syncthreads();   // prior stage1/2 reads of sh_k / sh_v complete
        {   // ---- K staging: key = tid>>2, 12 d per thread -> 6 packed ----
            int key = tid >> 2, dp = (tid & 3)*12;
            int gl = kt*64 + key;
            unsigned* kr = sh_k + key*28 + (tid & 3)*6;
            if (gl < L_) {
                #pragma unroll
                for (int t = 0; t < 3; t++) {
                    float4 kv = *(const float4*)(kb + (size_t)gl*C_ + dp + t*4);
                    kr[t*2+0] = pkbf(kv.x, kv.y);
                    kr[t*2+1] = pkbf(kv.z, kv.w);
                }
            } else {
                #pragma unroll
                for (int t = 0; t < 6; t++) kr[t] = 0u;
            }
        }
        if (tid < 192) {   // ---- V staging: key-pair kp, 8 d per thread ----
            int dblk = tid >> 5, kp = tid & 31;
            int gl0 = kt*64 + 2*kp, gl1 = gl0 + 1;
            int d0 = dblk*8;
            float4 v0a = make_float4(0.f,0.f,0.f,0.f), v0b = v0a, v1a = v0a, v1b = v0a;
            if (gl0 < L_) {
                v0a = *(const float4*)(vb + (size_t)gl0*C_ + d0);
                v0b = *(const float4*)(vb + (size_t)gl0*C_ + d0 + 4);
            }
            if (gl1 < L_) {
                v1a = *(const float4*)(vb + (size_t)gl1*C_ + d0);
                v1b = *(const float4*)(vb + (size_t)gl1*C_ + d0 + 4);
            }
            sh_v[(d0+0)*36 + kp] = pkbf(v0a.x, v1a.x);
            sh_v[(d0+1)*36 + kp] = pkbf(v0a.y, v1a.y);
            sh_v[(d0+2)*36 + kp] = pkbf(v0a.z, v1a.z);
            sh_v[(d0+3)*36 + kp] = pkbf(v0a.w, v1a.w);
            sh_v[(d0+4)*36 + kp] = pkbf(v0b.x, v1b.x);
            sh_v[(d0+5)*36 + kp] = pkbf(v0b.y, v1b.y);
            sh_v[(d0+6)*36 + kp] = pkbf(v0b.z, v1b.z);
            sh_v[(d0+7)*36 + kp] = pkbf(v0b.w, v1b.w);
        }
        __syncthreads();

        // ---- stage 1: S = Q K^T (3 k16 blocks x 8 n-tiles via 4 x4-ldmatrix) ----
        float s[8][4];
        #pragma unroll
        for (int nt = 0; nt < 8; nt++)
            #pragma unroll
            for (int t = 0; t < 4; t++) s[nt][t] = 0.f;
        #pragma unroll
        for (int i = 0; i < 3; i++) {
            #pragma unroll
            for (int np = 0; np < 4; np++) {
                unsigned kf[4];
                ldsm_x4(kf, shkS + ((np*16*28 + i*8) << 2) + koff);
                unsigned be[2] = { kf[0], kf[2] };
                unsigned bo[2] = { kf[1], kf[3] };
                mma_bf16(s[2*np  ], qfr[i], be);
                mma_bf16(s[2*np+1], qfr[i], bo);
            }
        }

        // ---- warp-local running softmax (rows gid / gid+8) ----
        float corr[2];
        int kbase = kt*64 + 2*tig;
        #pragma unroll
        for (int r = 0; r < 2; r++) {
            int i0 = 2*r;
            float mx = -1e30f;
            #pragma unroll
            for (int nt = 0; nt < 8; nt++) {
                int c0 = kbase + nt*8;
                float v0 = (c0   < L_) ? s[nt][i0  ]*SCALE_ : -1e30f;
                float v1 = (c0+1 < L_) ? s[nt][i0+1]*SCALE_ : -1e30f;
                s[nt][i0] = v0; s[nt][i0+1] = v1;
                mx = fmaxf(mx, fmaxf(v0, v1));
            }
            mx = fmaxf(mx, __shfl_xor_sync(0xffffffffu, mx, 1));
            mx = fmaxf(mx, __shfl_xor_sync(0xffffffffu, mx, 2));
            float mnew = fmaxf(m[r], mx);
            corr[r] = __expf(m[r] - mnew);
            m[r] = mnew;
            float lp = 0.f;
            #pragma unroll
            for (int nt = 0; nt < 8; nt++) {
                float p0 = __expf(s[nt][i0  ] - mnew);
                float p1 = __expf(s[nt][i0+1] - mnew);
                s[nt][i0] = p0; s[nt][i0+1] = p1;
                lp += p0 + p1;
            }
            lp += __shfl_xor_sync(0xffffffffu, lp, 1);
            lp += __shfl_xor_sync(0xffffffffu, lp, 2);
            lsum[r] = lsum[r]*corr[r] + lp;
        }

        // ---- rescale O frags, then stage 2: O += P V (P frags direct from s) ----
        #pragma unroll
        for (int nt = 0; nt < 6; nt++) {
            o[nt][0] *= corr[0]; o[nt][1] *= corr[0];
            o[nt][2] *= corr[1]; o[nt][3] *= corr[1];
        }
        #pragma unroll
        for (int j = 0; j < 4; j++) {          // k16 blocks over 64 keys
            unsigned afr[4];
            afr[0] = pkbf(s[2*j  ][0], s[2*j  ][1]);
            afr[1] = pkbf(s[2*j  ][2], s[2*j  ][3]);
            afr[2] = pkbf(s[2*j+1][0], s[2*j+1][1]);
            afr[3] = pkbf(s[2*j+1][2], s[2*j+1][3]);
            #pragma unroll
            for (int np = 0; np < 3; np++) {   // 6 n-tiles = 3 x4-ldmatrix
                unsigned vf[4];
                ldsm_x4(vf, shvS + ((np*16*36 + j*8) << 2) + voff);
                unsigned be[2] = { vf[0], vf[2] };
                unsigned bo[2] = { vf[1], vf[3] };
                mma_bf16(o[2*np  ], afr, be);
                mma_bf16(o[2*np+1], afr, bo);
            }
        }
    }

    // ---- epilogue: normalize and scatter via the flat-reshape mapping ----
    {
        float inv0 = 1.f/lsum[0], inv1 = 1.f/lsum[1];
        int q0 = qt*128 + qw + gid, q1 = q0 + 8;
        float* xcb = g_xc + (size_t)b*L_*C_;
        #pragma unroll
        for (int nt = 0; nt < 6; nt++) {
            #pragma unroll
            for (int j = 0; j < 2; j++) {
                int d = nt*8 + 2*tig + j;
                int c = h*HD_ + d;
                if (q0 < L_) {
                    int flat = c*L_ + q0;
                    int lp2 = flat / C2_;
                    int cp  = flat - lp2*C2_;
                    xcb[(size_t)lp2*C_ + C2_ + cp] = o[nt][j]*inv0;
                }
                if (q1 < L_) {
                    int flat = c*L_ + q1;
                    int lp2 = flat / C2_;
                    int cp  = flat - lp2*C2_;
                    xcb[(size_t)lp2*C_ + C2_ + cp] = o[nt][j+2]*inv1;
                }
            }
        }
    }
}

// ---------------- stage 8a: t1 = gelu(dw3(xc)) with fused BN1 partials ----------------
__global__ void pjdw_kernel(const float* __restrict__ dww, const float* __restrict__ dwb) {
    int b = blockIdx.y, chunk = blockIdx.x;   // 8 x 8
    int c = threadIdx.x;                      // 768
    int l0 = chunk*125, l1 = min(l0+125, L_);
    float w0 = dww[c*3], w1 = dww[c*3+1], w2 = dww[c*3+2], bb = dwb[c];
    const float* xb = g_xc + (size_t)b*L_*C_ + c;
    float*       yb = g_t1 + (size_t)b*L_*C_ + c;
    float s = 0.f, s2 = 0.f;
    float xm1 = (l0 > 0) ? xb[(size_t)(l0-1)*C_] : 0.f;
    float x0  = xb[(size_t)l0*C_];
    for (int l = l0; l < l1; l++) {
        float xp1 = (l+1 < L_) ? xb[(size_t)(l+1)*C_] : 0.f;
        float v = gelu_f(xm1*w0 + x0*w1 + xp1*w2 + bb);
        yb[(size_t)l*C_] = v;
        s += v; s2 += v*v;
        xm1 = x0; x0 = xp1;
    }
    int blk = b*8 + chunk;
    g_ps [(size_t)blk*C_ + c] = s;
    g_ps2[(size_t)blk*C_ + c] = s2;
}

// ---------------- deterministic BN finalize: partials -> affine (a,b) ----------
__global__ void stats_finalize_kernel(int nblk, int Cch,
                                      const float* __restrict__ gam,
                                      const float* __restrict__ bet) {
    int c = blockIdx.x*blockDim.x + threadIdx.x;
    if (c >= Cch) return;
    double s = 0.0, s2 = 0.0;
    for (int i = 0; i < nblk; i++) { s += (double)g_ps[(size_t)i*Cch+c]; s2 += (double)g_ps2[(size_t)i*Cch+c]; }
    double mean = s / (double)M_;
    double var  = s2 / (double)M_ - mean*mean;
    if (var < 0.0) var = 0.0;
    float rs = (float)(1.0 / sqrt(var + (double)EPS_));
    float a  = gam[c]*rs;
    g_an[c] = a;
    g_bn[c] = bet[c] - (float)mean*a;
}

// ---------------- final: out = bn3(t3) + xc ----------------
__global__ void final_add_kernel(float* __restrict__ out) {
    int idx4 = blockIdx.x*blockDim.x + threadIdx.x;
    if (idx4 >= M_*C_/4) return;
    int idx = idx4*4;
    int c = idx % C_;
    float4 t = *(const float4*)(g_t3 + idx);
    float4 xv= *(const float4*)(g_xc + idx);
    float4 a = *(const float4*)(g_an + c);
    float4 bb= *(const float4*)(g_bn + c);
    float4 r;
    r.x = t.x*a.x + bb.x + xv.x;
    r.y = t.y*a.y + bb.y + xv.y;
    r.z = t.z*a.z + bb.z + xv.z;
    r.w = t.w*a.w + bb.w + xv.w;
    *(float4*)(out + idx) = r;
}

// =======================================================================================
extern "C" void kernel_launch(void* const* d_in, const int* in_sizes, int n_in,
                              void* d_out, int out_size) {
    const float* x        = (const float*)d_in[0];
    const float* dc_weight= (const float*)d_in[1];
    const float* dc_bias  = (const float*)d_in[2];
    const float* dc_p1w   = (const float*)d_in[3];
    const float* dc_p1b   = (const float*)d_in[4];
    const float* dc_p2w   = (const float*)d_in[5];
    const float* dc_p2b   = (const float*)d_in[6];
    const float* at_qw    = (const float*)d_in[7];
    const float* at_qb    = (const float*)d_in[8];
    const float* at_kvw   = (const float*)d_in[9];
    const float* at_kvb   = (const float*)d_in[10];
    const float* at_lcw   = (const float*)d_in[11];
    const float* at_lcb   = (const float*)d_in[12];
    const float* pj_dww   = (const float*)d_in[13];
    const float* pj_dwb   = (const float*)d_in[14];
    const float* pj_bn1g  = (const float*)d_in[15];
    const float* pj_bn1b  = (const float*)d_in[16];
    const float* pj_c1w   = (const float*)d_in[17];
    const float* pj_c1b   = (const float*)d_in[18];
    const float* pj_bn2g  = (const float*)d_in[19];
    const float* pj_bn2b  = (const float*)d_in[20];
    const float* pj_c2w   = (const float*)d_in[21];
    const float* pj_c2b   = (const float*)d_in[22];
    const float* pj_bn3g  = (const float*)d_in[23];
    const float* pj_bn3b  = (const float*)d_in[24];
    float* out = (float*)d_out;

    float *pq, *pkvin, *pkv, *pt1, *pt2, *pt3, *pan, *pbn, *pps, *pps2;
    cudaGetSymbolAddress((void**)&pq,    g_q);
    cudaGetSymbolAddress((void**)&pkvin, g_kvin);
    cudaGetSymbolAddress((void**)&pkv,   g_kv);
    cudaGetSymbolAddress((void**)&pt1,   g_t1);
    cudaGetSymbolAddress((void**)&pt2,   g_t2);
    cudaGetSymbolAddress((void**)&pt3,   g_t3);
    cudaGetSymbolAddress((void**)&pan,   g_an);
    cudaGetSymbolAddress((void**)&pbn,   g_bn);
    cudaGetSymbolAddress((void**)&pps,   g_ps);
    cudaGetSymbolAddress((void**)&pps2,  g_ps2);

    // ---- branch 1: dynamic conv scores ----
    pooled_kernel<<<96, C2_>>>(x);
    dcmlp_kernel<<<B_, C2_>>>(dc_p1w, dc_p1b, dc_p2w, dc_p2b, dc_weight, dc_bias);
    // ---- dconv + kvin (merged) ----
    dckv_kernel<<<dim3(125, B_), 768>>>(x, at_lcw, at_lcb);

    // ---- attention: merged q + kv projection, then flash attention ----
    qkv_kernel<<<dim3(63, 9), 256>>>(x, at_qw, at_qb, at_kvw, at_kvb);
    attn_kernel<<<dim3(8, H_, B_), 256>>>();

    // ---- projection: dw3 + gelu with fused BN1 partials ----
    pjdw_kernel<<<dim3(8, B_), C_>>>(pj_dww, pj_dwb);
    stats_finalize_kernel<<<3, 256>>>(64, C_, pj_bn1g, pj_bn1b);

    // ---- c1 (bn1 folded into A) + gelu + fused BN2 partials ----
    gemm_kernel<<<dim3(63, 1), 256>>>(pt1, C_, pj_c1w, pj_c1b,
                                      pt2, PJIN_, M_, PJIN_, C_, pan, pbn, 1, pps, pps2);
    stats_finalize_kernel<<<1, 256>>>(63, PJIN_, pj_bn2g, pj_bn2b);

    // ---- c2 (bn2 folded into A) + fused BN3 partials ----
    gemm_kernel<<<dim3(63, 6), 256>>>(pt2, PJIN_, pj_c2w, pj_c2b,
                                      pt3, C_, M_, C_, PJIN_, pan, pbn, 0, pps, pps2);
    stats_finalize_kernel<<<3, 256>>>(63, C_, pj_bn3g, pj_bn3b);

    // ---- bn3 + residual ----
    final_add_kernel<<<(M_*C_/4 + 255)/256, 256>>>(out);
}